// round 1
// baseline (speedup 1.0000x reference)
#include <cuda_runtime.h>
#include <math.h>

#define BATCH 8
#define EMB 768
#define NHEAD 12
#define NLAYER 12
#define HD 64
#define NTOK 197
#define MROWS (BATCH*NTOK)   /* 1576 */
#define E3 2304
#define MLPD 3072
#define QSCALE 0.125f
#define NCLS 1000

enum { EPI_BIAS=0, EPI_ELU1=1, EPI_GELU=2, EPI_RES=3 };

/* ------------------------------ scratch ------------------------------ */
__device__ float g_patches[MROWS*EMB];
__device__ float g_xm[MROWS*EMB];
__device__ float g_xc[MROWS*EMB];
__device__ float g_tn[MROWS*EMB];
__device__ float g_qkvm[MROWS*E3];
__device__ float g_qkvc[MROWS*E3];
__device__ float g_qbuf[BATCH*NHEAD*NTOK*HD];
__device__ float g_kbuf[BATCH*NHEAD*NTOK*HD];
__device__ float g_cqs[BATCH*NHEAD*NTOK*HD];
__device__ float g_cks[BATCH*NHEAD*NTOK*HD];
__device__ float g_qs2[BATCH*NHEAD*NTOK];
__device__ float g_ks2[BATCH*NHEAD*NTOK];
__device__ float g_cqsum[BATCH*NHEAD*NTOK];
__device__ float g_cksum[BATCH*NHEAD*NTOK];
__device__ float g_attn[BATCH*NHEAD*NTOK*NTOK];
__device__ float g_mctx[MROWS*EMB];
__device__ float g_cctx[MROWS*EMB];
__device__ float g_hbuf[MROWS*MLPD];
__device__ float g_qkvb[NLAYER*E3];
__device__ float g_cqkvb[NLAYER*E3];
__device__ float g_pool[BATCH*EMB];
__device__ float g_pooln[BATCH*EMB];

/* ------------------------------ GEMM: C[M,N] = A[M,K] * B[N,K]^T ------ */
template<int BM, int BN, int TM, int TN>
__global__ void __launch_bounds__((BM/TM)*(BN/TN))
gemm_nt(const float* __restrict__ A, const float* __restrict__ B,
        const float* __restrict__ bias, const float* __restrict__ gamma,
        float* __restrict__ C, int M, int N, int K, int epi)
{
    constexpr int BK = 8;
    constexpr int NT = (BM/TM)*(BN/TN);
    __shared__ float As[BK][BM];
    __shared__ float Bs[BK][BN];
    const int tid = threadIdx.x;
    const int bm = blockIdx.y * BM;
    const int bn = blockIdx.x * BN;
    const int tx = tid % (BN/TN);
    const int ty = tid / (BN/TN);

    float acc[TM][TN];
#pragma unroll
    for (int i=0;i<TM;i++)
#pragma unroll
        for (int j=0;j<TN;j++) acc[i][j]=0.f;

    for (int k0=0;k0<K;k0+=BK) {
        for (int i = tid*4; i < BM*BK; i += NT*4) {
            int r = i >> 3, c = i & 7;
            int gm = bm + r;
            float4 v;
            if (gm < M) v = *(const float4*)(A + (size_t)gm*K + k0 + c);
            else        v = make_float4(0.f,0.f,0.f,0.f);
            As[c+0][r]=v.x; As[c+1][r]=v.y; As[c+2][r]=v.z; As[c+3][r]=v.w;
        }
        for (int i = tid*4; i < BN*BK; i += NT*4) {
            int r = i >> 3, c = i & 7;
            float4 v = *(const float4*)(B + (size_t)(bn + r)*K + k0 + c);
            Bs[c+0][r]=v.x; Bs[c+1][r]=v.y; Bs[c+2][r]=v.z; Bs[c+3][r]=v.w;
        }
        __syncthreads();
#pragma unroll
        for (int kk=0;kk<BK;kk++){
            float a[TM], b[TN];
#pragma unroll
            for (int i=0;i<TM;i++) a[i]=As[kk][ty*TM+i];
#pragma unroll
            for (int j=0;j<TN;j++) b[j]=Bs[kk][tx*TN+j];
#pragma unroll
            for (int i=0;i<TM;i++)
#pragma unroll
                for (int j=0;j<TN;j++) acc[i][j] = fmaf(a[i], b[j], acc[i][j]);
        }
        __syncthreads();
    }
#pragma unroll
    for (int i=0;i<TM;i++){
        int gm = bm + ty*TM + i;
        if (gm >= M) continue;
        float* crow = C + (size_t)gm*N;
#pragma unroll
        for (int j=0;j<TN;j++){
            int gn = bn + tx*TN + j;
            float z = acc[i][j] + (bias ? bias[gn] : 0.f);
            float o;
            if      (epi == EPI_BIAS) o = z;
            else if (epi == EPI_ELU1) o = (z > 0.f) ? z + 1.f : expf(z);
            else if (epi == EPI_GELU) o = 0.5f*z*(1.f+erff(z*0.70710678118f));
            else                      o = crow[gn] + gamma[gn]*z;
            crow[gn] = o;
        }
    }
}

/* ------------------------------ LayerNorm (row = 768) ----------------- */
__global__ void __launch_bounds__(256) ln_kernel(const float* __restrict__ x,
        const float* __restrict__ g, const float* __restrict__ b,
        float* __restrict__ y)
{
    int row = blockIdx.x;
    const float* xr = x + (size_t)row*EMB;
    float* yr = y + (size_t)row*EMB;
    int tid = threadIdx.x;
    float v0=xr[tid], v1=xr[tid+256], v2=xr[tid+512];
    float s  = v0+v1+v2;
    float s2 = v0*v0+v1*v1+v2*v2;
    __shared__ float red[2][8];
    int lane=tid&31, wid=tid>>5;
#pragma unroll
    for(int o=16;o;o>>=1){ s+=__shfl_xor_sync(0xffffffffu,s,o); s2+=__shfl_xor_sync(0xffffffffu,s2,o); }
    if(!lane){ red[0][wid]=s; red[1][wid]=s2; }
    __syncthreads();
    s=0.f; s2=0.f;
#pragma unroll
    for (int i=0;i<8;i++){ s+=red[0][i]; s2+=red[1][i]; }
    float mu = s * (1.f/768.f);
    float var = s2*(1.f/768.f) - mu*mu;
    float inv = rsqrtf(var + 1e-5f);
    yr[tid]     = (v0-mu)*inv*g[tid]     + b[tid];
    yr[tid+256] = (v1-mu)*inv*g[tid+256] + b[tid+256];
    yr[tid+512] = (v2-mu)*inv*g[tid+512] + b[tid+512];
}

/* ------------------------------ im2col -------------------------------- */
__global__ void im2col_kernel(const float* __restrict__ x, float* __restrict__ p)
{
    int idx = blockIdx.x*blockDim.x + threadIdx.x;
    if (idx >= MROWS*EMB) return;
    int r = idx / EMB, col = idx % EMB;
    int b = r / NTOK, t = r % NTOK;
    float v = 0.f;
    if (t > 0){
        int pp = t-1;
        int py = pp/14, px = pp%14;
        int c = col >> 8, ph = (col>>4)&15, pw = col&15;
        v = x[(((size_t)b*3 + c)*224 + py*16+ph)*224 + px*16+pw];
    }
    p[idx]=v;
}

__global__ void fill_cls(const float* __restrict__ cls, const float* __restrict__ ccls,
                         float* __restrict__ xm, float* __restrict__ xc)
{
    int b = blockIdx.x, tid=threadIdx.x;
#pragma unroll
    for (int r=0;r<3;r++){
        int e = tid+r*256;
        xm[(size_t)b*NTOK*EMB+e]=cls[e];
        xc[(size_t)b*NTOK*EMB+e]=ccls[e];
    }
}

__global__ void build_qkvb(const float* __restrict__ qb, const float* __restrict__ vb,
                           const float* __restrict__ cqb, const float* __restrict__ cvb,
                           float* __restrict__ outv, float* __restrict__ coutv)
{
    int idx = blockIdx.x*blockDim.x+threadIdx.x;
    if (idx >= NLAYER*E3) return;
    int l = idx / E3, j = idx % E3;
    float v=0.f, cv=0.f;
    if (j < EMB)        { v=qb[l*EMB+j];        cv=cqb[l*EMB+j]; }
    else if (j >= 2*EMB){ v=vb[l*EMB+j-2*EMB];  cv=cvb[l*EMB+j-2*EMB]; }
    outv[idx]=v; coutv[idx]=cv;
}

/* -------- attention preprocess: reorder q/k, sqrt covs, row stats ----- */
__global__ void __launch_bounds__(64) attn_pre(const float* __restrict__ qkvm, const float* __restrict__ qkvc,
   float* __restrict__ qb, float* __restrict__ kb, float* __restrict__ cqs, float* __restrict__ cks,
   float* __restrict__ qs2, float* __restrict__ ks2, float* __restrict__ cqsum, float* __restrict__ cksum)
{
    int idx = blockIdx.x;            /* (b*H+h)*197 + t */
    int t  = idx % NTOK;
    int bh = idx / NTOK;
    int h  = bh % NHEAD;
    int b  = bh / NHEAD;
    int d  = threadIdx.x;
    size_t base = ((size_t)(b*NTOK+t)*3)*EMB + h*HD + d;
    float q  = qkvm[base]*QSCALE;
    float k  = qkvm[base+EMB];
    float cq = qkvc[base];
    float ck = qkvc[base+EMB];
    float sq = sqrtf(fmaxf(cq,1e-24f));
    float sk = sqrtf(fmaxf(ck,1e-24f));
    size_t o = (size_t)idx*HD + d;
    qb[o]=q; kb[o]=k; cqs[o]=sq; cks[o]=sk;
    float r0=q*q, r1=k*k, r2=cq, r3=ck;
#pragma unroll
    for(int off=16;off;off>>=1){
        r0+=__shfl_xor_sync(0xffffffffu,r0,off);
        r1+=__shfl_xor_sync(0xffffffffu,r1,off);
        r2+=__shfl_xor_sync(0xffffffffu,r2,off);
        r3+=__shfl_xor_sync(0xffffffffu,r3,off);
    }
    __shared__ float sh[4][2];
    int lane=d&31, w=d>>5;
    if(!lane){ sh[0][w]=r0; sh[1][w]=r1; sh[2][w]=r2; sh[3][w]=r3; }
    __syncthreads();
    if (d==0){
        qs2[idx]  =sh[0][0]+sh[0][1];
        ks2[idx]  =sh[1][0]+sh[1][1];
        cqsum[idx]=sh[2][0]+sh[2][1];
        cksum[idx]=sh[3][0]+sh[3][1];
    }
}

/* -------- Wasserstein scores + sigmoid + bias + softmax --------------- */
#define SNT 16
#define SMT 32
__global__ void __launch_bounds__(256) attn_score(
    const float* __restrict__ qbuf, const float* __restrict__ cqs,
    const float* __restrict__ kbuf, const float* __restrict__ cks,
    const float* __restrict__ qs2,  const float* __restrict__ cqsum,
    const float* __restrict__ ks2,  const float* __restrict__ cksum,
    const float* __restrict__ relb, float* __restrict__ attn)
{
    int bh = blockIdx.y;
    int h  = bh % NHEAD;
    int n0 = blockIdx.x * SNT;
    __shared__ float qsh[SNT][64];
    __shared__ float cqsh[SNT][64];
    __shared__ float kt[SMT][65];
    __shared__ float ckt[SMT][65];
    __shared__ float ssc[SNT][208];
    __shared__ float rowq2[SNT], rowcq[SNT];
    int tid = threadIdx.x;

    for (int i = tid; i < SNT*64; i += 256) {
        int nl = i>>6, d = i&63;
        int n = n0+nl;
        float qv=0.f, cv=0.f;
        if (n < NTOK) { size_t o=((size_t)bh*NTOK+n)*64+d; qv=qbuf[o]; cv=cqs[o]; }
        qsh[nl][d]=qv; cqsh[nl][d]=cv;
    }
    if (tid < SNT) {
        int n = n0+tid;
        rowq2[tid] = (n<NTOK)? qs2[bh*NTOK+n]:0.f;
        rowcq[tid] = (n<NTOK)? cqsum[bh*NTOK+n]:0.f;
    }
    __syncthreads();

    for (int m0=0; m0<NTOK; m0+=SMT) {
        for (int i = tid; i < SMT*64; i += 256) {
            int ml=i>>6, d=i&63; int m=m0+ml;
            float kv=0.f,cv=0.f;
            if (m<NTOK){ size_t o=((size_t)bh*NTOK+m)*64+d; kv=kbuf[o]; cv=cks[o]; }
            kt[ml][d]=kv; ckt[ml][d]=cv;
        }
        __syncthreads();
#pragma unroll
        for (int rep=0; rep<2; rep++){
            int pair = tid + rep*256;
            int nl = pair >> 5;
            int ml = pair & 31;
            int n = n0+nl, m = m0+ml;
            if (n<NTOK && m<NTOK) {
                float dm=0.f, dc=0.f;
#pragma unroll
                for (int d=0; d<64; d++){
                    dm = fmaf(qsh[nl][d],  kt[ml][d],  dm);
                    dc = fmaf(cqsh[nl][d], ckt[ml][d], dc);
                }
                float w = -2.f*dm + rowq2[nl] + ks2[bh*NTOK+m]
                          -2.f*dc + rowcq[nl] + cksum[bh*NTOK+m];
                float s = 1.f/(1.f+expf(w - 1e-24f));   /* sigmoid(-w+eps) */
                ssc[nl][m] = s + relb[((size_t)h*NTOK + n)*NTOK + m];
            }
        }
        __syncthreads();
    }
    /* softmax per row */
    int wid = tid>>5, lane = tid&31;
    for (int nl = wid; nl < SNT; nl += 8) {
        int n = n0+nl;
        if (n >= NTOK) continue;
        float mx = -1e30f;
        for (int m=lane; m<NTOK; m+=32) mx = fmaxf(mx, ssc[nl][m]);
#pragma unroll
        for (int o=16;o;o>>=1) mx = fmaxf(mx, __shfl_xor_sync(0xffffffffu,mx,o));
        float sum=0.f;
        for (int m=lane;m<NTOK;m+=32){ float e=expf(ssc[nl][m]-mx); ssc[nl][m]=e; sum+=e; }
#pragma unroll
        for (int o=16;o;o>>=1) sum += __shfl_xor_sync(0xffffffffu,sum,o);
        float inv = 1.f/sum;
        for (int m=lane;m<NTOK;m+=32)
            attn[(((size_t)bh)*NTOK+n)*NTOK+m] = ssc[nl][m]*inv;
    }
}

/* -------- AV: mean_ctx = attn@v ; cov_ctx = attn^2 @ cv ---------------- */
__global__ void __launch_bounds__(256) attn_av(const float* __restrict__ attn,
    const float* __restrict__ qkvm, const float* __restrict__ qkvc,
    float* __restrict__ mctx, float* __restrict__ cctx)
{
    int bn = blockIdx.x;           /* b*197+n */
    int b = bn/NTOK, n=bn%NTOK;
    __shared__ float ash[NHEAD][200];
    int tid=threadIdx.x;
    for (int i=tid;i<NHEAD*NTOK;i+=256){
        int h=i/NTOK, m=i%NTOK;
        ash[h][m] = attn[(((size_t)(b*NHEAD+h))*NTOK+n)*NTOK+m];
    }
    __syncthreads();
    float acc0=0.f,acc1=0.f,acc2=0.f, c0=0.f,c1=0.f,c2=0.f;
    int e0=tid, e1=tid+256, e2=tid+512;
    for (int m=0;m<NTOK;m++){
        const float* vrow  = qkvm + ((size_t)(b*NTOK+m)*3+2)*EMB;
        const float* cvrow = qkvc + ((size_t)(b*NTOK+m)*3+2)*EMB;
        float a0=ash[e0>>6][m], a1=ash[e1>>6][m], a2=ash[e2>>6][m];
        acc0 = fmaf(a0, vrow[e0], acc0);
        acc1 = fmaf(a1, vrow[e1], acc1);
        acc2 = fmaf(a2, vrow[e2], acc2);
        c0 = fmaf(a0*a0, cvrow[e0], c0);
        c1 = fmaf(a1*a1, cvrow[e1], c1);
        c2 = fmaf(a2*a2, cvrow[e2], c2);
    }
    size_t o = (size_t)bn*EMB;
    mctx[o+e0]=acc0; mctx[o+e1]=acc1; mctx[o+e2]=acc2;
    cctx[o+e0]=c0;   cctx[o+e1]=c1;   cctx[o+e2]=c2;
}

/* ------------------------------ tail ---------------------------------- */
__global__ void __launch_bounds__(256) pool_kernel(const float* __restrict__ xm, float* __restrict__ pool)
{
    int b = blockIdx.x;
    int tid=threadIdx.x;
#pragma unroll
    for (int r=0;r<3;r++){
        int e = tid + r*256;
        float s=0.f;
        for (int n=1;n<NTOK;n++) s += xm[((size_t)(b*NTOK+n))*EMB+e];
        pool[b*EMB+e]=s*(1.f/196.f);
    }
}

__global__ void head_kernel(const float* __restrict__ t, const float* __restrict__ w,
                            const float* __restrict__ hb, float* __restrict__ out)
{
    int idx = blockIdx.x*blockDim.x + threadIdx.x;
    if (idx >= BATCH*NCLS) return;
    int b = idx/NCLS, c = idx%NCLS;
    const float* tr = t + b*EMB;
    const float* wr = w + (size_t)c*EMB;
    float s = hb[c];
    for (int e=0;e<EMB;e+=4){
        float4 tv=*(const float4*)(tr+e);
        float4 wv=*(const float4*)(wr+e);
        s += tv.x*wv.x+tv.y*wv.y+tv.z*wv.z+tv.w*wv.w;
    }
    out[idx]=s;
}

/* ------------------------------ host ---------------------------------- */
static inline void gemm128(const float*A,const float*B,const float*bias,const float*gamma,
                           float*C,int M,int N,int K,int epi){
    dim3 grid(N/128,(M+127)/128);
    gemm_nt<128,128,8,8><<<grid,256>>>(A,B,bias,gamma,C,M,N,K,epi);
}
static inline void gemm64(const float*A,const float*B,const float*bias,const float*gamma,
                          float*C,int M,int N,int K,int epi){
    dim3 grid(N/128,(M+63)/64);
    gemm_nt<64,128,4,8><<<grid,256>>>(A,B,bias,gamma,C,M,N,K,epi);
}

extern "C" void kernel_launch(void* const* d_in, const int* in_sizes, int n_in,
                              void* d_out, int out_size)
{
    const float* x        = (const float*)d_in[0];
    const float* relb     = (const float*)d_in[1];
    const float* patch_w  = (const float*)d_in[2];
    const float* patch_b  = (const float*)d_in[3];
    const float* cpatch_w = (const float*)d_in[4];
    const float* cpatch_b = (const float*)d_in[5];
    const float* cls      = (const float*)d_in[6];
    const float* ccls     = (const float*)d_in[7];
    const float* n1g      = (const float*)d_in[8];
    const float* n1b      = (const float*)d_in[9];
    const float* qkvw     = (const float*)d_in[10];
    const float* qb       = (const float*)d_in[11];
    const float* vb       = (const float*)d_in[12];
    const float* cqb      = (const float*)d_in[13];
    const float* cvb      = (const float*)d_in[14];
    const float* projw    = (const float*)d_in[15];
    const float* projb    = (const float*)d_in[16];
    const float* cprojw   = (const float*)d_in[17];
    const float* cprojb   = (const float*)d_in[18];
    const float* gamma1   = (const float*)d_in[19];
    const float* gamma2   = (const float*)d_in[20];
    const float* n2g      = (const float*)d_in[21];
    const float* n2b      = (const float*)d_in[22];
    const float* fc1w     = (const float*)d_in[23];
    const float* fc1b     = (const float*)d_in[24];
    const float* fc2w     = (const float*)d_in[25];
    const float* fc2b     = (const float*)d_in[26];
    const float* fng      = (const float*)d_in[27];
    const float* fnb      = (const float*)d_in[28];
    const float* headw    = (const float*)d_in[29];
    const float* headb    = (const float*)d_in[30];
    float* out = (float*)d_out;

    float *p_patches,*p_xm,*p_xc,*p_tn,*p_qkvm,*p_qkvc,*p_qbuf,*p_kbuf,*p_cqs,*p_cks,
          *p_qs2,*p_ks2,*p_cqsum,*p_cksum,*p_attn,*p_mctx,*p_cctx,*p_hbuf,
          *p_qkvb,*p_cqkvb,*p_pool,*p_pooln;
    cudaGetSymbolAddress((void**)&p_patches, g_patches);
    cudaGetSymbolAddress((void**)&p_xm,   g_xm);
    cudaGetSymbolAddress((void**)&p_xc,   g_xc);
    cudaGetSymbolAddress((void**)&p_tn,   g_tn);
    cudaGetSymbolAddress((void**)&p_qkvm, g_qkvm);
    cudaGetSymbolAddress((void**)&p_qkvc, g_qkvc);
    cudaGetSymbolAddress((void**)&p_qbuf, g_qbuf);
    cudaGetSymbolAddress((void**)&p_kbuf, g_kbuf);
    cudaGetSymbolAddress((void**)&p_cqs,  g_cqs);
    cudaGetSymbolAddress((void**)&p_cks,  g_cks);
    cudaGetSymbolAddress((void**)&p_qs2,  g_qs2);
    cudaGetSymbolAddress((void**)&p_ks2,  g_ks2);
    cudaGetSymbolAddress((void**)&p_cqsum,g_cqsum);
    cudaGetSymbolAddress((void**)&p_cksum,g_cksum);
    cudaGetSymbolAddress((void**)&p_attn, g_attn);
    cudaGetSymbolAddress((void**)&p_mctx, g_mctx);
    cudaGetSymbolAddress((void**)&p_cctx, g_cctx);
    cudaGetSymbolAddress((void**)&p_hbuf, g_hbuf);
    cudaGetSymbolAddress((void**)&p_qkvb, g_qkvb);
    cudaGetSymbolAddress((void**)&p_cqkvb,g_cqkvb);
    cudaGetSymbolAddress((void**)&p_pool, g_pool);
    cudaGetSymbolAddress((void**)&p_pooln,g_pooln);

    build_qkvb<<<(NLAYER*E3+255)/256,256>>>(qb,vb,cqb,cvb,p_qkvb,p_cqkvb);
    im2col_kernel<<<(MROWS*EMB+255)/256,256>>>(x, p_patches);
    gemm64(p_patches, patch_w,  patch_b,  nullptr, p_xm, MROWS, EMB, EMB, EPI_BIAS);
    gemm64(p_patches, cpatch_w, cpatch_b, nullptr, p_xc, MROWS, EMB, EMB, EPI_BIAS);
    fill_cls<<<BATCH,256>>>(cls, ccls, p_xm, p_xc);

    for (int i=0;i<NLAYER;i++){
        const float* qkvw_i = qkvw + (size_t)i*E3*EMB;
        /* attention block */
        ln_kernel<<<MROWS,256>>>(p_xm, n1g+i*EMB, n1b+i*EMB, p_tn);
        gemm128(p_tn, qkvw_i, p_qkvb + i*E3,  nullptr, p_qkvm, MROWS, E3, EMB, EPI_BIAS);
        ln_kernel<<<MROWS,256>>>(p_xc, n1g+i*EMB, n1b+i*EMB, p_tn);
        gemm128(p_tn, qkvw_i, p_cqkvb + i*E3, nullptr, p_qkvc, MROWS, E3, EMB, EPI_ELU1);

        attn_pre<<<BATCH*NHEAD*NTOK,64>>>(p_qkvm,p_qkvc,p_qbuf,p_kbuf,p_cqs,p_cks,
                                          p_qs2,p_ks2,p_cqsum,p_cksum);
        attn_score<<<dim3((NTOK+SNT-1)/SNT, BATCH*NHEAD),256>>>(
            p_qbuf,p_cqs,p_kbuf,p_cks,p_qs2,p_cqsum,p_ks2,p_cksum,relb,p_attn);
        attn_av<<<MROWS,256>>>(p_attn,p_qkvm,p_qkvc,p_mctx,p_cctx);

        gemm64(p_mctx, projw  + (size_t)i*EMB*EMB, projb +i*EMB, gamma1+i*EMB, p_xm, MROWS, EMB, EMB, EPI_RES);
        gemm64(p_cctx, cprojw + (size_t)i*EMB*EMB, cprojb+i*EMB, gamma1+i*EMB, p_xc, MROWS, EMB, EMB, EPI_RES);

        /* MLP (mean path) */
        ln_kernel<<<MROWS,256>>>(p_xm, n2g+i*EMB, n2b+i*EMB, p_tn);
        gemm128(p_tn,  fc1w + (size_t)i*MLPD*EMB, fc1b+i*MLPD, nullptr,      p_hbuf, MROWS, MLPD, EMB, EPI_GELU);
        gemm64 (p_hbuf,fc2w + (size_t)i*EMB*MLPD, fc2b+i*EMB,  gamma2+i*EMB, p_xm,   MROWS, EMB, MLPD, EPI_RES);
        /* MLP (cov path, same weights) */
        ln_kernel<<<MROWS,256>>>(p_xc, n2g+i*EMB, n2b+i*EMB, p_tn);
        gemm128(p_tn,  fc1w + (size_t)i*MLPD*EMB, fc1b+i*MLPD, nullptr,      p_hbuf, MROWS, MLPD, EMB, EPI_GELU);
        gemm64 (p_hbuf,fc2w + (size_t)i*EMB*MLPD, fc2b+i*EMB,  gamma2+i*EMB, p_xc,   MROWS, EMB, MLPD, EPI_RES);
    }

    pool_kernel<<<BATCH,256>>>(p_xm, p_pool);
    ln_kernel<<<BATCH,256>>>(p_pool, fng, fnb, p_pooln);
    head_kernel<<<(BATCH*NCLS+255)/256,256>>>(p_pooln, headw, headb, out);
}

// round 3
// speedup vs baseline: 2.3234x; 2.3234x over previous
#include <cuda_runtime.h>
#include <cuda_bf16.h>
#include <stdint.h>
#include <math.h>

#define BATCH 8
#define EMB 768
#define NHEAD 12
#define NLAYER 12
#define HD 64
#define NTOK 197
#define MROWS (BATCH*NTOK)   /* 1576 */
#define MPAD 1664            /* 13*128 */
#define E3 2304
#define MLPD 3072
#define QSCALE 0.125f
#define NCLS 1000

enum { EPI_BIAS=0, EPI_ELU1=1, EPI_GELU=2, EPI_RES=3 };

/* ---------------- weight plane offsets (elements) ---------------- */
#define OFF_PW    0ULL
#define OFF_CPW   589824ULL
#define OFF_QKV   1179648ULL
#define OFF_PROJ  22413312ULL
#define OFF_CPROJ 29491200ULL
#define OFF_FC1   36569088ULL
#define OFF_FC2   64880640ULL
#define WTOT      93192192ULL

/* ------------------------------ scratch ------------------------------ */
__device__ __nv_bfloat16 g_whi[WTOT];
__device__ __nv_bfloat16 g_wlo[WTOT];

__device__ __nv_bfloat16 g_pat_hi[MPAD*EMB], g_pat_lo[MPAD*EMB];
__device__ __nv_bfloat16 g_tn_hi [MPAD*EMB], g_tn_lo [MPAD*EMB];
__device__ __nv_bfloat16 g_mc_hi [MPAD*EMB], g_mc_lo [MPAD*EMB];
__device__ __nv_bfloat16 g_cc_hi [MPAD*EMB], g_cc_lo [MPAD*EMB];
__device__ __nv_bfloat16 g_h_hi [MPAD*MLPD], g_h_lo [MPAD*MLPD];

__device__ float g_xm[MROWS*EMB];
__device__ float g_xc[MROWS*EMB];
__device__ float g_qkvm[MROWS*E3];
__device__ float g_qkvc[MROWS*E3];
__device__ float g_qbuf[BATCH*NHEAD*NTOK*HD];
__device__ float g_kbuf[BATCH*NHEAD*NTOK*HD];
__device__ float g_cqs[BATCH*NHEAD*NTOK*HD];
__device__ float g_cks[BATCH*NHEAD*NTOK*HD];
__device__ float g_qs2[BATCH*NHEAD*NTOK];
__device__ float g_ks2[BATCH*NHEAD*NTOK];
__device__ float g_cqsum[BATCH*NHEAD*NTOK];
__device__ float g_cksum[BATCH*NHEAD*NTOK];
__device__ float g_attn[BATCH*NHEAD*NTOK*NTOK];
__device__ float g_qkvb[NLAYER*E3];
__device__ float g_cqkvb[NLAYER*E3];
__device__ float g_pool[BATCH*EMB];
__device__ float g_pooln[BATCH*EMB];

/* ------------------------------ helpers ------------------------------ */
__device__ __forceinline__ uint32_t s2u(const void* p){
    return (uint32_t)__cvta_generic_to_shared(p);
}
__device__ __forceinline__ void cpa16(uint32_t dst, const void* src){
    asm volatile("cp.async.cg.shared.global [%0], [%1], 16;\n" :: "r"(dst), "l"(src));
}
__device__ __forceinline__ void mma16816(float* c, uint32_t a0,uint32_t a1,uint32_t a2,uint32_t a3,
                                         uint32_t b0,uint32_t b1){
    asm volatile("mma.sync.aligned.m16n8k16.row.col.f32.bf16.bf16.f32 "
        "{%0,%1,%2,%3},{%4,%5,%6,%7},{%8,%9},{%0,%1,%2,%3};\n"
        : "+f"(c[0]),"+f"(c[1]),"+f"(c[2]),"+f"(c[3])
        : "r"(a0),"r"(a1),"r"(a2),"r"(a3),"r"(b0),"r"(b1));
}
__device__ __forceinline__ void split_bf16(float f, __nv_bfloat16& h, __nv_bfloat16& l){
    h = __float2bfloat16(f);
    l = __float2bfloat16(f - __bfloat162float(h));
}

/* ---------------- bf16 split GEMM: C[M,N] = A[M,K]*B[N,K]^T ----------
   A,B given as hi/lo bf16 planes. 128x128x32 tiles, 8 warps (2x4),
   warp tile 64x32, mma.m16n8k16, 3-product split accumulate.        */
#define APITCH 20
#define PLANE_U32 (128*APITCH)
#define STAGE_U32 (4*PLANE_U32)
#define GEMM_SMEM (2*STAGE_U32*4)

__global__ void __launch_bounds__(256)
gemm_bf16(const __nv_bfloat16* __restrict__ Ahi, const __nv_bfloat16* __restrict__ Alo,
          const __nv_bfloat16* __restrict__ Bhi, const __nv_bfloat16* __restrict__ Blo,
          const float* __restrict__ bias, const float* __restrict__ gamma,
          float* __restrict__ C, __nv_bfloat16* __restrict__ Chi, __nv_bfloat16* __restrict__ Clo,
          int N, int K, int epi)
{
    extern __shared__ uint32_t smem[];
    const int tid = threadIdx.x;
    const int lane = tid & 31, wid = tid >> 5;
    const int wm = wid >> 2, wn = wid & 3;
    const int g = lane >> 2, tig = lane & 3;
    const int bm = blockIdx.y * 128;
    const int bn = blockIdx.x * 128;
    const int K2 = K >> 1;
    const uint32_t* gAh = (const uint32_t*)Ahi;
    const uint32_t* gAl = (const uint32_t*)Alo;
    const uint32_t* gBh = (const uint32_t*)Bhi;
    const uint32_t* gBl = (const uint32_t*)Blo;
    const uint32_t sbase_u = s2u(smem);

    float acc[4][4][4];
#pragma unroll
    for (int a=0;a<4;a++)
#pragma unroll
        for (int b=0;b<4;b++)
#pragma unroll
            for (int c=0;c<4;c++) acc[a][b][c]=0.f;

    const int KT = K >> 5;

    auto fill = [&](int buf, int kt){
        uint32_t sd = sbase_u + (uint32_t)buf*STAGE_U32*4;
        int kc0 = kt*16;
#pragma unroll
        for (int i=0;i<2;i++){
            int t = tid + i*256;
            int row = t >> 2, ch = (t & 3) * 4;
            size_t ga = (size_t)(bm+row)*K2 + kc0 + ch;
            size_t gb = (size_t)(bn+row)*K2 + kc0 + ch;
            uint32_t so = (uint32_t)(row*APITCH + ch)*4;
            cpa16(sd + so,                   gAh + ga);
            cpa16(sd + PLANE_U32*4   + so,   gAl + ga);
            cpa16(sd + 2*PLANE_U32*4 + so,   gBh + gb);
            cpa16(sd + 3*PLANE_U32*4 + so,   gBl + gb);
        }
        asm volatile("cp.async.commit_group;\n");
    };

    fill(0, 0);
    for (int kt=0; kt<KT; kt++){
        int buf = kt & 1;
        if (kt+1 < KT) fill(buf^1, kt+1);
        else asm volatile("cp.async.commit_group;\n");
        asm volatile("cp.async.wait_group 1;\n" ::: "memory");
        __syncthreads();

        const uint32_t* sAh = smem + buf*STAGE_U32;
        const uint32_t* sAl = sAh + PLANE_U32;
        const uint32_t* sBh = sAh + 2*PLANE_U32;
        const uint32_t* sBl = sAh + 3*PLANE_U32;

#pragma unroll
        for (int ks=0; ks<2; ks++){
            const int kc = ks*8 + tig;
            uint32_t bh[4][2], bl[4][2];
#pragma unroll
            for (int nt=0;nt<4;nt++){
                int n = wn*32 + nt*8 + g;
                bh[nt][0]=sBh[n*APITCH+kc]; bh[nt][1]=sBh[n*APITCH+kc+4];
                bl[nt][0]=sBl[n*APITCH+kc]; bl[nt][1]=sBl[n*APITCH+kc+4];
            }
#pragma unroll
            for (int mt=0;mt<4;mt++){
                int m = wm*64 + mt*16 + g;
                uint32_t ah0=sAh[m*APITCH+kc],     ah1=sAh[(m+8)*APITCH+kc];
                uint32_t ah2=sAh[m*APITCH+kc+4],   ah3=sAh[(m+8)*APITCH+kc+4];
                uint32_t al0=sAl[m*APITCH+kc],     al1=sAl[(m+8)*APITCH+kc];
                uint32_t al2=sAl[m*APITCH+kc+4],   al3=sAl[(m+8)*APITCH+kc+4];
#pragma unroll
                for (int nt=0;nt<4;nt++){
                    mma16816(acc[mt][nt], ah0,ah1,ah2,ah3, bh[nt][0],bh[nt][1]);
                    mma16816(acc[mt][nt], ah0,ah1,ah2,ah3, bl[nt][0],bl[nt][1]);
                    mma16816(acc[mt][nt], al0,al1,al2,al3, bh[nt][0],bh[nt][1]);
                }
            }
        }
        __syncthreads();
    }

    /* epilogue */
#pragma unroll
    for (int mt=0;mt<4;mt++){
        int gm0 = bm + wm*64 + mt*16 + g;
#pragma unroll
        for (int half=0; half<2; half++){
            int gm = gm0 + half*8;
            if (gm >= MROWS) continue;
#pragma unroll
            for (int nt=0;nt<4;nt++){
                int gn = bn + wn*32 + nt*8 + tig*2;
                float z0 = acc[mt][nt][half*2+0];
                float z1 = acc[mt][nt][half*2+1];
                if (bias){ z0 += bias[gn]; z1 += bias[gn+1]; }
                if (epi == EPI_BIAS){
                    float2 o = make_float2(z0, z1);
                    *(float2*)(C + (size_t)gm*N + gn) = o;
                } else if (epi == EPI_ELU1){
                    float o0 = (z0>0.f)? z0+1.f : expf(z0);
                    float o1 = (z1>0.f)? z1+1.f : expf(z1);
                    *(float2*)(C + (size_t)gm*N + gn) = make_float2(o0,o1);
                } else if (epi == EPI_GELU){
                    float o0 = 0.5f*z0*(1.f+erff(z0*0.70710678118f));
                    float o1 = 0.5f*z1*(1.f+erff(z1*0.70710678118f));
                    __nv_bfloat16 h0,l0,h1,l1;
                    split_bf16(o0,h0,l0); split_bf16(o1,h1,l1);
                    __nv_bfloat162 hv; hv.x=h0; hv.y=h1;
                    __nv_bfloat162 lv; lv.x=l0; lv.y=l1;
                    *(__nv_bfloat162*)(Chi + (size_t)gm*N + gn) = hv;
                    *(__nv_bfloat162*)(Clo + (size_t)gm*N + gn) = lv;
                } else {
                    float2 old = *(const float2*)(C + (size_t)gm*N + gn);
                    float o0 = old.x + gamma[gn]*z0;
                    float o1 = old.y + gamma[gn+1]*z1;
                    *(float2*)(C + (size_t)gm*N + gn) = make_float2(o0,o1);
                }
            }
        }
    }
}

/* ---------------- weight split (vectorized) ---------------- */
__global__ void wsplit4(const float4* __restrict__ src, __nv_bfloat16* __restrict__ hi,
                        __nv_bfloat16* __restrict__ lo, size_t n4)
{
    size_t i = (size_t)blockIdx.x*256 + threadIdx.x;
    if (i >= n4) return;
    float4 f = src[i];
    __nv_bfloat16 h0,l0,h1,l1,h2,l2,h3,l3;
    split_bf16(f.x,h0,l0); split_bf16(f.y,h1,l1);
    split_bf16(f.z,h2,l2); split_bf16(f.w,h3,l3);
    __nv_bfloat162 a,b,c,d;
    a.x=h0;a.y=h1; b.x=h2;b.y=h3; c.x=l0;c.y=l1; d.x=l2;d.y=l3;
    *(__nv_bfloat162*)(hi + 4*i)   = a;
    *(__nv_bfloat162*)(hi + 4*i+2) = b;
    *(__nv_bfloat162*)(lo + 4*i)   = c;
    *(__nv_bfloat162*)(lo + 4*i+2) = d;
}

/* ---------------- LayerNorm -> bf16 hi/lo planes ---------------- */
__global__ void __launch_bounds__(256) ln_split(const float* __restrict__ x,
        const float* __restrict__ g, const float* __restrict__ b,
        __nv_bfloat16* __restrict__ yh, __nv_bfloat16* __restrict__ yl)
{
    int row = blockIdx.x;
    const float* xr = x + (size_t)row*EMB;
    int tid = threadIdx.x;
    float v0=xr[tid], v1=xr[tid+256], v2=xr[tid+512];
    float s  = v0+v1+v2;
    float s2 = v0*v0+v1*v1+v2*v2;
    __shared__ float red[2][8];
    int lane=tid&31, wid=tid>>5;
#pragma unroll
    for(int o=16;o;o>>=1){ s+=__shfl_xor_sync(0xffffffffu,s,o); s2+=__shfl_xor_sync(0xffffffffu,s2,o); }
    if(!lane){ red[0][wid]=s; red[1][wid]=s2; }
    __syncthreads();
    s=0.f; s2=0.f;
#pragma unroll
    for (int i=0;i<8;i++){ s+=red[0][i]; s2+=red[1][i]; }
    float mu = s * (1.f/768.f);
    float var = s2*(1.f/768.f) - mu*mu;
    float inv = rsqrtf(var + 1e-5f);
    size_t o0 = (size_t)row*EMB;
#pragma unroll
    for (int r=0;r<3;r++){
        int e = tid + r*256;
        float v = (r==0)?v0:((r==1)?v1:v2);
        float y = (v-mu)*inv*g[e] + b[e];
        __nv_bfloat16 h,l; split_bf16(y,h,l);
        yh[o0+e]=h; yl[o0+e]=l;
    }
}

/* fp32 LayerNorm for the final pooled vector */
__global__ void __launch_bounds__(256) ln_f32(const float* __restrict__ x,
        const float* __restrict__ g, const float* __restrict__ b,
        float* __restrict__ y)
{
    int row = blockIdx.x;
    const float* xr = x + (size_t)row*EMB;
    float* yr = y + (size_t)row*EMB;
    int tid = threadIdx.x;
    float v0=xr[tid], v1=xr[tid+256], v2=xr[tid+512];
    float s  = v0+v1+v2;
    float s2 = v0*v0+v1*v1+v2*v2;
    __shared__ float red[2][8];
    int lane=tid&31, wid=tid>>5;
#pragma unroll
    for(int o=16;o;o>>=1){ s+=__shfl_xor_sync(0xffffffffu,s,o); s2+=__shfl_xor_sync(0xffffffffu,s2,o); }
    if(!lane){ red[0][wid]=s; red[1][wid]=s2; }
    __syncthreads();
    s=0.f; s2=0.f;
#pragma unroll
    for (int i=0;i<8;i++){ s+=red[0][i]; s2+=red[1][i]; }
    float mu = s * (1.f/768.f);
    float var = s2*(1.f/768.f) - mu*mu;
    float inv = rsqrtf(var + 1e-5f);
    yr[tid]     = (v0-mu)*inv*g[tid]     + b[tid];
    yr[tid+256] = (v1-mu)*inv*g[tid+256] + b[tid+256];
    yr[tid+512] = (v2-mu)*inv*g[tid+512] + b[tid+512];
}

/* ---------------- im2col -> bf16 planes ---------------- */
__global__ void im2col_split(const float* __restrict__ x,
                             __nv_bfloat16* __restrict__ ph, __nv_bfloat16* __restrict__ pl)
{
    int idx = blockIdx.x*blockDim.x + threadIdx.x;
    if (idx >= MROWS*EMB) return;
    int r = idx / EMB, col = idx % EMB;
    int b = r / NTOK, t = r % NTOK;
    float v = 0.f;
    if (t > 0){
        int pp = t-1;
        int py = pp/14, px = pp%14;
        int c = col >> 8, phh = (col>>4)&15, pw = col&15;
        v = x[(((size_t)b*3 + c)*224 + py*16+phh)*224 + px*16+pw];
    }
    __nv_bfloat16 h,l; split_bf16(v,h,l);
    ph[idx]=h; pl[idx]=l;
}

__global__ void fill_cls(const float* __restrict__ cls, const float* __restrict__ ccls,
                         float* __restrict__ xm, float* __restrict__ xc)
{
    int b = blockIdx.x, tid=threadIdx.x;
#pragma unroll
    for (int r=0;r<3;r++){
        int e = tid+r*256;
        xm[(size_t)b*NTOK*EMB+e]=cls[e];
        xc[(size_t)b*NTOK*EMB+e]=ccls[e];
    }
}

__global__ void build_qkvb(const float* __restrict__ qb, const float* __restrict__ vb,
                           const float* __restrict__ cqb, const float* __restrict__ cvb,
                           float* __restrict__ outv, float* __restrict__ coutv)
{
    int idx = blockIdx.x*blockDim.x+threadIdx.x;
    if (idx >= NLAYER*E3) return;
    int l = idx / E3, j = idx % E3;
    float v=0.f, cv=0.f;
    if (j < EMB)        { v=qb[l*EMB+j];        cv=cqb[l*EMB+j]; }
    else if (j >= 2*EMB){ v=vb[l*EMB+j-2*EMB];  cv=cvb[l*EMB+j-2*EMB]; }
    outv[idx]=v; coutv[idx]=cv;
}

/* -------- attention preprocess -------- */
__global__ void __launch_bounds__(64) attn_pre(const float* __restrict__ qkvm, const float* __restrict__ qkvc,
   float* __restrict__ qb, float* __restrict__ kb, float* __restrict__ cqs, float* __restrict__ cks,
   float* __restrict__ qs2, float* __restrict__ ks2, float* __restrict__ cqsum, float* __restrict__ cksum)
{
    int idx = blockIdx.x;
    int t  = idx % NTOK;
    int bh = idx / NTOK;
    int h  = bh % NHEAD;
    int b  = bh / NHEAD;
    int d  = threadIdx.x;
    size_t base = ((size_t)(b*NTOK+t)*3)*EMB + h*HD + d;
    float q  = qkvm[base]*QSCALE;
    float k  = qkvm[base+EMB];
    float cq = qkvc[base];
    float ck = qkvc[base+EMB];
    float sq = sqrtf(fmaxf(cq,1e-24f));
    float sk = sqrtf(fmaxf(ck,1e-24f));
    size_t o = (size_t)idx*HD + d;
    qb[o]=q; kb[o]=k; cqs[o]=sq; cks[o]=sk;
    float r0=q*q, r1=k*k, r2=cq, r3=ck;
#pragma unroll
    for(int off=16;off;off>>=1){
        r0+=__shfl_xor_sync(0xffffffffu,r0,off);
        r1+=__shfl_xor_sync(0xffffffffu,r1,off);
        r2+=__shfl_xor_sync(0xffffffffu,r2,off);
        r3+=__shfl_xor_sync(0xffffffffu,r3,off);
    }
    __shared__ float sh[4][2];
    int lane=d&31, w=d>>5;
    if(!lane){ sh[0][w]=r0; sh[1][w]=r1; sh[2][w]=r2; sh[3][w]=r3; }
    __syncthreads();
    if (d==0){
        qs2[idx]  =sh[0][0]+sh[0][1];
        ks2[idx]  =sh[1][0]+sh[1][1];
        cqsum[idx]=sh[2][0]+sh[2][1];
        cksum[idx]=sh[3][0]+sh[3][1];
    }
}

/* -------- Wasserstein scores + sigmoid + bias + softmax -------- */
#define SNT 16
#define SMT 32
__global__ void __launch_bounds__(256) attn_score(
    const float* __restrict__ qbuf, const float* __restrict__ cqs,
    const float* __restrict__ kbuf, const float* __restrict__ cks,
    const float* __restrict__ qs2,  const float* __restrict__ cqsum,
    const float* __restrict__ ks2,  const float* __restrict__ cksum,
    const float* __restrict__ relb, float* __restrict__ attn)
{
    int bh = blockIdx.y;
    int h  = bh % NHEAD;
    int n0 = blockIdx.x * SNT;
    __shared__ float qsh[SNT][64];
    __shared__ float cqsh[SNT][64];
    __shared__ float kt[SMT][65];
    __shared__ float ckt[SMT][65];
    __shared__ float ssc[SNT][208];
    __shared__ float rowq2[SNT], rowcq[SNT];
    int tid = threadIdx.x;

    for (int i = tid; i < SNT*64; i += 256) {
        int nl = i>>6, d = i&63;
        int n = n0+nl;
        float qv=0.f, cv=0.f;
        if (n < NTOK) { size_t o=((size_t)bh*NTOK+n)*64+d; qv=qbuf[o]; cv=cqs[o]; }
        qsh[nl][d]=qv; cqsh[nl][d]=cv;
    }
    if (tid < SNT) {
        int n = n0+tid;
        rowq2[tid] = (n<NTOK)? qs2[bh*NTOK+n]:0.f;
        rowcq[tid] = (n<NTOK)? cqsum[bh*NTOK+n]:0.f;
    }
    __syncthreads();

    for (int m0=0; m0<NTOK; m0+=SMT) {
        for (int i = tid; i < SMT*64; i += 256) {
            int ml=i>>6, d=i&63; int m=m0+ml;
            float kv=0.f,cv=0.f;
            if (m<NTOK){ size_t o=((size_t)bh*NTOK+m)*64+d; kv=kbuf[o]; cv=cks[o]; }
            kt[ml][d]=kv; ckt[ml][d]=cv;
        }
        __syncthreads();
#pragma unroll
        for (int rep=0; rep<2; rep++){
            int pair = tid + rep*256;
            int nl = pair >> 5;
            int ml = pair & 31;
            int n = n0+nl, m = m0+ml;
            if (n<NTOK && m<NTOK) {
                float dm=0.f, dc=0.f;
#pragma unroll
                for (int d=0; d<64; d++){
                    dm = fmaf(qsh[nl][d],  kt[ml][d],  dm);
                    dc = fmaf(cqsh[nl][d], ckt[ml][d], dc);
                }
                float w = -2.f*dm + rowq2[nl] + ks2[bh*NTOK+m]
                          -2.f*dc + rowcq[nl] + cksum[bh*NTOK+m];
                float s = 1.f/(1.f+expf(w - 1e-24f));
                ssc[nl][m] = s + relb[((size_t)h*NTOK + n)*NTOK + m];
            }
        }
        __syncthreads();
    }
    int wid = tid>>5, lane = tid&31;
    for (int nl = wid; nl < SNT; nl += 8) {
        int n = n0+nl;
        if (n >= NTOK) continue;
        float mx = -1e30f;
        for (int m=lane; m<NTOK; m+=32) mx = fmaxf(mx, ssc[nl][m]);
#pragma unroll
        for (int o=16;o;o>>=1) mx = fmaxf(mx, __shfl_xor_sync(0xffffffffu,mx,o));
        float sum=0.f;
        for (int m=lane;m<NTOK;m+=32){ float e=expf(ssc[nl][m]-mx); ssc[nl][m]=e; sum+=e; }
#pragma unroll
        for (int o=16;o;o>>=1) sum += __shfl_xor_sync(0xffffffffu,sum,o);
        float inv = 1.f/sum;
        for (int m=lane;m<NTOK;m+=32)
            attn[(((size_t)bh)*NTOK+n)*NTOK+m] = ssc[nl][m]*inv;
    }
}

/* -------- AV: mean_ctx / cov_ctx, tiled, writes bf16 planes -------- */
__global__ void __launch_bounds__(256) attn_av2(const float* __restrict__ attn,
    const float* __restrict__ qkvm, const float* __restrict__ qkvc,
    __nv_bfloat16* __restrict__ mhi, __nv_bfloat16* __restrict__ mlo,
    __nv_bfloat16* __restrict__ chi, __nv_bfloat16* __restrict__ clo)
{
    int h  = blockIdx.x;            /* head 0..11 -> e0 = h*64 */
    int n0 = blockIdx.y * 32;
    int b  = blockIdx.z;
    int e0 = h * 64;
    __shared__ float sat[32][200];
    __shared__ float sv[32][64], scv[32][64];
    int tid = threadIdx.x;
    int wid = tid>>5, lane = tid&31;

    for (int r = wid; r < 32; r += 8){
        int n = n0 + r;
        if (n < NTOK){
            const float* src = attn + (((size_t)(b*NHEAD+h))*NTOK + n)*NTOK;
            for (int m=lane; m<NTOK; m+=32) sat[r][m] = src[m];
        } else {
            for (int m=lane; m<NTOK; m+=32) sat[r][m] = 0.f;
        }
    }

    float acc[2][4]={{0}}, cac[2][4]={{0}};
    int ew = (tid & 15) * 4;
    int nb = (tid >> 4) * 2;

    for (int m0=0; m0<NTOK; m0+=32){
        __syncthreads();
        for (int i = tid; i < 32*16; i += 256){
            int mr = i >> 4, c4 = (i & 15)*4;
            int m = m0 + mr;
            float4 v = make_float4(0,0,0,0), cv = make_float4(0,0,0,0);
            if (m < NTOK){
                size_t base = ((size_t)(b*NTOK+m)*3+2)*EMB + e0 + c4;
                v  = *(const float4*)(qkvm + base);
                cv = *(const float4*)(qkvc + base);
            }
            *(float4*)&sv[mr][c4]  = v;
            *(float4*)&scv[mr][c4] = cv;
        }
        __syncthreads();
        int mlim = min(32, NTOK-m0);
        for (int mm=0; mm<mlim; mm++){
            float4 v  = *(const float4*)&sv[mm][ew];
            float4 cv = *(const float4*)&scv[mm][ew];
#pragma unroll
            for (int i=0;i<2;i++){
                float a = sat[nb+i][m0+mm];
                float a2 = a*a;
                acc[i][0]=fmaf(a,v.x,acc[i][0]); acc[i][1]=fmaf(a,v.y,acc[i][1]);
                acc[i][2]=fmaf(a,v.z,acc[i][2]); acc[i][3]=fmaf(a,v.w,acc[i][3]);
                cac[i][0]=fmaf(a2,cv.x,cac[i][0]); cac[i][1]=fmaf(a2,cv.y,cac[i][1]);
                cac[i][2]=fmaf(a2,cv.z,cac[i][2]); cac[i][3]=fmaf(a2,cv.w,cac[i][3]);
            }
        }
    }
#pragma unroll
    for (int i=0;i<2;i++){
        int n = n0 + nb + i;
        if (n >= NTOK) continue;
        size_t base = ((size_t)(b*NTOK+n))*EMB + e0 + ew;
#pragma unroll
        for (int j=0;j<4;j++){
            __nv_bfloat16 hh,ll;
            split_bf16(acc[i][j],hh,ll); mhi[base+j]=hh; mlo[base+j]=ll;
            split_bf16(cac[i][j],hh,ll); chi[base+j]=hh; clo[base+j]=ll;
        }
    }
}

/* ------------------------------ tail ---------------------------------- */
__global__ void __launch_bounds__(256) pool_kernel(const float* __restrict__ xm, float* __restrict__ pool)
{
    int b = blockIdx.x;
    int tid=threadIdx.x;
#pragma unroll
    for (int r=0;r<3;r++){
        int e = tid + r*256;
        float s=0.f;
        for (int n=1;n<NTOK;n++) s += xm[((size_t)(b*NTOK+n))*EMB+e];
        pool[b*EMB+e]=s*(1.f/196.f);
    }
}

__global__ void head_kernel(const float* __restrict__ t, const float* __restrict__ w,
                            const float* __restrict__ hb, float* __restrict__ out)
{
    int idx = blockIdx.x*blockDim.x + threadIdx.x;
    if (idx >= BATCH*NCLS) return;
    int b = idx/NCLS, c = idx%NCLS;
    const float* tr = t + b*EMB;
    const float* wr = w + (size_t)c*EMB;
    float s = hb[c];
    for (int e=0;e<EMB;e+=4){
        float4 tv=*(const float4*)(tr+e);
        float4 wv=*(const float4*)(wr+e);
        s += tv.x*wv.x+tv.y*wv.y+tv.z*wv.z+tv.w*wv.w;
    }
    out[idx]=s;
}

/* ------------------------------ host ---------------------------------- */
static inline void launch_gemm(const __nv_bfloat16* Ahi, const __nv_bfloat16* Alo,
    const __nv_bfloat16* Bhi, const __nv_bfloat16* Blo,
    const float* bias, const float* gamma,
    float* C, __nv_bfloat16* Chi, __nv_bfloat16* Clo, int N, int K, int epi)
{
    dim3 grid(N/128, MPAD/128);
    gemm_bf16<<<grid, 256, GEMM_SMEM>>>(Ahi,Alo,Bhi,Blo,bias,gamma,C,Chi,Clo,N,K,epi);
}

extern "C" void kernel_launch(void* const* d_in, const int* in_sizes, int n_in,
                              void* d_out, int out_size)
{
    const float* x        = (const float*)d_in[0];
    const float* relb     = (const float*)d_in[1];
    const float* patch_w  = (const float*)d_in[2];
    const float* patch_b  = (const float*)d_in[3];
    const float* cpatch_w = (const float*)d_in[4];
    const float* cpatch_b = (const float*)d_in[5];
    const float* cls      = (const float*)d_in[6];
    const float* ccls     = (const float*)d_in[7];
    const float* n1g      = (const float*)d_in[8];
    const float* n1b      = (const float*)d_in[9];
    const float* qkvw     = (const float*)d_in[10];
    const float* qb       = (const float*)d_in[11];
    const float* vb       = (const float*)d_in[12];
    const float* cqb      = (const float*)d_in[13];
    const float* cvb      = (const float*)d_in[14];
    const float* projw    = (const float*)d_in[15];
    const float* projb    = (const float*)d_in[16];
    const float* cprojw   = (const float*)d_in[17];
    const float* cprojb   = (const float*)d_in[18];
    const float* gamma1   = (const float*)d_in[19];
    const float* gamma2   = (const float*)d_in[20];
    const float* n2g      = (const float*)d_in[21];
    const float* n2b      = (const float*)d_in[22];
    const float* fc1w     = (const float*)d_in[23];
    const float* fc1b     = (const float*)d_in[24];
    const float* fc2w     = (const float*)d_in[25];
    const float* fc2b     = (const float*)d_in[26];
    const float* fng      = (const float*)d_in[27];
    const float* fnb      = (const float*)d_in[28];
    const float* headw    = (const float*)d_in[29];
    const float* headb    = (const float*)d_in[30];
    float* out = (float*)d_out;

    static int smem_set = 0;
    if (!smem_set){
        cudaFuncSetAttribute(gemm_bf16, cudaFuncAttributeMaxDynamicSharedMemorySize, GEMM_SMEM);
        smem_set = 1;
    }

    __nv_bfloat16 *whi,*wlo,*pat_hi,*pat_lo,*tn_hi,*tn_lo,*mc_hi,*mc_lo,*cc_hi,*cc_lo,*h_hi,*h_lo;
    float *p_xm,*p_xc,*p_qkvm,*p_qkvc,*p_qbuf,*p_kbuf,*p_cqs,*p_cks,
          *p_qs2,*p_ks2,*p_cqsum,*p_cksum,*p_attn,*p_qkvb,*p_cqkvb,*p_pool,*p_pooln;
    cudaGetSymbolAddress((void**)&whi, g_whi);
    cudaGetSymbolAddress((void**)&wlo, g_wlo);
    cudaGetSymbolAddress((void**)&pat_hi, g_pat_hi);
    cudaGetSymbolAddress((void**)&pat_lo, g_pat_lo);
    cudaGetSymbolAddress((void**)&tn_hi, g_tn_hi);
    cudaGetSymbolAddress((void**)&tn_lo, g_tn_lo);
    cudaGetSymbolAddress((void**)&mc_hi, g_mc_hi);
    cudaGetSymbolAddress((void**)&mc_lo, g_mc_lo);
    cudaGetSymbolAddress((void**)&cc_hi, g_cc_hi);
    cudaGetSymbolAddress((void**)&cc_lo, g_cc_lo);
    cudaGetSymbolAddress((void**)&h_hi, g_h_hi);
    cudaGetSymbolAddress((void**)&h_lo, g_h_lo);
    cudaGetSymbolAddress((void**)&p_xm,   g_xm);
    cudaGetSymbolAddress((void**)&p_xc,   g_xc);
    cudaGetSymbolAddress((void**)&p_qkvm, g_qkvm);
    cudaGetSymbolAddress((void**)&p_qkvc, g_qkvc);
    cudaGetSymbolAddress((void**)&p_qbuf, g_qbuf);
    cudaGetSymbolAddress((void**)&p_kbuf, g_kbuf);
    cudaGetSymbolAddress((void**)&p_cqs,  g_cqs);
    cudaGetSymbolAddress((void**)&p_cks,  g_cks);
    cudaGetSymbolAddress((void**)&p_qs2,  g_qs2);
    cudaGetSymbolAddress((void**)&p_ks2,  g_ks2);
    cudaGetSymbolAddress((void**)&p_cqsum,g_cqsum);
    cudaGetSymbolAddress((void**)&p_cksum,g_cksum);
    cudaGetSymbolAddress((void**)&p_attn, g_attn);
    cudaGetSymbolAddress((void**)&p_qkvb, g_qkvb);
    cudaGetSymbolAddress((void**)&p_cqkvb,g_cqkvb);
    cudaGetSymbolAddress((void**)&p_pool, g_pool);
    cudaGetSymbolAddress((void**)&p_pooln,g_pooln);

    /* weight splits */
    auto wsp = [&](const float* src, size_t off, size_t cnt){
        size_t n4 = cnt/4;
        wsplit4<<<(unsigned)((n4+255)/256),256>>>((const float4*)src, whi+off, wlo+off, n4);
    };
    wsp(patch_w,  OFF_PW,    589824);
    wsp(cpatch_w, OFF_CPW,   589824);
    wsp(qkvw,     OFF_QKV,   21233664);
    wsp(projw,    OFF_PROJ,  7077888);
    wsp(cprojw,   OFF_CPROJ, 7077888);
    wsp(fc1w,     OFF_FC1,   28311552);
    wsp(fc2w,     OFF_FC2,   28311552);

    build_qkvb<<<(NLAYER*E3+255)/256,256>>>(qb,vb,cqb,cvb,p_qkvb,p_cqkvb);
    im2col_split<<<(MROWS*EMB+255)/256,256>>>(x, pat_hi, pat_lo);

    launch_gemm(pat_hi,pat_lo, whi+OFF_PW,  wlo+OFF_PW,  patch_b,  nullptr, p_xm, nullptr,nullptr, EMB, EMB, EPI_BIAS);
    launch_gemm(pat_hi,pat_lo, whi+OFF_CPW, wlo+OFF_CPW, cpatch_b, nullptr, p_xc, nullptr,nullptr, EMB, EMB, EPI_BIAS);
    fill_cls<<<BATCH,256>>>(cls, ccls, p_xm, p_xc);

    for (int i=0;i<NLAYER;i++){
        size_t qkv_o  = OFF_QKV   + (size_t)i*E3*EMB;
        size_t proj_o = OFF_PROJ  + (size_t)i*EMB*EMB;
        size_t cprj_o = OFF_CPROJ + (size_t)i*EMB*EMB;
        size_t fc1_o  = OFF_FC1   + (size_t)i*MLPD*EMB;
        size_t fc2_o  = OFF_FC2   + (size_t)i*EMB*MLPD;

        ln_split<<<MROWS,256>>>(p_xm, n1g+i*EMB, n1b+i*EMB, tn_hi, tn_lo);
        launch_gemm(tn_hi,tn_lo, whi+qkv_o, wlo+qkv_o, p_qkvb+i*E3, nullptr, p_qkvm, nullptr,nullptr, E3, EMB, EPI_BIAS);
        ln_split<<<MROWS,256>>>(p_xc, n1g+i*EMB, n1b+i*EMB, tn_hi, tn_lo);
        launch_gemm(tn_hi,tn_lo, whi+qkv_o, wlo+qkv_o, p_cqkvb+i*E3, nullptr, p_qkvc, nullptr,nullptr, E3, EMB, EPI_ELU1);

        attn_pre<<<BATCH*NHEAD*NTOK,64>>>(p_qkvm,p_qkvc,p_qbuf,p_kbuf,p_cqs,p_cks,
                                          p_qs2,p_ks2,p_cqsum,p_cksum);
        attn_score<<<dim3((NTOK+SNT-1)/SNT, BATCH*NHEAD),256>>>(
            p_qbuf,p_cqs,p_kbuf,p_cks,p_qs2,p_cqsum,p_ks2,p_cksum,relb,p_attn);
        attn_av2<<<dim3(NHEAD,(NTOK+31)/32,BATCH),256>>>(p_attn,p_qkvm,p_qkvc,
                                                         mc_hi,mc_lo,cc_hi,cc_lo);

        launch_gemm(mc_hi,mc_lo, whi+proj_o, wlo+proj_o, projb +i*EMB, gamma1+i*EMB, p_xm, nullptr,nullptr, EMB, EMB, EPI_RES);
        launch_gemm(cc_hi,cc_lo, whi+cprj_o, wlo+cprj_o, cprojb+i*EMB, gamma1+i*EMB, p_xc, nullptr,nullptr, EMB, EMB, EPI_RES);

        ln_split<<<MROWS,256>>>(p_xm, n2g+i*EMB, n2b+i*EMB, tn_hi, tn_lo);
        launch_gemm(tn_hi,tn_lo, whi+fc1_o, wlo+fc1_o, fc1b+i*MLPD, nullptr, nullptr, h_hi, h_lo, MLPD, EMB, EPI_GELU);
        launch_gemm(h_hi,h_lo,   whi+fc2_o, wlo+fc2_o, fc2b+i*EMB, gamma2+i*EMB, p_xm, nullptr,nullptr, EMB, MLPD, EPI_RES);

        ln_split<<<MROWS,256>>>(p_xc, n2g+i*EMB, n2b+i*EMB, tn_hi, tn_lo);
        launch_gemm(tn_hi,tn_lo, whi+fc1_o, wlo+fc1_o, fc1b+i*MLPD, nullptr, nullptr, h_hi, h_lo, MLPD, EMB, EPI_GELU);
        launch_gemm(h_hi,h_lo,   whi+fc2_o, wlo+fc2_o, fc2b+i*EMB, gamma2+i*EMB, p_xc, nullptr,nullptr, EMB, MLPD, EPI_RES);
    }

    pool_kernel<<<BATCH,256>>>(p_xm, p_pool);
    ln_f32<<<BATCH,256>>>(p_pool, fng, fnb, p_pooln);
    head_kernel<<<(BATCH*NCLS+255)/256,256>>>(p_pooln, headw, headb, out);
}

// round 4
// speedup vs baseline: 2.6197x; 1.1275x over previous
#include <cuda_runtime.h>
#include <cuda_bf16.h>
#include <stdint.h>
#include <math.h>

#define BATCH 8
#define EMB 768
#define NHEAD 12
#define NLAYER 12
#define HD 64
#define NTOK 197
#define MROWS (BATCH*NTOK)   /* 1576 */
#define MPAD 1664            /* 13*128 */
#define E3 2304
#define MLPD 3072
#define QSCALE 0.125f
#define NCLS 1000

enum { EPI_BIAS=0, EPI_ELU1=1, EPI_GELU=2, EPI_RES=3 };

/* ---------------- weight plane offsets (elements) ---------------- */
#define OFF_PW    0ULL
#define OFF_CPW   589824ULL
#define OFF_QKV   1179648ULL
#define OFF_PROJ  22413312ULL
#define OFF_CPROJ 29491200ULL
#define OFF_FC1   36569088ULL
#define OFF_FC2   64880640ULL
#define WTOT      93192192ULL

/* ------------------------------ scratch ------------------------------ */
__device__ __nv_bfloat16 g_whi[WTOT];
__device__ __nv_bfloat16 g_wlo[WTOT];

__device__ __nv_bfloat16 g_pat_hi[MPAD*EMB],    g_pat_lo[MPAD*EMB];
__device__ __nv_bfloat16 g_tn_hi [2*MPAD*EMB],  g_tn_lo [2*MPAD*EMB];
__device__ __nv_bfloat16 g_ctx_hi[2*MPAD*EMB],  g_ctx_lo[2*MPAD*EMB];
__device__ __nv_bfloat16 g_h_hi  [2*(size_t)MPAD*MLPD], g_h_lo[2*(size_t)MPAD*MLPD];

__device__ float g_x[2*MROWS*EMB];        /* mean rows [0,MROWS), cov rows [MROWS,2MROWS) */
__device__ float g_qkv[2*(size_t)MROWS*E3];
__device__ float g_qbuf[BATCH*NHEAD*NTOK*HD];
__device__ float g_kbuf[BATCH*NHEAD*NTOK*HD];
__device__ float g_cqs[BATCH*NHEAD*NTOK*HD];
__device__ float g_cks[BATCH*NHEAD*NTOK*HD];
__device__ float g_qs2[BATCH*NHEAD*NTOK];
__device__ float g_ks2[BATCH*NHEAD*NTOK];
__device__ float g_cqsum[BATCH*NHEAD*NTOK];
__device__ float g_cksum[BATCH*NHEAD*NTOK];
__device__ float g_attn[(size_t)BATCH*NHEAD*NTOK*NTOK];
__device__ float g_qkvb[NLAYER*E3];
__device__ float g_cqkvb[NLAYER*E3];
__device__ float g_pool[BATCH*EMB];
__device__ float g_pooln[BATCH*EMB];

/* ------------------------------ helpers ------------------------------ */
__device__ __forceinline__ uint32_t s2u(const void* p){
    return (uint32_t)__cvta_generic_to_shared(p);
}
__device__ __forceinline__ void cpa16(uint32_t dst, const void* src){
    asm volatile("cp.async.cg.shared.global [%0], [%1], 16;\n" :: "r"(dst), "l"(src));
}
__device__ __forceinline__ void mma16816(float* c, uint32_t a0,uint32_t a1,uint32_t a2,uint32_t a3,
                                         uint32_t b0,uint32_t b1){
    asm volatile("mma.sync.aligned.m16n8k16.row.col.f32.bf16.bf16.f32 "
        "{%0,%1,%2,%3},{%4,%5,%6,%7},{%8,%9},{%0,%1,%2,%3};\n"
        : "+f"(c[0]),"+f"(c[1]),"+f"(c[2]),"+f"(c[3])
        : "r"(a0),"r"(a1),"r"(a2),"r"(a3),"r"(b0),"r"(b1));
}
__device__ __forceinline__ void split_bf16(float f, __nv_bfloat16& h, __nv_bfloat16& l){
    h = __float2bfloat16(f);
    l = __float2bfloat16(f - __bfloat162float(h));
}

/* ---------------- unified split-bf16 GEMM ----------------
   grid = (N/128, 13, 2).  z = half (0 = mean path, 1 = cov path).
   A planes live in padded row space: row = (aShared?0:half*MPAD) + lm.
   B planes, bias, epilogue selected per half.
   float C rows = half*MROWS + lm; bf16 plane C rows = half*MPAD + lm. */
#define APITCH 20
#define PLANE_U32 (128*APITCH)
#define STAGE_U32 (4*PLANE_U32)
#define GEMM_SMEM (2*STAGE_U32*4)

__global__ void __launch_bounds__(256)
gemm_bf16(const __nv_bfloat16* __restrict__ Ahi, const __nv_bfloat16* __restrict__ Alo,
          const __nv_bfloat16* __restrict__ Bhi0, const __nv_bfloat16* __restrict__ Blo0,
          const __nv_bfloat16* __restrict__ Bhi1, const __nv_bfloat16* __restrict__ Blo1,
          const float* __restrict__ bias0, const float* __restrict__ bias1,
          const float* __restrict__ gamma,
          float* __restrict__ C, __nv_bfloat16* __restrict__ Chi, __nv_bfloat16* __restrict__ Clo,
          int N, int K, int epi0, int epi1, int aShared)
{
    extern __shared__ uint32_t smem[];
    const int tid = threadIdx.x;
    const int lane = tid & 31, wid = tid >> 5;
    const int wm = wid >> 2, wn = wid & 3;
    const int g = lane >> 2, tig = lane & 3;
    const int half = blockIdx.z;
    const int lmBase = blockIdx.y * 128;
    const int aBase = (aShared ? 0 : half*MPAD) + lmBase;
    const int bn = blockIdx.x * 128;
    const int K2 = K >> 1;
    const __nv_bfloat16* Bhi = half ? Bhi1 : Bhi0;
    const __nv_bfloat16* Blo = half ? Blo1 : Blo0;
    const float* bias = half ? bias1 : bias0;
    const int epi = half ? epi1 : epi0;

    const uint32_t* gAh = (const uint32_t*)Ahi;
    const uint32_t* gAl = (const uint32_t*)Alo;
    const uint32_t* gBh = (const uint32_t*)Bhi;
    const uint32_t* gBl = (const uint32_t*)Blo;
    const uint32_t sbase_u = s2u(smem);

    float acc[4][4][4];
#pragma unroll
    for (int a=0;a<4;a++)
#pragma unroll
        for (int b=0;b<4;b++)
#pragma unroll
            for (int c=0;c<4;c++) acc[a][b][c]=0.f;

    const int KT = K >> 5;

    auto fill = [&](int buf, int kt){
        uint32_t sd = sbase_u + (uint32_t)buf*STAGE_U32*4;
        int kc0 = kt*16;
#pragma unroll
        for (int i=0;i<2;i++){
            int t = tid + i*256;
            int row = t >> 2, ch = (t & 3) * 4;
            size_t ga = (size_t)(aBase+row)*K2 + kc0 + ch;
            size_t gb = (size_t)(bn + row)*K2 + kc0 + ch;
            uint32_t so = (uint32_t)(row*APITCH + ch)*4;
            cpa16(sd + so,                   gAh + ga);
            cpa16(sd + PLANE_U32*4   + so,   gAl + ga);
            cpa16(sd + 2*PLANE_U32*4 + so,   gBh + gb);
            cpa16(sd + 3*PLANE_U32*4 + so,   gBl + gb);
        }
        asm volatile("cp.async.commit_group;\n");
    };

    fill(0, 0);
    for (int kt=0; kt<KT; kt++){
        int buf = kt & 1;
        if (kt+1 < KT) fill(buf^1, kt+1);
        else asm volatile("cp.async.commit_group;\n");
        asm volatile("cp.async.wait_group 1;\n" ::: "memory");
        __syncthreads();

        const uint32_t* sAh = smem + buf*STAGE_U32;
        const uint32_t* sAl = sAh + PLANE_U32;
        const uint32_t* sBh = sAh + 2*PLANE_U32;
        const uint32_t* sBl = sAh + 3*PLANE_U32;

#pragma unroll
        for (int ks=0; ks<2; ks++){
            const int kc = ks*8 + tig;
            uint32_t bh[4][2], bl[4][2];
#pragma unroll
            for (int nt=0;nt<4;nt++){
                int n = wn*32 + nt*8 + g;
                bh[nt][0]=sBh[n*APITCH+kc]; bh[nt][1]=sBh[n*APITCH+kc+4];
                bl[nt][0]=sBl[n*APITCH+kc]; bl[nt][1]=sBl[n*APITCH+kc+4];
            }
#pragma unroll
            for (int mt=0;mt<4;mt++){
                int m = wm*64 + mt*16 + g;
                uint32_t ah0=sAh[m*APITCH+kc],     ah1=sAh[(m+8)*APITCH+kc];
                uint32_t ah2=sAh[m*APITCH+kc+4],   ah3=sAh[(m+8)*APITCH+kc+4];
                uint32_t al0=sAl[m*APITCH+kc],     al1=sAl[(m+8)*APITCH+kc];
                uint32_t al2=sAl[m*APITCH+kc+4],   al3=sAl[(m+8)*APITCH+kc+4];
#pragma unroll
                for (int nt=0;nt<4;nt++){
                    mma16816(acc[mt][nt], ah0,ah1,ah2,ah3, bh[nt][0],bh[nt][1]);
                    mma16816(acc[mt][nt], ah0,ah1,ah2,ah3, bl[nt][0],bl[nt][1]);
                    mma16816(acc[mt][nt], al0,al1,al2,al3, bh[nt][0],bh[nt][1]);
                }
            }
        }
        __syncthreads();
    }

    /* epilogue */
#pragma unroll
    for (int mt=0;mt<4;mt++){
        int lm0 = lmBase + wm*64 + mt*16 + g;
#pragma unroll
        for (int hf=0; hf<2; hf++){
            int lm = lm0 + hf*8;
            if (lm >= MROWS) continue;
            size_t crow = (size_t)(half*MROWS + lm)*N;
            size_t prow = (size_t)(half*MPAD  + lm)*N;
#pragma unroll
            for (int nt=0;nt<4;nt++){
                int gn = bn + wn*32 + nt*8 + tig*2;
                float z0 = acc[mt][nt][hf*2+0];
                float z1 = acc[mt][nt][hf*2+1];
                if (bias){ z0 += bias[gn]; z1 += bias[gn+1]; }
                if (epi == EPI_BIAS){
                    *(float2*)(C + crow + gn) = make_float2(z0, z1);
                } else if (epi == EPI_ELU1){
                    float o0 = (z0>0.f)? z0+1.f : expf(z0);
                    float o1 = (z1>0.f)? z1+1.f : expf(z1);
                    *(float2*)(C + crow + gn) = make_float2(o0,o1);
                } else if (epi == EPI_GELU){
                    float o0 = 0.5f*z0*(1.f+erff(z0*0.70710678118f));
                    float o1 = 0.5f*z1*(1.f+erff(z1*0.70710678118f));
                    __nv_bfloat16 h0,l0,h1,l1;
                    split_bf16(o0,h0,l0); split_bf16(o1,h1,l1);
                    __nv_bfloat162 hv; hv.x=h0; hv.y=h1;
                    __nv_bfloat162 lv; lv.x=l0; lv.y=l1;
                    *(__nv_bfloat162*)(Chi + prow + gn) = hv;
                    *(__nv_bfloat162*)(Clo + prow + gn) = lv;
                } else {
                    float2 old = *(const float2*)(C + crow + gn);
                    float o0 = old.x + gamma[gn]*z0;
                    float o1 = old.y + gamma[gn+1]*z1;
                    *(float2*)(C + crow + gn) = make_float2(o0,o1);
                }
            }
        }
    }
}

/* ---------------- weight split (vectorized) ---------------- */
__global__ void wsplit4(const float4* __restrict__ src, __nv_bfloat16* __restrict__ hi,
                        __nv_bfloat16* __restrict__ lo, size_t n4)
{
    size_t i = (size_t)blockIdx.x*256 + threadIdx.x;
    if (i >= n4) return;
    float4 f = src[i];
    __nv_bfloat16 h0,l0,h1,l1,h2,l2,h3,l3;
    split_bf16(f.x,h0,l0); split_bf16(f.y,h1,l1);
    split_bf16(f.z,h2,l2); split_bf16(f.w,h3,l3);
    __nv_bfloat162 a,b,c,d;
    a.x=h0;a.y=h1; b.x=h2;b.y=h3; c.x=l0;c.y=l1; d.x=l2;d.y=l3;
    *(__nv_bfloat162*)(hi + 4*i)   = a;
    *(__nv_bfloat162*)(hi + 4*i+2) = b;
    *(__nv_bfloat162*)(lo + 4*i)   = c;
    *(__nv_bfloat162*)(lo + 4*i+2) = d;
}

/* ---------------- merged LayerNorm -> bf16 hi/lo planes ----------------
   grid = 2*MROWS: rows [0,MROWS) mean -> plane rows [0,..); cov -> MPAD+.. */
__global__ void __launch_bounds__(256) ln_split(const float* __restrict__ x,
        const float* __restrict__ g, const float* __restrict__ b,
        __nv_bfloat16* __restrict__ yh, __nv_bfloat16* __restrict__ yl)
{
    int row = blockIdx.x;
    int drow = (row < MROWS) ? row : row + (MPAD - MROWS);
    const float* xr = x + (size_t)row*EMB;
    int tid = threadIdx.x;
    float v0=xr[tid], v1=xr[tid+256], v2=xr[tid+512];
    float s  = v0+v1+v2;
    float s2 = v0*v0+v1*v1+v2*v2;
    __shared__ float red[2][8];
    int lane=tid&31, wid=tid>>5;
#pragma unroll
    for(int o=16;o;o>>=1){ s+=__shfl_xor_sync(0xffffffffu,s,o); s2+=__shfl_xor_sync(0xffffffffu,s2,o); }
    if(!lane){ red[0][wid]=s; red[1][wid]=s2; }
    __syncthreads();
    s=0.f; s2=0.f;
#pragma unroll
    for (int i=0;i<8;i++){ s+=red[0][i]; s2+=red[1][i]; }
    float mu = s * (1.f/768.f);
    float var = s2*(1.f/768.f) - mu*mu;
    float inv = rsqrtf(var + 1e-5f);
    size_t o0 = (size_t)drow*EMB;
#pragma unroll
    for (int r=0;r<3;r++){
        int e = tid + r*256;
        float v = (r==0)?v0:((r==1)?v1:v2);
        float y = (v-mu)*inv*g[e] + b[e];
        __nv_bfloat16 h,l; split_bf16(y,h,l);
        yh[o0+e]=h; yl[o0+e]=l;
    }
}

/* fp32 LayerNorm for the final pooled vector */
__global__ void __launch_bounds__(256) ln_f32(const float* __restrict__ x,
        const float* __restrict__ g, const float* __restrict__ b,
        float* __restrict__ y)
{
    int row = blockIdx.x;
    const float* xr = x + (size_t)row*EMB;
    float* yr = y + (size_t)row*EMB;
    int tid = threadIdx.x;
    float v0=xr[tid], v1=xr[tid+256], v2=xr[tid+512];
    float s  = v0+v1+v2;
    float s2 = v0*v0+v1*v1+v2*v2;
    __shared__ float red[2][8];
    int lane=tid&31, wid=tid>>5;
#pragma unroll
    for(int o=16;o;o>>=1){ s+=__shfl_xor_sync(0xffffffffu,s,o); s2+=__shfl_xor_sync(0xffffffffu,s2,o); }
    if(!lane){ red[0][wid]=s; red[1][wid]=s2; }
    __syncthreads();
    s=0.f; s2=0.f;
#pragma unroll
    for (int i=0;i<8;i++){ s+=red[0][i]; s2+=red[1][i]; }
    float mu = s * (1.f/768.f);
    float var = s2*(1.f/768.f) - mu*mu;
    float inv = rsqrtf(var + 1e-5f);
    yr[tid]     = (v0-mu)*inv*g[tid]     + b[tid];
    yr[tid+256] = (v1-mu)*inv*g[tid+256] + b[tid+256];
    yr[tid+512] = (v2-mu)*inv*g[tid+512] + b[tid+512];
}

/* ---------------- im2col -> bf16 planes ---------------- */
__global__ void im2col_split(const float* __restrict__ x,
                             __nv_bfloat16* __restrict__ ph, __nv_bfloat16* __restrict__ pl)
{
    int idx = blockIdx.x*blockDim.x + threadIdx.x;
    if (idx >= MROWS*EMB) return;
    int r = idx / EMB, col = idx % EMB;
    int b = r / NTOK, t = r % NTOK;
    float v = 0.f;
    if (t > 0){
        int pp = t-1;
        int py = pp/14, px = pp%14;
        int c = col >> 8, phh = (col>>4)&15, pw = col&15;
        v = x[(((size_t)b*3 + c)*224 + py*16+phh)*224 + px*16+pw];
    }
    __nv_bfloat16 h,l; split_bf16(v,h,l);
    ph[idx]=h; pl[idx]=l;
}

__global__ void fill_cls(const float* __restrict__ cls, const float* __restrict__ ccls,
                         float* __restrict__ xx)
{
    int b = blockIdx.x, tid=threadIdx.x;
#pragma unroll
    for (int r=0;r<3;r++){
        int e = tid+r*256;
        xx[(size_t)b*NTOK*EMB+e]              = cls[e];
        xx[((size_t)MROWS + b*NTOK)*EMB+e]    = ccls[e];
    }
}

__global__ void build_qkvb(const float* __restrict__ qb, const float* __restrict__ vb,
                           const float* __restrict__ cqb, const float* __restrict__ cvb,
                           float* __restrict__ outv, float* __restrict__ coutv)
{
    int idx = blockIdx.x*blockDim.x+threadIdx.x;
    if (idx >= NLAYER*E3) return;
    int l = idx / E3, j = idx % E3;
    float v=0.f, cv=0.f;
    if (j < EMB)        { v=qb[l*EMB+j];        cv=cqb[l*EMB+j]; }
    else if (j >= 2*EMB){ v=vb[l*EMB+j-2*EMB];  cv=cvb[l*EMB+j-2*EMB]; }
    outv[idx]=v; coutv[idx]=cv;
}

/* -------- attention preprocess -------- */
__global__ void __launch_bounds__(64) attn_pre(const float* __restrict__ qkv,
   float* __restrict__ qb, float* __restrict__ kb, float* __restrict__ cqs, float* __restrict__ cks,
   float* __restrict__ qs2, float* __restrict__ ks2, float* __restrict__ cqsum, float* __restrict__ cksum)
{
    int idx = blockIdx.x;
    int t  = idx % NTOK;
    int bh = idx / NTOK;
    int h  = bh % NHEAD;
    int b  = bh / NHEAD;
    int d  = threadIdx.x;
    size_t mb = ((size_t)(b*NTOK+t))*E3 + h*HD + d;
    size_t cb = ((size_t)(MROWS + b*NTOK+t))*E3 + h*HD + d;
    float q  = qkv[mb]*QSCALE;
    float k  = qkv[mb+EMB];
    float cq = qkv[cb];
    float ck = qkv[cb+EMB];
    float sq = sqrtf(fmaxf(cq,1e-24f));
    float sk = sqrtf(fmaxf(ck,1e-24f));
    size_t o = (size_t)idx*HD + d;
    qb[o]=q; kb[o]=k; cqs[o]=sq; cks[o]=sk;
    float r0=q*q, r1=k*k, r2=cq, r3=ck;
#pragma unroll
    for(int off=16;off;off>>=1){
        r0+=__shfl_xor_sync(0xffffffffu,r0,off);
        r1+=__shfl_xor_sync(0xffffffffu,r1,off);
        r2+=__shfl_xor_sync(0xffffffffu,r2,off);
        r3+=__shfl_xor_sync(0xffffffffu,r3,off);
    }
    __shared__ float sh[4][2];
    int lane=d&31, w=d>>5;
    if(!lane){ sh[0][w]=r0; sh[1][w]=r1; sh[2][w]=r2; sh[3][w]=r3; }
    __syncthreads();
    if (d==0){
        qs2[idx]  =sh[0][0]+sh[0][1];
        ks2[idx]  =sh[1][0]+sh[1][1];
        cqsum[idx]=sh[2][0]+sh[2][1];
        cksum[idx]=sh[3][0]+sh[3][1];
    }
}

/* -------- Wasserstein scores + sigmoid + bias + softmax --------
   16 q-rows x 64 k-cols per inner tile, 4 scores per thread. */
#define SNT 16
#define SMT 64
#define OFF_QSH  0
#define OFF_CQSH (SNT*64)
#define OFF_KT   (2*SNT*64)
#define OFF_CKT  (2*SNT*64 + SMT*65)
#define OFF_SSC  (2*SNT*64 + 2*SMT*65)
#define OFF_RQ2  (OFF_SSC + SNT*208)
#define OFF_RCQ  (OFF_RQ2 + SNT)
#define SCORE_SMEM ((OFF_RCQ + SNT)*4)

__global__ void __launch_bounds__(256) attn_score(
    const float* __restrict__ qbuf, const float* __restrict__ cqs,
    const float* __restrict__ kbuf, const float* __restrict__ cks,
    const float* __restrict__ qs2,  const float* __restrict__ cqsum,
    const float* __restrict__ ks2,  const float* __restrict__ cksum,
    const float* __restrict__ relb, float* __restrict__ attn)
{
    extern __shared__ float sm[];
    float* qsh  = sm + OFF_QSH;    /* [SNT][64] */
    float* cqsh = sm + OFF_CQSH;
    float* kt   = sm + OFF_KT;     /* [SMT][65] */
    float* ckt  = sm + OFF_CKT;
    float* ssc  = sm + OFF_SSC;    /* [SNT][208] */
    float* rowq2= sm + OFF_RQ2;
    float* rowcq= sm + OFF_RCQ;

    int bh = blockIdx.y;
    int h  = bh % NHEAD;
    int n0 = blockIdx.x * SNT;
    int tid = threadIdx.x;

    for (int i = tid; i < SNT*64; i += 256) {
        int nl = i>>6, d = i&63;
        int n = n0+nl;
        float qv=0.f, cv=0.f;
        if (n < NTOK) { size_t o=((size_t)bh*NTOK+n)*64+d; qv=qbuf[o]; cv=cqs[o]; }
        qsh[nl*64+d]=qv; cqsh[nl*64+d]=cv;
    }
    if (tid < SNT) {
        int n = n0+tid;
        rowq2[tid] = (n<NTOK)? qs2[bh*NTOK+n]:0.f;
        rowcq[tid] = (n<NTOK)? cqsum[bh*NTOK+n]:0.f;
    }
    __syncthreads();

    const int nl  = tid >> 4;
    const int mlb = (tid & 15) * 4;
    const int n   = n0 + nl;

    for (int m0=0; m0<NTOK; m0+=SMT) {
        for (int i = tid; i < SMT*64; i += 256) {
            int ml=i>>6, d=i&63; int m=m0+ml;
            float kv=0.f,cv=0.f;
            if (m<NTOK){ size_t o=((size_t)bh*NTOK+m)*64+d; kv=kbuf[o]; cv=cks[o]; }
            kt[ml*65+d]=kv; ckt[ml*65+d]=cv;
        }
        __syncthreads();

        float dm[4]={0,0,0,0}, dc[4]={0,0,0,0};
#pragma unroll
        for (int d=0; d<64; d++){
            float qv = qsh[nl*64+d];
            float cqv= cqsh[nl*64+d];
#pragma unroll
            for (int j=0;j<4;j++){
                dm[j] = fmaf(qv,  kt[(mlb+j)*65+d],  dm[j]);
                dc[j] = fmaf(cqv, ckt[(mlb+j)*65+d], dc[j]);
            }
        }
        if (n < NTOK){
#pragma unroll
            for (int j=0;j<4;j++){
                int m = m0 + mlb + j;
                if (m < NTOK){
                    float w = -2.f*dm[j] + rowq2[nl] + ks2[bh*NTOK+m]
                              -2.f*dc[j] + rowcq[nl] + cksum[bh*NTOK+m];
                    float s = 1.f/(1.f+expf(w - 1e-24f));
                    ssc[nl*208+m] = s + relb[((size_t)h*NTOK + n)*NTOK + m];
                }
            }
        }
        __syncthreads();
    }
    int wid = tid>>5, lane = tid&31;
    for (int r = wid; r < SNT; r += 8) {
        int nn = n0+r;
        if (nn >= NTOK) continue;
        float mx = -1e30f;
        for (int m=lane; m<NTOK; m+=32) mx = fmaxf(mx, ssc[r*208+m]);
#pragma unroll
        for (int o=16;o;o>>=1) mx = fmaxf(mx, __shfl_xor_sync(0xffffffffu,mx,o));
        float sum=0.f;
        for (int m=lane;m<NTOK;m+=32){ float e=expf(ssc[r*208+m]-mx); ssc[r*208+m]=e; sum+=e; }
#pragma unroll
        for (int o=16;o;o>>=1) sum += __shfl_xor_sync(0xffffffffu,sum,o);
        float inv = 1.f/sum;
        for (int m=lane;m<NTOK;m+=32)
            attn[(((size_t)bh)*NTOK+nn)*NTOK+m] = ssc[r*208+m]*inv;
    }
}

/* -------- AV: mean_ctx / cov_ctx, tiled, writes combined bf16 planes -------- */
__global__ void __launch_bounds__(256) attn_av2(const float* __restrict__ attn,
    const float* __restrict__ qkv,
    __nv_bfloat16* __restrict__ chi_, __nv_bfloat16* __restrict__ clo_)
{
    int h  = blockIdx.x;
    int n0 = blockIdx.y * 32;
    int b  = blockIdx.z;
    int e0 = h * 64;
    __shared__ float sat[32][200];
    __shared__ float sv[32][64], scv[32][64];
    int tid = threadIdx.x;
    int wid = tid>>5, lane = tid&31;

    for (int r = wid; r < 32; r += 8){
        int n = n0 + r;
        if (n < NTOK){
            const float* src = attn + (((size_t)(b*NHEAD+h))*NTOK + n)*NTOK;
            for (int m=lane; m<NTOK; m+=32) sat[r][m] = src[m];
        } else {
            for (int m=lane; m<NTOK; m+=32) sat[r][m] = 0.f;
        }
    }

    float acc[2][4]={{0}}, cac[2][4]={{0}};
    int ew = (tid & 15) * 4;
    int nb = (tid >> 4) * 2;

    for (int m0=0; m0<NTOK; m0+=32){
        __syncthreads();
        for (int i = tid; i < 32*16; i += 256){
            int mr = i >> 4, c4 = (i & 15)*4;
            int m = m0 + mr;
            float4 v = make_float4(0,0,0,0), cv = make_float4(0,0,0,0);
            if (m < NTOK){
                size_t vb = ((size_t)(b*NTOK+m))*E3 + 2*EMB + e0 + c4;
                size_t cb = ((size_t)(MROWS + b*NTOK+m))*E3 + 2*EMB + e0 + c4;
                v  = *(const float4*)(qkv + vb);
                cv = *(const float4*)(qkv + cb);
            }
            *(float4*)&sv[mr][c4]  = v;
            *(float4*)&scv[mr][c4] = cv;
        }
        __syncthreads();
        int mlim = min(32, NTOK-m0);
        for (int mm=0; mm<mlim; mm++){
            float4 v  = *(const float4*)&sv[mm][ew];
            float4 cv = *(const float4*)&scv[mm][ew];
#pragma unroll
            for (int i=0;i<2;i++){
                float a = sat[nb+i][m0+mm];
                float a2 = a*a;
                acc[i][0]=fmaf(a,v.x,acc[i][0]); acc[i][1]=fmaf(a,v.y,acc[i][1]);
                acc[i][2]=fmaf(a,v.z,acc[i][2]); acc[i][3]=fmaf(a,v.w,acc[i][3]);
                cac[i][0]=fmaf(a2,cv.x,cac[i][0]); cac[i][1]=fmaf(a2,cv.y,cac[i][1]);
                cac[i][2]=fmaf(a2,cv.z,cac[i][2]); cac[i][3]=fmaf(a2,cv.w,cac[i][3]);
            }
        }
    }
#pragma unroll
    for (int i=0;i<2;i++){
        int n = n0 + nb + i;
        if (n >= NTOK) continue;
        size_t mbase = ((size_t)(b*NTOK+n))*EMB + e0 + ew;
        size_t cbase = ((size_t)(MPAD + b*NTOK+n))*EMB + e0 + ew;
#pragma unroll
        for (int j=0;j<4;j++){
            __nv_bfloat16 hh,ll;
            split_bf16(acc[i][j],hh,ll); chi_[mbase+j]=hh; clo_[mbase+j]=ll;
            split_bf16(cac[i][j],hh,ll); chi_[cbase+j]=hh; clo_[cbase+j]=ll;
        }
    }
}

/* ------------------------------ tail ---------------------------------- */
__global__ void __launch_bounds__(256) pool_kernel(const float* __restrict__ xx, float* __restrict__ pool)
{
    int b = blockIdx.x;
    int tid=threadIdx.x;
#pragma unroll
    for (int r=0;r<3;r++){
        int e = tid + r*256;
        float s=0.f;
        for (int n=1;n<NTOK;n++) s += xx[((size_t)(b*NTOK+n))*EMB+e];
        pool[b*EMB+e]=s*(1.f/196.f);
    }
}

__global__ void head_kernel(const float* __restrict__ t, const float* __restrict__ w,
                            const float* __restrict__ hb, float* __restrict__ out)
{
    int idx = blockIdx.x*blockDim.x + threadIdx.x;
    if (idx >= BATCH*NCLS) return;
    int b = idx/NCLS, c = idx%NCLS;
    const float* tr = t + b*EMB;
    const float* wr = w + (size_t)c*EMB;
    float s = hb[c];
    for (int e=0;e<EMB;e+=4){
        float4 tv=*(const float4*)(tr+e);
        float4 wv=*(const float4*)(wr+e);
        s += tv.x*wv.x+tv.y*wv.y+tv.z*wv.z+tv.w*wv.w;
    }
    out[idx]=s;
}

/* ------------------------------ host ---------------------------------- */
extern "C" void kernel_launch(void* const* d_in, const int* in_sizes, int n_in,
                              void* d_out, int out_size)
{
    const float* x        = (const float*)d_in[0];
    const float* relb     = (const float*)d_in[1];
    const float* patch_w  = (const float*)d_in[2];
    const float* patch_b  = (const float*)d_in[3];
    const float* cpatch_w = (const float*)d_in[4];
    const float* cpatch_b = (const float*)d_in[5];
    const float* cls      = (const float*)d_in[6];
    const float* ccls     = (const float*)d_in[7];
    const float* n1g      = (const float*)d_in[8];
    const float* n1b      = (const float*)d_in[9];
    const float* qkvw     = (const float*)d_in[10];
    const float* qb       = (const float*)d_in[11];
    const float* vb       = (const float*)d_in[12];
    const float* cqb      = (const float*)d_in[13];
    const float* cvb      = (const float*)d_in[14];
    const float* projw    = (const float*)d_in[15];
    const float* projb    = (const float*)d_in[16];
    const float* cprojw   = (const float*)d_in[17];
    const float* cprojb   = (const float*)d_in[18];
    const float* gamma1   = (const float*)d_in[19];
    const float* gamma2   = (const float*)d_in[20];
    const float* n2g      = (const float*)d_in[21];
    const float* n2b      = (const float*)d_in[22];
    const float* fc1w     = (const float*)d_in[23];
    const float* fc1b     = (const float*)d_in[24];
    const float* fc2w     = (const float*)d_in[25];
    const float* fc2b     = (const float*)d_in[26];
    const float* fng      = (const float*)d_in[27];
    const float* fnb      = (const float*)d_in[28];
    const float* headw    = (const float*)d_in[29];
    const float* headb    = (const float*)d_in[30];
    float* out = (float*)d_out;

    static int attr_set = 0;
    if (!attr_set){
        cudaFuncSetAttribute(gemm_bf16, cudaFuncAttributeMaxDynamicSharedMemorySize, GEMM_SMEM);
        cudaFuncSetAttribute(attn_score, cudaFuncAttributeMaxDynamicSharedMemorySize, SCORE_SMEM);
        attr_set = 1;
    }

    __nv_bfloat16 *whi,*wlo,*pat_hi,*pat_lo,*tn_hi,*tn_lo,*ctx_hi,*ctx_lo,*h_hi,*h_lo;
    float *p_x,*p_qkv,*p_qbuf,*p_kbuf,*p_cqs,*p_cks,
          *p_qs2,*p_ks2,*p_cqsum,*p_cksum,*p_attn,*p_qkvb,*p_cqkvb,*p_pool,*p_pooln;
    cudaGetSymbolAddress((void**)&whi, g_whi);
    cudaGetSymbolAddress((void**)&wlo, g_wlo);
    cudaGetSymbolAddress((void**)&pat_hi, g_pat_hi);
    cudaGetSymbolAddress((void**)&pat_lo, g_pat_lo);
    cudaGetSymbolAddress((void**)&tn_hi, g_tn_hi);
    cudaGetSymbolAddress((void**)&tn_lo, g_tn_lo);
    cudaGetSymbolAddress((void**)&ctx_hi, g_ctx_hi);
    cudaGetSymbolAddress((void**)&ctx_lo, g_ctx_lo);
    cudaGetSymbolAddress((void**)&h_hi, g_h_hi);
    cudaGetSymbolAddress((void**)&h_lo, g_h_lo);
    cudaGetSymbolAddress((void**)&p_x,    g_x);
    cudaGetSymbolAddress((void**)&p_qkv,  g_qkv);
    cudaGetSymbolAddress((void**)&p_qbuf, g_qbuf);
    cudaGetSymbolAddress((void**)&p_kbuf, g_kbuf);
    cudaGetSymbolAddress((void**)&p_cqs,  g_cqs);
    cudaGetSymbolAddress((void**)&p_cks,  g_cks);
    cudaGetSymbolAddress((void**)&p_qs2,  g_qs2);
    cudaGetSymbolAddress((void**)&p_ks2,  g_ks2);
    cudaGetSymbolAddress((void**)&p_cqsum,g_cqsum);
    cudaGetSymbolAddress((void**)&p_cksum,g_cksum);
    cudaGetSymbolAddress((void**)&p_attn, g_attn);
    cudaGetSymbolAddress((void**)&p_qkvb, g_qkvb);
    cudaGetSymbolAddress((void**)&p_cqkvb,g_cqkvb);
    cudaGetSymbolAddress((void**)&p_pool, g_pool);
    cudaGetSymbolAddress((void**)&p_pooln,g_pooln);

    auto wsp = [&](const float* src, size_t off, size_t cnt){
        size_t n4 = cnt/4;
        wsplit4<<<(unsigned)((n4+255)/256),256>>>((const float4*)src, whi+off, wlo+off, n4);
    };
    wsp(patch_w,  OFF_PW,    589824);
    wsp(cpatch_w, OFF_CPW,   589824);
    wsp(qkvw,     OFF_QKV,   21233664);
    wsp(projw,    OFF_PROJ,  7077888);
    wsp(cprojw,   OFF_CPROJ, 7077888);
    wsp(fc1w,     OFF_FC1,   28311552);
    wsp(fc2w,     OFF_FC2,   28311552);

    build_qkvb<<<(NLAYER*E3+255)/256,256>>>(qb,vb,cqb,cvb,p_qkvb,p_cqkvb);
    im2col_split<<<(MROWS*EMB+255)/256,256>>>(x, pat_hi, pat_lo);

    /* patch embed: z-batched over (patch_w, cov_patch_w), A shared */
    gemm_bf16<<<dim3(EMB/128,13,2),256,GEMM_SMEM>>>(
        pat_hi,pat_lo, whi+OFF_PW,wlo+OFF_PW, whi+OFF_CPW,wlo+OFF_CPW,
        patch_b, cpatch_b, nullptr, p_x, nullptr,nullptr, EMB, EMB, EPI_BIAS, EPI_BIAS, 1);
    fill_cls<<<BATCH,256>>>(cls, ccls, p_x);

    for (int i=0;i<NLAYER;i++){
        size_t qkv_o  = OFF_QKV   + (size_t)i*E3*EMB;
        size_t proj_o = OFF_PROJ  + (size_t)i*EMB*EMB;
        size_t cprj_o = OFF_CPROJ + (size_t)i*EMB*EMB;
        size_t fc1_o  = OFF_FC1   + (size_t)i*(size_t)MLPD*EMB;
        size_t fc2_o  = OFF_FC2   + (size_t)i*(size_t)EMB*MLPD;

        ln_split<<<2*MROWS,256>>>(p_x, n1g+i*EMB, n1b+i*EMB, tn_hi, tn_lo);
        gemm_bf16<<<dim3(E3/128,13,2),256,GEMM_SMEM>>>(
            tn_hi,tn_lo, whi+qkv_o,wlo+qkv_o, whi+qkv_o,wlo+qkv_o,
            p_qkvb+i*E3, p_cqkvb+i*E3, nullptr, p_qkv, nullptr,nullptr,
            E3, EMB, EPI_BIAS, EPI_ELU1, 0);

        attn_pre<<<BATCH*NHEAD*NTOK,64>>>(p_qkv,p_qbuf,p_kbuf,p_cqs,p_cks,
                                          p_qs2,p_ks2,p_cqsum,p_cksum);
        attn_score<<<dim3((NTOK+SNT-1)/SNT, BATCH*NHEAD),256,SCORE_SMEM>>>(
            p_qbuf,p_cqs,p_kbuf,p_cks,p_qs2,p_cqsum,p_ks2,p_cksum,relb,p_attn);
        attn_av2<<<dim3(NHEAD,(NTOK+31)/32,BATCH),256>>>(p_attn,p_qkv,ctx_hi,ctx_lo);

        gemm_bf16<<<dim3(EMB/128,13,2),256,GEMM_SMEM>>>(
            ctx_hi,ctx_lo, whi+proj_o,wlo+proj_o, whi+cprj_o,wlo+cprj_o,
            projb+i*EMB, cprojb+i*EMB, gamma1+i*EMB, p_x, nullptr,nullptr,
            EMB, EMB, EPI_RES, EPI_RES, 0);

        ln_split<<<2*MROWS,256>>>(p_x, n2g+i*EMB, n2b+i*EMB, tn_hi, tn_lo);
        gemm_bf16<<<dim3(MLPD/128,13,2),256,GEMM_SMEM>>>(
            tn_hi,tn_lo, whi+fc1_o,wlo+fc1_o, whi+fc1_o,wlo+fc1_o,
            fc1b+i*MLPD, fc1b+i*MLPD, nullptr, nullptr, h_hi,h_lo,
            MLPD, EMB, EPI_GELU, EPI_GELU, 0);
        gemm_bf16<<<dim3(EMB/128,13,2),256,GEMM_SMEM>>>(
            h_hi,h_lo, whi+fc2_o,wlo+fc2_o, whi+fc2_o,wlo+fc2_o,
            fc2b+i*EMB, fc2b+i*EMB, gamma2+i*EMB, p_x, nullptr,nullptr,
            EMB, MLPD, EPI_RES, EPI_RES, 0);
    }

    pool_kernel<<<BATCH,256>>>(p_x, p_pool);
    ln_f32<<<BATCH,256>>>(p_pool, fng, fnb, p_pooln);
    head_kernel<<<(BATCH*NCLS+255)/256,256>>>(p_pooln, headw, headb, out);
}

// round 6
// speedup vs baseline: 3.3202x; 1.2674x over previous
#include <cuda_runtime.h>
#include <cuda_fp16.h>
#include <stdint.h>
#include <math.h>

#define BATCH 8
#define EMB 768
#define NHEAD 12
#define NLAYER 12
#define HD 64
#define NTOK 197
#define MROWS (BATCH*NTOK)   /* 1576 */
#define MPAD 1664            /* 13*128 */
#define E3 2304
#define MLPD 3072
#define QSCALE 0.125f
#define NCLS 1000

enum { EPI_BIAS=0, EPI_ELU1=1, EPI_GELU=2, EPI_RES=3 };

/* ---------------- weight plane offsets (elements) ---------------- */
#define OFF_PW    0ULL
#define OFF_CPW   589824ULL
#define OFF_QKV   1179648ULL
#define OFF_PROJ  22413312ULL
#define OFF_CPROJ 29491200ULL
#define OFF_FC1   36569088ULL
#define OFF_FC2   64880640ULL
#define WTOT      93192192ULL

/* ------------------------------ scratch ------------------------------ */
__device__ __half g_w[WTOT];                       /* fp16 weights (single plane) */

__device__ __half g_pat_hi[MPAD*EMB],    g_pat_lo[MPAD*EMB];
__device__ __half g_tn_hi [2*MPAD*EMB],  g_tn_lo [2*MPAD*EMB];
__device__ __half g_ctx_hi[2*MPAD*EMB],  g_ctx_lo[2*MPAD*EMB];
__device__ __half g_h_hi  [2*(size_t)MPAD*MLPD], g_h_lo[2*(size_t)MPAD*MLPD];

__device__ float g_x[2*MROWS*EMB];        /* mean rows [0,MROWS), cov rows [MROWS,2MROWS) */
__device__ float g_qkv[2*(size_t)MROWS*E3];
__device__ float g_qbuf[BATCH*NHEAD*NTOK*HD];
__device__ float g_kbuf[BATCH*NHEAD*NTOK*HD];
__device__ float g_cqs[BATCH*NHEAD*NTOK*HD];
__device__ float g_cks[BATCH*NHEAD*NTOK*HD];
__device__ float g_qs2[BATCH*NHEAD*NTOK];
__device__ float g_ks2[BATCH*NHEAD*NTOK];
__device__ float g_cqsum[BATCH*NHEAD*NTOK];
__device__ float g_cksum[BATCH*NHEAD*NTOK];
__device__ float g_attn[(size_t)BATCH*NHEAD*NTOK*NTOK];
__device__ float g_qkvb[NLAYER*E3];
__device__ float g_cqkvb[NLAYER*E3];
__device__ float g_pool[BATCH*EMB];
__device__ float g_pooln[BATCH*EMB];

/* ------------------------------ helpers ------------------------------ */
__device__ __forceinline__ uint32_t s2u(const void* p){
    return (uint32_t)__cvta_generic_to_shared(p);
}
__device__ __forceinline__ void cpa16(uint32_t dst, const void* src){
    asm volatile("cp.async.cg.shared.global [%0], [%1], 16;\n" :: "r"(dst), "l"(src));
}
__device__ __forceinline__ void mma16816(float* c, uint32_t a0,uint32_t a1,uint32_t a2,uint32_t a3,
                                         uint32_t b0,uint32_t b1){
    asm volatile("mma.sync.aligned.m16n8k16.row.col.f32.f16.f16.f32 "
        "{%0,%1,%2,%3},{%4,%5,%6,%7},{%8,%9},{%0,%1,%2,%3};\n"
        : "+f"(c[0]),"+f"(c[1]),"+f"(c[2]),"+f"(c[3])
        : "r"(a0),"r"(a1),"r"(a2),"r"(a3),"r"(b0),"r"(b1));
}
__device__ __forceinline__ void split_h(float f, __half& h, __half& l){
    h = __float2half_rn(f);
    l = __float2half_rn(f - __half2float(h));
}

/* ---------------- fp16 2-product GEMM: C[M,N] = A[M,K]*B[N,K]^T ------
   A given as hi/lo fp16 planes (exact), B single fp16 plane per half.
   128x128x32 tiles, 8 warps (2x4), warp tile 64x32, mma.m16n8k16.
   grid = (N/128, 13, 2). z = half (0 mean path, 1 cov path).         */
#define APITCH 20
#define PLANE_U32 (128*APITCH)
#define STAGE_U32 (3*PLANE_U32)
#define GEMM_SMEM (2*STAGE_U32*4)

__global__ void __launch_bounds__(256)
gemm_h(const __half* __restrict__ Ahi, const __half* __restrict__ Alo,
       const __half* __restrict__ B0, const __half* __restrict__ B1,
       const float* __restrict__ bias0, const float* __restrict__ bias1,
       const float* __restrict__ gamma,
       float* __restrict__ C, __half* __restrict__ Chi, __half* __restrict__ Clo,
       int N, int K, int epi0, int epi1, int aShared)
{
    extern __shared__ uint32_t smem[];
    const int tid = threadIdx.x;
    const int lane = tid & 31, wid = tid >> 5;
    const int wm = wid >> 2, wn = wid & 3;
    const int g = lane >> 2, tig = lane & 3;
    const int half_ = blockIdx.z;
    const int lmBase = blockIdx.y * 128;
    const int aBase = (aShared ? 0 : half_*MPAD) + lmBase;
    const int bn = blockIdx.x * 128;
    const int K2 = K >> 1;
    const __half* B = half_ ? B1 : B0;
    const float* bias = half_ ? bias1 : bias0;
    const int epi = half_ ? epi1 : epi0;

    const uint32_t* gAh = (const uint32_t*)Ahi;
    const uint32_t* gAl = (const uint32_t*)Alo;
    const uint32_t* gB  = (const uint32_t*)B;
    const uint32_t sbase_u = s2u(smem);

    float acc[4][4][4];
#pragma unroll
    for (int a=0;a<4;a++)
#pragma unroll
        for (int b=0;b<4;b++)
#pragma unroll
            for (int c=0;c<4;c++) acc[a][b][c]=0.f;

    const int KT = K >> 5;

    auto fill = [&](int buf, int kt){
        uint32_t sd = sbase_u + (uint32_t)buf*STAGE_U32*4;
        int kc0 = kt*16;
#pragma unroll
        for (int i=0;i<2;i++){
            int t = tid + i*256;
            int row = t >> 2, ch = (t & 3) * 4;
            size_t ga = (size_t)(aBase+row)*K2 + kc0 + ch;
            size_t gb = (size_t)(bn + row)*K2 + kc0 + ch;
            uint32_t so = (uint32_t)(row*APITCH + ch)*4;
            cpa16(sd + so,                   gAh + ga);
            cpa16(sd + PLANE_U32*4   + so,   gAl + ga);
            cpa16(sd + 2*PLANE_U32*4 + so,   gB  + gb);
        }
        asm volatile("cp.async.commit_group;\n");
    };

    fill(0, 0);
    for (int kt=0; kt<KT; kt++){
        int buf = kt & 1;
        if (kt+1 < KT) fill(buf^1, kt+1);
        else asm volatile("cp.async.commit_group;\n");
        asm volatile("cp.async.wait_group 1;\n" ::: "memory");
        __syncthreads();

        const uint32_t* sAh = smem + buf*STAGE_U32;
        const uint32_t* sAl = sAh + PLANE_U32;
        const uint32_t* sB  = sAh + 2*PLANE_U32;

#pragma unroll
        for (int ks=0; ks<2; ks++){
            const int kc = ks*8 + tig;
            uint32_t bh[4][2];
#pragma unroll
            for (int nt=0;nt<4;nt++){
                int n = wn*32 + nt*8 + g;
                bh[nt][0]=sB[n*APITCH+kc]; bh[nt][1]=sB[n*APITCH+kc+4];
            }
#pragma unroll
            for (int mt=0;mt<4;mt++){
                int m = wm*64 + mt*16 + g;
                uint32_t ah0=sAh[m*APITCH+kc],     ah1=sAh[(m+8)*APITCH+kc];
                uint32_t ah2=sAh[m*APITCH+kc+4],   ah3=sAh[(m+8)*APITCH+kc+4];
                uint32_t al0=sAl[m*APITCH+kc],     al1=sAl[(m+8)*APITCH+kc];
                uint32_t al2=sAl[m*APITCH+kc+4],   al3=sAl[(m+8)*APITCH+kc+4];
#pragma unroll
                for (int nt=0;nt<4;nt++){
                    mma16816(acc[mt][nt], ah0,ah1,ah2,ah3, bh[nt][0],bh[nt][1]);
                    mma16816(acc[mt][nt], al0,al1,al2,al3, bh[nt][0],bh[nt][1]);
                }
            }
        }
        __syncthreads();
    }

    /* epilogue */
#pragma unroll
    for (int mt=0;mt<4;mt++){
        int lm0 = lmBase + wm*64 + mt*16 + g;
#pragma unroll
        for (int hf=0; hf<2; hf++){
            int lm = lm0 + hf*8;
            if (lm >= MROWS) continue;
            size_t crow = (size_t)(half_*MROWS + lm)*N;
            size_t prow = (size_t)(half_*MPAD  + lm)*N;
#pragma unroll
            for (int nt=0;nt<4;nt++){
                int gn = bn + wn*32 + nt*8 + tig*2;
                float z0 = acc[mt][nt][hf*2+0];
                float z1 = acc[mt][nt][hf*2+1];
                if (bias){ z0 += bias[gn]; z1 += bias[gn+1]; }
                if (epi == EPI_BIAS){
                    *(float2*)(C + crow + gn) = make_float2(z0, z1);
                } else if (epi == EPI_ELU1){
                    float o0 = (z0>0.f)? z0+1.f : expf(z0);
                    float o1 = (z1>0.f)? z1+1.f : expf(z1);
                    *(float2*)(C + crow + gn) = make_float2(o0,o1);
                } else if (epi == EPI_GELU){
                    float o0 = 0.5f*z0*(1.f+erff(z0*0.70710678118f));
                    float o1 = 0.5f*z1*(1.f+erff(z1*0.70710678118f));
                    __half h0,l0,h1,l1;
                    split_h(o0,h0,l0); split_h(o1,h1,l1);
                    __half2 hv; hv.x=h0; hv.y=h1;
                    __half2 lv; lv.x=l0; lv.y=l1;
                    *(__half2*)(Chi + prow + gn) = hv;
                    *(__half2*)(Clo + prow + gn) = lv;
                } else {
                    float2 old = *(const float2*)(C + crow + gn);
                    float o0 = old.x + gamma[gn]*z0;
                    float o1 = old.y + gamma[gn+1]*z1;
                    *(float2*)(C + crow + gn) = make_float2(o0,o1);
                }
            }
        }
    }
}

/* ---------------- weight -> fp16 (single plane) ---------------- */
__global__ void wsplit_h(const float4* __restrict__ src, __half* __restrict__ hi, size_t n4)
{
    size_t i = (size_t)blockIdx.x*256 + threadIdx.x;
    if (i >= n4) return;
    float4 f = src[i];
    __half2 a, b;
    a.x = __float2half_rn(f.x); a.y = __float2half_rn(f.y);
    b.x = __float2half_rn(f.z); b.y = __float2half_rn(f.w);
    *(__half2*)(hi + 4*i)   = a;
    *(__half2*)(hi + 4*i+2) = b;
}

/* ---------------- merged LayerNorm -> fp16 hi/lo planes ---------------- */
__global__ void __launch_bounds__(256) ln_split(const float* __restrict__ x,
        const float* __restrict__ g, const float* __restrict__ b,
        __half* __restrict__ yh, __half* __restrict__ yl)
{
    int row = blockIdx.x;
    int drow = (row < MROWS) ? row : row + (MPAD - MROWS);
    const float* xr = x + (size_t)row*EMB;
    int tid = threadIdx.x;
    float v0=xr[tid], v1=xr[tid+256], v2=xr[tid+512];
    float s  = v0+v1+v2;
    float s2 = v0*v0+v1*v1+v2*v2;
    __shared__ float red[2][8];
    int lane=tid&31, wid=tid>>5;
#pragma unroll
    for(int o=16;o;o>>=1){ s+=__shfl_xor_sync(0xffffffffu,s,o); s2+=__shfl_xor_sync(0xffffffffu,s2,o); }
    if(!lane){ red[0][wid]=s; red[1][wid]=s2; }
    __syncthreads();
    s=0.f; s2=0.f;
#pragma unroll
    for (int i=0;i<8;i++){ s+=red[0][i]; s2+=red[1][i]; }
    float mu = s * (1.f/768.f);
    float var = s2*(1.f/768.f) - mu*mu;
    float inv = rsqrtf(var + 1e-5f);
    size_t o0 = (size_t)drow*EMB;
#pragma unroll
    for (int r=0;r<3;r++){
        int e = tid + r*256;
        float v = (r==0)?v0:((r==1)?v1:v2);
        float y = (v-mu)*inv*g[e] + b[e];
        __half h,l; split_h(y,h,l);
        yh[o0+e]=h; yl[o0+e]=l;
    }
}

__global__ void __launch_bounds__(256) ln_f32(const float* __restrict__ x,
        const float* __restrict__ g, const float* __restrict__ b,
        float* __restrict__ y)
{
    int row = blockIdx.x;
    const float* xr = x + (size_t)row*EMB;
    float* yr = y + (size_t)row*EMB;
    int tid = threadIdx.x;
    float v0=xr[tid], v1=xr[tid+256], v2=xr[tid+512];
    float s  = v0+v1+v2;
    float s2 = v0*v0+v1*v1+v2*v2;
    __shared__ float red[2][8];
    int lane=tid&31, wid=tid>>5;
#pragma unroll
    for(int o=16;o;o>>=1){ s+=__shfl_xor_sync(0xffffffffu,s,o); s2+=__shfl_xor_sync(0xffffffffu,s2,o); }
    if(!lane){ red[0][wid]=s; red[1][wid]=s2; }
    __syncthreads();
    s=0.f; s2=0.f;
#pragma unroll
    for (int i=0;i<8;i++){ s+=red[0][i]; s2+=red[1][i]; }
    float mu = s * (1.f/768.f);
    float var = s2*(1.f/768.f) - mu*mu;
    float inv = rsqrtf(var + 1e-5f);
    yr[tid]     = (v0-mu)*inv*g[tid]     + b[tid];
    yr[tid+256] = (v1-mu)*inv*g[tid+256] + b[tid+256];
    yr[tid+512] = (v2-mu)*inv*g[tid+512] + b[tid+512];
}

/* ---------------- im2col -> fp16 planes ---------------- */
__global__ void im2col_split(const float* __restrict__ x,
                             __half* __restrict__ ph, __half* __restrict__ pl)
{
    int idx = blockIdx.x*blockDim.x + threadIdx.x;
    if (idx >= MROWS*EMB) return;
    int r = idx / EMB, col = idx % EMB;
    int b = r / NTOK, t = r % NTOK;
    float v = 0.f;
    if (t > 0){
        int pp = t-1;
        int py = pp/14, px = pp%14;
        int c = col >> 8, phh = (col>>4)&15, pw = col&15;
        v = x[(((size_t)b*3 + c)*224 + py*16+phh)*224 + px*16+pw];
    }
    __half h,l; split_h(v,h,l);
    ph[idx]=h; pl[idx]=l;
}

__global__ void fill_cls(const float* __restrict__ cls, const float* __restrict__ ccls,
                         float* __restrict__ xx)
{
    int b = blockIdx.x, tid=threadIdx.x;
#pragma unroll
    for (int r=0;r<3;r++){
        int e = tid+r*256;
        xx[(size_t)b*NTOK*EMB+e]              = cls[e];
        xx[((size_t)MROWS + b*NTOK)*EMB+e]    = ccls[e];
    }
}

__global__ void build_qkvb(const float* __restrict__ qb, const float* __restrict__ vb,
                           const float* __restrict__ cqb, const float* __restrict__ cvb,
                           float* __restrict__ outv, float* __restrict__ coutv)
{
    int idx = blockIdx.x*blockDim.x+threadIdx.x;
    if (idx >= NLAYER*E3) return;
    int l = idx / E3, j = idx % E3;
    float v=0.f, cv=0.f;
    if (j < EMB)        { v=qb[l*EMB+j];        cv=cqb[l*EMB+j]; }
    else if (j >= 2*EMB){ v=vb[l*EMB+j-2*EMB];  cv=cvb[l*EMB+j-2*EMB]; }
    outv[idx]=v; coutv[idx]=cv;
}

/* -------- attention preprocess: 4 tokens per 256-thread block -------- */
__global__ void __launch_bounds__(256) attn_pre(const float* __restrict__ qkv,
   float* __restrict__ qb, float* __restrict__ kb, float* __restrict__ cqs, float* __restrict__ cks,
   float* __restrict__ qs2, float* __restrict__ ks2, float* __restrict__ cqsum, float* __restrict__ cksum)
{
    int grp = threadIdx.x >> 6;
    int d   = threadIdx.x & 63;
    int idx = blockIdx.x*4 + grp;
    int t  = idx % NTOK;
    int bh = idx / NTOK;
    int h  = bh % NHEAD;
    int b  = bh / NHEAD;
    size_t mb = ((size_t)(b*NTOK+t))*E3 + h*HD + d;
    size_t cb = ((size_t)(MROWS + b*NTOK+t))*E3 + h*HD + d;
    float q  = qkv[mb]*QSCALE;
    float k  = qkv[mb+EMB];
    float cq = qkv[cb];
    float ck = qkv[cb+EMB];
    float sq = sqrtf(fmaxf(cq,1e-24f));
    float sk = sqrtf(fmaxf(ck,1e-24f));
    size_t o = (size_t)idx*HD + d;
    qb[o]=q; kb[o]=k; cqs[o]=sq; cks[o]=sk;
    float r0=q*q, r1=k*k, r2=cq, r3=ck;
#pragma unroll
    for(int off=16;off;off>>=1){
        r0+=__shfl_xor_sync(0xffffffffu,r0,off);
        r1+=__shfl_xor_sync(0xffffffffu,r1,off);
        r2+=__shfl_xor_sync(0xffffffffu,r2,off);
        r3+=__shfl_xor_sync(0xffffffffu,r3,off);
    }
    __shared__ float sh[4][4][2];
    int lane = threadIdx.x & 31;
    int wno = (threadIdx.x >> 5) & 1;
    if(!lane){ sh[grp][0][wno]=r0; sh[grp][1][wno]=r1; sh[grp][2][wno]=r2; sh[grp][3][wno]=r3; }
    __syncthreads();
    if (d==0){
        qs2[idx]  =sh[grp][0][0]+sh[grp][0][1];
        ks2[idx]  =sh[grp][1][0]+sh[grp][1][1];
        cqsum[idx]=sh[grp][2][0]+sh[grp][2][1];
        cksum[idx]=sh[grp][3][0]+sh[grp][3][1];
    }
}

/* -------- Wasserstein scores + sigmoid + bias + softmax --------
   16 q-rows x 64 k-cols per tile, thread handles m = mlb + 16j (interleaved),
   float4 smem reads, conflict-free.                                       */
#define SNT 16
#define SMT 64
#define KP  68
#define OFF_QSH  0
#define OFF_CQSH (SNT*KP)
#define OFF_KT   (2*SNT*KP)
#define OFF_CKT  (OFF_KT + SMT*KP)
#define OFF_SSC  (OFF_CKT + SMT*KP)
#define OFF_RQ2  (OFF_SSC + SNT*208)
#define OFF_RCQ  (OFF_RQ2 + SNT)
#define SCORE_SMEM ((OFF_RCQ + SNT)*4)

__global__ void __launch_bounds__(256) attn_score(
    const float* __restrict__ qbuf, const float* __restrict__ cqs,
    const float* __restrict__ kbuf, const float* __restrict__ cks,
    const float* __restrict__ qs2,  const float* __restrict__ cqsum,
    const float* __restrict__ ks2,  const float* __restrict__ cksum,
    const float* __restrict__ relb, float* __restrict__ attn)
{
    extern __shared__ float sm[];
    float* qsh  = sm + OFF_QSH;    /* [SNT][KP] */
    float* cqsh = sm + OFF_CQSH;
    float* kt   = sm + OFF_KT;     /* [SMT][KP] */
    float* ckt  = sm + OFF_CKT;
    float* ssc  = sm + OFF_SSC;    /* [SNT][208] */
    float* rowq2= sm + OFF_RQ2;
    float* rowcq= sm + OFF_RCQ;

    int bh = blockIdx.y;
    int h  = bh % NHEAD;
    int n0 = blockIdx.x * SNT;
    int tid = threadIdx.x;

    for (int i = tid; i < SNT*64; i += 256) {
        int nl = i>>6, d = i&63;
        int n = n0+nl;
        float qv=0.f, cv=0.f;
        if (n < NTOK) { size_t o=((size_t)bh*NTOK+n)*64+d; qv=qbuf[o]; cv=cqs[o]; }
        qsh[nl*KP+d]=qv; cqsh[nl*KP+d]=cv;
    }
    if (tid < SNT) {
        int n = n0+tid;
        rowq2[tid] = (n<NTOK)? qs2[bh*NTOK+n]:0.f;
        rowcq[tid] = (n<NTOK)? cqsum[bh*NTOK+n]:0.f;
    }
    __syncthreads();

    const int nl  = tid >> 4;
    const int mlb = tid & 15;
    const int n   = n0 + nl;

    for (int m0=0; m0<NTOK; m0+=SMT) {
        for (int i = tid; i < SMT*64; i += 256) {
            int ml=i>>6, d=i&63; int m=m0+ml;
            float kv=0.f,cv=0.f;
            if (m<NTOK){ size_t o=((size_t)bh*NTOK+m)*64+d; kv=kbuf[o]; cv=cks[o]; }
            kt[ml*KP+d]=kv; ckt[ml*KP+d]=cv;
        }
        __syncthreads();

        float dm[4]={0,0,0,0}, dc[4]={0,0,0,0};
#pragma unroll
        for (int d=0; d<64; d+=4){
            float4 q4 = *(const float4*)&qsh[nl*KP+d];
            float4 c4 = *(const float4*)&cqsh[nl*KP+d];
#pragma unroll
            for (int j=0;j<4;j++){
                float4 k4 = *(const float4*)&kt[(mlb+16*j)*KP+d];
                dm[j] = fmaf(q4.x,k4.x,fmaf(q4.y,k4.y,fmaf(q4.z,k4.z,fmaf(q4.w,k4.w,dm[j]))));
                float4 e4 = *(const float4*)&ckt[(mlb+16*j)*KP+d];
                dc[j] = fmaf(c4.x,e4.x,fmaf(c4.y,e4.y,fmaf(c4.z,e4.z,fmaf(c4.w,e4.w,dc[j]))));
            }
        }
        if (n < NTOK){
#pragma unroll
            for (int j=0;j<4;j++){
                int m = m0 + mlb + 16*j;
                if (m < NTOK){
                    float w = -2.f*dm[j] + rowq2[nl] + ks2[bh*NTOK+m]
                              -2.f*dc[j] + rowcq[nl] + cksum[bh*NTOK+m];
                    float s = 1.f/(1.f+expf(w - 1e-24f));
                    ssc[nl*208+m] = s + relb[((size_t)h*NTOK + n)*NTOK + m];
                }
            }
        }
        __syncthreads();
    }
    int wid = tid>>5, lane = tid&31;
    for (int r = wid; r < SNT; r += 8) {
        int nn = n0+r;
        if (nn >= NTOK) continue;
        float mx = -1e30f;
        for (int m=lane; m<NTOK; m+=32) mx = fmaxf(mx, ssc[r*208+m]);
#pragma unroll
        for (int o=16;o;o>>=1) mx = fmaxf(mx, __shfl_xor_sync(0xffffffffu,mx,o));
        float sum=0.f;
        for (int m=lane;m<NTOK;m+=32){ float e=expf(ssc[r*208+m]-mx); ssc[r*208+m]=e; sum+=e; }
#pragma unroll
        for (int o=16;o;o>>=1) sum += __shfl_xor_sync(0xffffffffu,sum,o);
        float inv = 1.f/sum;
        for (int m=lane;m<NTOK;m+=32)
            attn[(((size_t)bh)*NTOK+nn)*NTOK+m] = ssc[r*208+m]*inv;
    }
}

/* -------- AV: mean_ctx / cov_ctx, writes fp16 hi/lo planes -------- */
__global__ void __launch_bounds__(256) attn_av2(const float* __restrict__ attn,
    const float* __restrict__ qkv,
    __half* __restrict__ chi_, __half* __restrict__ clo_)
{
    int h  = blockIdx.x;
    int n0 = blockIdx.y * 32;
    int b  = blockIdx.z;
    int e0 = h * 64;
    __shared__ float sat[32][200];
    __shared__ float sv[32][64], scv[32][64];
    int tid = threadIdx.x;
    int wid = tid>>5, lane = tid&31;

    for (int r = wid; r < 32; r += 8){
        int n = n0 + r;
        if (n < NTOK){
            const float* src = attn + (((size_t)(b*NHEAD+h))*NTOK + n)*NTOK;
            for (int m=lane; m<NTOK; m+=32) sat[r][m] = src[m];
        } else {
            for (int m=lane; m<NTOK; m+=32) sat[r][m] = 0.f;
        }
    }

    float acc[2][4]={{0}}, cac[2][4]={{0}};
    int ew = (tid & 15) * 4;
    int nb = (tid >> 4) * 2;

    for (int m0=0; m0<NTOK; m0+=32){
        __syncthreads();
        for (int i = tid; i < 32*16; i += 256){
            int mr = i >> 4, c4 = (i & 15)*4;
            int m = m0 + mr;
            float4 v = make_float4(0,0,0,0), cv = make_float4(0,0,0,0);
            if (m < NTOK){
                size_t vb = ((size_t)(b*NTOK+m))*E3 + 2*EMB + e0 + c4;
                size_t cb = ((size_t)(MROWS + b*NTOK+m))*E3 + 2*EMB + e0 + c4;
                v  = *(const float4*)(qkv + vb);
                cv = *(const float4*)(qkv + cb);
            }
            *(float4*)&sv[mr][c4]  = v;
            *(float4*)&scv[mr][c4] = cv;
        }
        __syncthreads();
        int mlim = min(32, NTOK-m0);
        for (int mm=0; mm<mlim; mm++){
            float4 v  = *(const float4*)&sv[mm][ew];
            float4 cv = *(const float4*)&scv[mm][ew];
#pragma unroll
            for (int i=0;i<2;i++){
                float a = sat[nb+i][m0+mm];
                float a2 = a*a;
                acc[i][0]=fmaf(a,v.x,acc[i][0]); acc[i][1]=fmaf(a,v.y,acc[i][1]);
                acc[i][2]=fmaf(a,v.z,acc[i][2]); acc[i][3]=fmaf(a,v.w,acc[i][3]);
                cac[i][0]=fmaf(a2,cv.x,cac[i][0]); cac[i][1]=fmaf(a2,cv.y,cac[i][1]);
                cac[i][2]=fmaf(a2,cv.z,cac[i][2]); cac[i][3]=fmaf(a2,cv.w,cac[i][3]);
            }
        }
    }
#pragma unroll
    for (int i=0;i<2;i++){
        int n = n0 + nb + i;
        if (n >= NTOK) continue;
        size_t mbase = ((size_t)(b*NTOK+n))*EMB + e0 + ew;
        size_t cbase = ((size_t)(MPAD + b*NTOK+n))*EMB + e0 + ew;
#pragma unroll
        for (int j=0;j<4;j++){
            __half hh,ll;
            split_h(acc[i][j],hh,ll); chi_[mbase+j]=hh; clo_[mbase+j]=ll;
            split_h(cac[i][j],hh,ll); chi_[cbase+j]=hh; clo_[cbase+j]=ll;
        }
    }
}

/* ------------------------------ tail ---------------------------------- */
__global__ void __launch_bounds__(256) pool_kernel(const float* __restrict__ xx, float* __restrict__ pool)
{
    int b = blockIdx.x;
    int tid=threadIdx.x;
#pragma unroll
    for (int r=0;r<3;r++){
        int e = tid + r*256;
        float s=0.f;
        for (int n=1;n<NTOK;n++) s += xx[((size_t)(b*NTOK+n))*EMB+e];
        pool[b*EMB+e]=s*(1.f/196.f);
    }
}

__global__ void head_kernel(const float* __restrict__ t, const float* __restrict__ w,
                            const float* __restrict__ hb, float* __restrict__ out)
{
    int idx = blockIdx.x*blockDim.x + threadIdx.x;
    if (idx >= BATCH*NCLS) return;
    int b = idx/NCLS, c = idx%NCLS;
    const float* tr = t + b*EMB;
    const float* wr = w + (size_t)c*EMB;
    float s = hb[c];
    for (int e=0;e<EMB;e+=4){
        float4 tv=*(const float4*)(tr+e);
        float4 wv=*(const float4*)(wr+e);
        s += tv.x*wv.x+tv.y*wv.y+tv.z*wv.z+tv.w*wv.w;
    }
    out[idx]=s;
}

/* ------------------------------ host ---------------------------------- */
extern "C" void kernel_launch(void* const* d_in, const int* in_sizes, int n_in,
                              void* d_out, int out_size)
{
    const float* x        = (const float*)d_in[0];
    const float* relb     = (const float*)d_in[1];
    const float* patch_w  = (const float*)d_in[2];
    const float* patch_b  = (const float*)d_in[3];
    const float* cpatch_w = (const float*)d_in[4];
    const float* cpatch_b = (const float*)d_in[5];
    const float* cls      = (const float*)d_in[6];
    const float* ccls     = (const float*)d_in[7];
    const float* n1g      = (const float*)d_in[8];
    const float* n1b      = (const float*)d_in[9];
    const float* qkvw     = (const float*)d_in[10];
    const float* qb       = (const float*)d_in[11];
    const float* vb       = (const float*)d_in[12];
    const float* cqb      = (const float*)d_in[13];
    const float* cvb      = (const float*)d_in[14];
    const float* projw    = (const float*)d_in[15];
    const float* projb    = (const float*)d_in[16];
    const float* cprojw   = (const float*)d_in[17];
    const float* cprojb   = (const float*)d_in[18];
    const float* gamma1   = (const float*)d_in[19];
    const float* gamma2   = (const float*)d_in[20];
    const float* n2g      = (const float*)d_in[21];
    const float* n2b      = (const float*)d_in[22];
    const float* fc1w     = (const float*)d_in[23];
    const float* fc1b     = (const float*)d_in[24];
    const float* fc2w     = (const float*)d_in[25];
    const float* fc2b     = (const float*)d_in[26];
    const float* fng      = (const float*)d_in[27];
    const float* fnb      = (const float*)d_in[28];
    const float* headw    = (const float*)d_in[29];
    const float* headb    = (const float*)d_in[30];
    float* out = (float*)d_out;

    static int attr_set = 0;
    if (!attr_set){
        cudaFuncSetAttribute(gemm_h, cudaFuncAttributeMaxDynamicSharedMemorySize, GEMM_SMEM);
        cudaFuncSetAttribute(attn_score, cudaFuncAttributeMaxDynamicSharedMemorySize, SCORE_SMEM);
        attr_set = 1;
    }

    __half *w,*pat_hi,*pat_lo,*tn_hi,*tn_lo,*ctx_hi,*ctx_lo,*h_hi,*h_lo;
    float *p_x,*p_qkv,*p_qbuf,*p_kbuf,*p_cqs,*p_cks,
          *p_qs2,*p_ks2,*p_cqsum,*p_cksum,*p_attn,*p_qkvb,*p_cqkvb,*p_pool,*p_pooln;
    cudaGetSymbolAddress((void**)&w, g_w);
    cudaGetSymbolAddress((void**)&pat_hi, g_pat_hi);
    cudaGetSymbolAddress((void**)&pat_lo, g_pat_lo);
    cudaGetSymbolAddress((void**)&tn_hi, g_tn_hi);
    cudaGetSymbolAddress((void**)&tn_lo, g_tn_lo);
    cudaGetSymbolAddress((void**)&ctx_hi, g_ctx_hi);
    cudaGetSymbolAddress((void**)&ctx_lo, g_ctx_lo);
    cudaGetSymbolAddress((void**)&h_hi, g_h_hi);
    cudaGetSymbolAddress((void**)&h_lo, g_h_lo);
    cudaGetSymbolAddress((void**)&p_x,    g_x);
    cudaGetSymbolAddress((void**)&p_qkv,  g_qkv);
    cudaGetSymbolAddress((void**)&p_qbuf, g_qbuf);
    cudaGetSymbolAddress((void**)&p_kbuf, g_kbuf);
    cudaGetSymbolAddress((void**)&p_cqs,  g_cqs);
    cudaGetSymbolAddress((void**)&p_cks,  g_cks);
    cudaGetSymbolAddress((void**)&p_qs2,  g_qs2);
    cudaGetSymbolAddress((void**)&p_ks2,  g_ks2);
    cudaGetSymbolAddress((void**)&p_cqsum,g_cqsum);
    cudaGetSymbolAddress((void**)&p_cksum,g_cksum);
    cudaGetSymbolAddress((void**)&p_attn, g_attn);
    cudaGetSymbolAddress((void**)&p_qkvb, g_qkvb);
    cudaGetSymbolAddress((void**)&p_cqkvb,g_cqkvb);
    cudaGetSymbolAddress((void**)&p_pool, g_pool);
    cudaGetSymbolAddress((void**)&p_pooln,g_pooln);

    auto wsp = [&](const float* src, size_t off, size_t cnt){
        size_t n4 = cnt/4;
        wsplit_h<<<(unsigned)((n4+255)/256),256>>>((const float4*)src, w+off, n4);
    };
    wsp(patch_w,  OFF_PW,    589824);
    wsp(cpatch_w, OFF_CPW,   589824);
    wsp(qkvw,     OFF_QKV,   21233664);
    wsp(projw,    OFF_PROJ,  7077888);
    wsp(cprojw,   OFF_CPROJ, 7077888);
    wsp(fc1w,     OFF_FC1,   28311552);
    wsp(fc2w,     OFF_FC2,   28311552);

    build_qkvb<<<(NLAYER*E3+255)/256,256>>>(qb,vb,cqb,cvb,p_qkvb,p_cqkvb);
    im2col_split<<<(MROWS*EMB+255)/256,256>>>(x, pat_hi, pat_lo);

    gemm_h<<<dim3(EMB/128,13,2),256,GEMM_SMEM>>>(
        pat_hi,pat_lo, w+OFF_PW, w+OFF_CPW,
        patch_b, cpatch_b, nullptr, p_x, nullptr,nullptr, EMB, EMB, EPI_BIAS, EPI_BIAS, 1);
    fill_cls<<<BATCH,256>>>(cls, ccls, p_x);

    for (int i=0;i<NLAYER;i++){
        size_t qkv_o  = OFF_QKV   + (size_t)i*E3*EMB;
        size_t proj_o = OFF_PROJ  + (size_t)i*EMB*EMB;
        size_t cprj_o = OFF_CPROJ + (size_t)i*EMB*EMB;
        size_t fc1_o  = OFF_FC1   + (size_t)i*(size_t)MLPD*EMB;
        size_t fc2_o  = OFF_FC2   + (size_t)i*(size_t)EMB*MLPD;

        ln_split<<<2*MROWS,256>>>(p_x, n1g+i*EMB, n1b+i*EMB, tn_hi, tn_lo);
        gemm_h<<<dim3(E3/128,13,2),256,GEMM_SMEM>>>(
            tn_hi,tn_lo, w+qkv_o, w+qkv_o,
            p_qkvb+i*E3, p_cqkvb+i*E3, nullptr, p_qkv, nullptr,nullptr,
            E3, EMB, EPI_BIAS, EPI_ELU1, 0);

        attn_pre<<<BATCH*NHEAD*NTOK/4,256>>>(p_qkv,p_qbuf,p_kbuf,p_cqs,p_cks,
                                             p_qs2,p_ks2,p_cqsum,p_cksum);
        attn_score<<<dim3((NTOK+SNT-1)/SNT, BATCH*NHEAD),256,SCORE_SMEM>>>(
            p_qbuf,p_cqs,p_kbuf,p_cks,p_qs2,p_cqsum,p_ks2,p_cksum,relb,p_attn);
        attn_av2<<<dim3(NHEAD,(NTOK+31)/32,BATCH),256>>>(p_attn,p_qkv,ctx_hi,ctx_lo);

        gemm_h<<<dim3(EMB/128,13,2),256,GEMM_SMEM>>>(
            ctx_hi,ctx_lo, w+proj_o, w+cprj_o,
            projb+i*EMB, cprojb+i*EMB, gamma1+i*EMB, p_x, nullptr,nullptr,
            EMB, EMB, EPI_RES, EPI_RES, 0);

        ln_split<<<2*MROWS,256>>>(p_x, n2g+i*EMB, n2b+i*EMB, tn_hi, tn_lo);
        gemm_h<<<dim3(MLPD/128,13,2),256,GEMM_SMEM>>>(
            tn_hi,tn_lo, w+fc1_o, w+fc1_o,
            fc1b+i*MLPD, fc1b+i*MLPD, nullptr, nullptr, h_hi,h_lo,
            MLPD, EMB, EPI_GELU, EPI_GELU, 0);
        gemm_h<<<dim3(EMB/128,13,2),256,GEMM_SMEM>>>(
            h_hi,h_lo, w+fc2_o, w+fc2_o,
            fc2b+i*EMB, fc2b+i*EMB, gamma2+i*EMB, p_x, nullptr,nullptr,
            EMB, MLPD, EPI_RES, EPI_RES, 0);
    }

    pool_kernel<<<BATCH,256>>>(p_x, p_pool);
    ln_f32<<<BATCH,256>>>(p_pool, fng, fnb, p_pooln);
    head_kernel<<<(BATCH*NCLS+255)/256,256>>>(p_pooln, headw, headb, out);
}

// round 7
// speedup vs baseline: 4.5293x; 1.3642x over previous
#include <cuda_runtime.h>
#include <cuda_fp16.h>
#include <stdint.h>
#include <math.h>

#define BATCH 8
#define EMB 768
#define NHEAD 12
#define NLAYER 12
#define HD 64
#define NTOK 197
#define MROWS (BATCH*NTOK)   /* 1576 */
#define MPAD 1664            /* 13*128 */
#define E3 2304
#define MLPD 3072
#define QSCALE 0.125f
#define NCLS 1000

enum { EPI_BIAS=0, EPI_ELU1=1, EPI_GELU=2, EPI_RES=3 };

/* ---------------- weight plane offsets (elements) ---------------- */
#define OFF_PW    0ULL
#define OFF_CPW   589824ULL
#define OFF_QKV   1179648ULL
#define OFF_PROJ  22413312ULL
#define OFF_CPROJ 29491200ULL
#define OFF_FC1   36569088ULL
#define OFF_FC2   64880640ULL
#define WTOT      93192192ULL

/* ------------------------------ scratch ------------------------------ */
__device__ __half g_w[WTOT];                       /* fp16 weights */

__device__ __half g_pat[MPAD*EMB];
__device__ __half g_tn [2*MPAD*EMB];
__device__ __half g_ctx[2*MPAD*EMB];
__device__ __half g_h  [2*(size_t)MPAD*MLPD];

__device__ float g_x[2*MROWS*EMB];        /* mean rows [0,MROWS), cov rows [MROWS,2MROWS) */
__device__ float g_qkv[2*(size_t)MROWS*E3];
__device__ float g_qbuf[BATCH*NHEAD*NTOK*HD];
__device__ float g_kbuf[BATCH*NHEAD*NTOK*HD];
__device__ float g_cqs[BATCH*NHEAD*NTOK*HD];
__device__ float g_cks[BATCH*NHEAD*NTOK*HD];
__device__ float g_qs2[BATCH*NHEAD*NTOK];
__device__ float g_ks2[BATCH*NHEAD*NTOK];
__device__ float g_cqsum[BATCH*NHEAD*NTOK];
__device__ float g_cksum[BATCH*NHEAD*NTOK];
__device__ float g_attn[(size_t)BATCH*NHEAD*NTOK*NTOK];
__device__ float g_qkvb[NLAYER*E3];
__device__ float g_cqkvb[NLAYER*E3];
__device__ float g_pool[BATCH*EMB];
__device__ float g_pooln[BATCH*EMB];

/* ------------------------------ helpers ------------------------------ */
__device__ __forceinline__ uint32_t s2u(const void* p){
    return (uint32_t)__cvta_generic_to_shared(p);
}
__device__ __forceinline__ void cpa16(uint32_t dst, const void* src){
    asm volatile("cp.async.cg.shared.global [%0], [%1], 16;\n" :: "r"(dst), "l"(src));
}
__device__ __forceinline__ void mma16816(float* c, uint32_t a0,uint32_t a1,uint32_t a2,uint32_t a3,
                                         uint32_t b0,uint32_t b1){
    asm volatile("mma.sync.aligned.m16n8k16.row.col.f32.f16.f16.f32 "
        "{%0,%1,%2,%3},{%4,%5,%6,%7},{%8,%9},{%0,%1,%2,%3};\n"
        : "+f"(c[0]),"+f"(c[1]),"+f"(c[2]),"+f"(c[3])
        : "r"(a0),"r"(a1),"r"(a2),"r"(a3),"r"(b0),"r"(b1));
}

/* ---------------- fp16 GEMM: C[M,N] = A[M,K]*B[N,K]^T ----------------
   A and B single fp16 planes. 128x128x32 tiles, 8 warps (2x4),
   warp tile 64x32, mma.m16n8k16.
   grid = (N/128, 13, 2). z = half (0 mean path, 1 cov path).         */
#define APITCH 20
#define PLANE_U32 (128*APITCH)
#define STAGE_U32 (2*PLANE_U32)
#define GEMM_SMEM (2*STAGE_U32*4)

__global__ void __launch_bounds__(256)
gemm_h(const __half* __restrict__ A,
       const __half* __restrict__ B0, const __half* __restrict__ B1,
       const float* __restrict__ bias0, const float* __restrict__ bias1,
       const float* __restrict__ gamma,
       float* __restrict__ C, __half* __restrict__ Ch,
       int N, int K, int epi0, int epi1, int aShared)
{
    extern __shared__ uint32_t smem[];
    const int tid = threadIdx.x;
    const int lane = tid & 31, wid = tid >> 5;
    const int wm = wid >> 2, wn = wid & 3;
    const int g = lane >> 2, tig = lane & 3;
    const int half_ = blockIdx.z;
    const int lmBase = blockIdx.y * 128;
    const int aBase = (aShared ? 0 : half_*MPAD) + lmBase;
    const int bn = blockIdx.x * 128;
    const int K2 = K >> 1;
    const __half* B = half_ ? B1 : B0;
    const float* bias = half_ ? bias1 : bias0;
    const int epi = half_ ? epi1 : epi0;

    const uint32_t* gA = (const uint32_t*)A;
    const uint32_t* gB = (const uint32_t*)B;
    const uint32_t sbase_u = s2u(smem);

    float acc[4][4][4];
#pragma unroll
    for (int a=0;a<4;a++)
#pragma unroll
        for (int b=0;b<4;b++)
#pragma unroll
            for (int c=0;c<4;c++) acc[a][b][c]=0.f;

    const int KT = K >> 5;

    auto fill = [&](int buf, int kt){
        uint32_t sd = sbase_u + (uint32_t)buf*STAGE_U32*4;
        int kc0 = kt*16;
#pragma unroll
        for (int i=0;i<2;i++){
            int t = tid + i*256;
            int row = t >> 2, ch = (t & 3) * 4;
            size_t ga = (size_t)(aBase+row)*K2 + kc0 + ch;
            size_t gb = (size_t)(bn + row)*K2 + kc0 + ch;
            uint32_t so = (uint32_t)(row*APITCH + ch)*4;
            cpa16(sd + so,                 gA + ga);
            cpa16(sd + PLANE_U32*4 + so,   gB + gb);
        }
        asm volatile("cp.async.commit_group;\n");
    };

    fill(0, 0);
    for (int kt=0; kt<KT; kt++){
        int buf = kt & 1;
        if (kt+1 < KT) fill(buf^1, kt+1);
        else asm volatile("cp.async.commit_group;\n");
        asm volatile("cp.async.wait_group 1;\n" ::: "memory");
        __syncthreads();

        const uint32_t* sA = smem + buf*STAGE_U32;
        const uint32_t* sB = sA + PLANE_U32;

#pragma unroll
        for (int ks=0; ks<2; ks++){
            const int kc = ks*8 + tig;
            uint32_t bh[4][2];
#pragma unroll
            for (int nt=0;nt<4;nt++){
                int n = wn*32 + nt*8 + g;
                bh[nt][0]=sB[n*APITCH+kc]; bh[nt][1]=sB[n*APITCH+kc+4];
            }
#pragma unroll
            for (int mt=0;mt<4;mt++){
                int m = wm*64 + mt*16 + g;
                uint32_t a0=sA[m*APITCH+kc],     a1=sA[(m+8)*APITCH+kc];
                uint32_t a2=sA[m*APITCH+kc+4],   a3=sA[(m+8)*APITCH+kc+4];
#pragma unroll
                for (int nt=0;nt<4;nt++){
                    mma16816(acc[mt][nt], a0,a1,a2,a3, bh[nt][0],bh[nt][1]);
                }
            }
        }
        __syncthreads();
    }

    /* epilogue */
#pragma unroll
    for (int mt=0;mt<4;mt++){
        int lm0 = lmBase + wm*64 + mt*16 + g;
#pragma unroll
        for (int hf=0; hf<2; hf++){
            int lm = lm0 + hf*8;
            if (lm >= MROWS) continue;
            size_t crow = (size_t)(half_*MROWS + lm)*N;
            size_t prow = (size_t)(half_*MPAD  + lm)*N;
#pragma unroll
            for (int nt=0;nt<4;nt++){
                int gn = bn + wn*32 + nt*8 + tig*2;
                float z0 = acc[mt][nt][hf*2+0];
                float z1 = acc[mt][nt][hf*2+1];
                if (bias){ z0 += bias[gn]; z1 += bias[gn+1]; }
                if (epi == EPI_BIAS){
                    *(float2*)(C + crow + gn) = make_float2(z0, z1);
                } else if (epi == EPI_ELU1){
                    float o0 = (z0>0.f)? z0+1.f : expf(z0);
                    float o1 = (z1>0.f)? z1+1.f : expf(z1);
                    *(float2*)(C + crow + gn) = make_float2(o0,o1);
                } else if (epi == EPI_GELU){
                    float o0 = 0.5f*z0*(1.f+erff(z0*0.70710678118f));
                    float o1 = 0.5f*z1*(1.f+erff(z1*0.70710678118f));
                    __half2 hv;
                    hv.x = __float2half_rn(o0); hv.y = __float2half_rn(o1);
                    *(__half2*)(Ch + prow + gn) = hv;
                } else {
                    float2 old = *(const float2*)(C + crow + gn);
                    float o0 = old.x + gamma[gn]*z0;
                    float o1 = old.y + gamma[gn+1]*z1;
                    *(float2*)(C + crow + gn) = make_float2(o0,o1);
                }
            }
        }
    }
}

/* ---------------- weight -> fp16 ---------------- */
__global__ void wsplit_h(const float4* __restrict__ src, __half* __restrict__ hi, size_t n4)
{
    size_t i = (size_t)blockIdx.x*256 + threadIdx.x;
    if (i >= n4) return;
    float4 f = src[i];
    __half2 a, b;
    a.x = __float2half_rn(f.x); a.y = __float2half_rn(f.y);
    b.x = __float2half_rn(f.z); b.y = __float2half_rn(f.w);
    *(__half2*)(hi + 4*i)   = a;
    *(__half2*)(hi + 4*i+2) = b;
}

/* ---------------- merged LayerNorm -> fp16 plane ---------------- */
__global__ void __launch_bounds__(256) ln_split(const float* __restrict__ x,
        const float* __restrict__ g, const float* __restrict__ b,
        __half* __restrict__ yh)
{
    int row = blockIdx.x;
    int drow = (row < MROWS) ? row : row + (MPAD - MROWS);
    const float* xr = x + (size_t)row*EMB;
    int tid = threadIdx.x;
    float v0=xr[tid], v1=xr[tid+256], v2=xr[tid+512];
    float s  = v0+v1+v2;
    float s2 = v0*v0+v1*v1+v2*v2;
    __shared__ float red[2][8];
    int lane=tid&31, wid=tid>>5;
#pragma unroll
    for(int o=16;o;o>>=1){ s+=__shfl_xor_sync(0xffffffffu,s,o); s2+=__shfl_xor_sync(0xffffffffu,s2,o); }
    if(!lane){ red[0][wid]=s; red[1][wid]=s2; }
    __syncthreads();
    s=0.f; s2=0.f;
#pragma unroll
    for (int i=0;i<8;i++){ s+=red[0][i]; s2+=red[1][i]; }
    float mu = s * (1.f/768.f);
    float var = s2*(1.f/768.f) - mu*mu;
    float inv = rsqrtf(var + 1e-5f);
    size_t o0 = (size_t)drow*EMB;
#pragma unroll
    for (int r=0;r<3;r++){
        int e = tid + r*256;
        float v = (r==0)?v0:((r==1)?v1:v2);
        float y = (v-mu)*inv*g[e] + b[e];
        yh[o0+e] = __float2half_rn(y);
    }
}

__global__ void __launch_bounds__(256) ln_f32(const float* __restrict__ x,
        const float* __restrict__ g, const float* __restrict__ b,
        float* __restrict__ y)
{
    int row = blockIdx.x;
    const float* xr = x + (size_t)row*EMB;
    float* yr = y + (size_t)row*EMB;
    int tid = threadIdx.x;
    float v0=xr[tid], v1=xr[tid+256], v2=xr[tid+512];
    float s  = v0+v1+v2;
    float s2 = v0*v0+v1*v1+v2*v2;
    __shared__ float red[2][8];
    int lane=tid&31, wid=tid>>5;
#pragma unroll
    for(int o=16;o;o>>=1){ s+=__shfl_xor_sync(0xffffffffu,s,o); s2+=__shfl_xor_sync(0xffffffffu,s2,o); }
    if(!lane){ red[0][wid]=s; red[1][wid]=s2; }
    __syncthreads();
    s=0.f; s2=0.f;
#pragma unroll
    for (int i=0;i<8;i++){ s+=red[0][i]; s2+=red[1][i]; }
    float mu = s * (1.f/768.f);
    float var = s2*(1.f/768.f) - mu*mu;
    float inv = rsqrtf(var + 1e-5f);
    yr[tid]     = (v0-mu)*inv*g[tid]     + b[tid];
    yr[tid+256] = (v1-mu)*inv*g[tid+256] + b[tid+256];
    yr[tid+512] = (v2-mu)*inv*g[tid+512] + b[tid+512];
}

/* ---------------- im2col -> fp16 plane ---------------- */
__global__ void im2col_split(const float* __restrict__ x, __half* __restrict__ ph)
{
    int idx = blockIdx.x*blockDim.x + threadIdx.x;
    if (idx >= MROWS*EMB) return;
    int r = idx / EMB, col = idx % EMB;
    int b = r / NTOK, t = r % NTOK;
    float v = 0.f;
    if (t > 0){
        int pp = t-1;
        int py = pp/14, px = pp%14;
        int c = col >> 8, phh = (col>>4)&15, pw = col&15;
        v = x[(((size_t)b*3 + c)*224 + py*16+phh)*224 + px*16+pw];
    }
    ph[idx] = __float2half_rn(v);
}

__global__ void fill_cls(const float* __restrict__ cls, const float* __restrict__ ccls,
                         float* __restrict__ xx)
{
    int b = blockIdx.x, tid=threadIdx.x;
#pragma unroll
    for (int r=0;r<3;r++){
        int e = tid+r*256;
        xx[(size_t)b*NTOK*EMB+e]              = cls[e];
        xx[((size_t)MROWS + b*NTOK)*EMB+e]    = ccls[e];
    }
}

__global__ void build_qkvb(const float* __restrict__ qb, const float* __restrict__ vb,
                           const float* __restrict__ cqb, const float* __restrict__ cvb,
                           float* __restrict__ outv, float* __restrict__ coutv)
{
    int idx = blockIdx.x*blockDim.x+threadIdx.x;
    if (idx >= NLAYER*E3) return;
    int l = idx / E3, j = idx % E3;
    float v=0.f, cv=0.f;
    if (j < EMB)        { v=qb[l*EMB+j];        cv=cqb[l*EMB+j]; }
    else if (j >= 2*EMB){ v=vb[l*EMB+j-2*EMB];  cv=cvb[l*EMB+j-2*EMB]; }
    outv[idx]=v; coutv[idx]=cv;
}

/* -------- attention preprocess: 4 tokens per 256-thread block -------- */
__global__ void __launch_bounds__(256) attn_pre(const float* __restrict__ qkv,
   float* __restrict__ qb, float* __restrict__ kb, float* __restrict__ cqs, float* __restrict__ cks,
   float* __restrict__ qs2, float* __restrict__ ks2, float* __restrict__ cqsum, float* __restrict__ cksum)
{
    int grp = threadIdx.x >> 6;
    int d   = threadIdx.x & 63;
    int idx = blockIdx.x*4 + grp;
    int t  = idx % NTOK;
    int bh = idx / NTOK;
    int h  = bh % NHEAD;
    int b  = bh / NHEAD;
    size_t mb = ((size_t)(b*NTOK+t))*E3 + h*HD + d;
    size_t cb = ((size_t)(MROWS + b*NTOK+t))*E3 + h*HD + d;
    float q  = qkv[mb]*QSCALE;
    float k  = qkv[mb+EMB];
    float cq = qkv[cb];
    float ck = qkv[cb+EMB];
    float sq = sqrtf(fmaxf(cq,1e-24f));
    float sk = sqrtf(fmaxf(ck,1e-24f));
    size_t o = (size_t)idx*HD + d;
    qb[o]=q; kb[o]=k; cqs[o]=sq; cks[o]=sk;
    float r0=q*q, r1=k*k, r2=cq, r3=ck;
#pragma unroll
    for(int off=16;off;off>>=1){
        r0+=__shfl_xor_sync(0xffffffffu,r0,off);
        r1+=__shfl_xor_sync(0xffffffffu,r1,off);
        r2+=__shfl_xor_sync(0xffffffffu,r2,off);
        r3+=__shfl_xor_sync(0xffffffffu,r3,off);
    }
    __shared__ float sh[4][4][2];
    int lane = threadIdx.x & 31;
    int wno = (threadIdx.x >> 5) & 1;
    if(!lane){ sh[grp][0][wno]=r0; sh[grp][1][wno]=r1; sh[grp][2][wno]=r2; sh[grp][3][wno]=r3; }
    __syncthreads();
    if (d==0){
        qs2[idx]  =sh[grp][0][0]+sh[grp][0][1];
        ks2[idx]  =sh[grp][1][0]+sh[grp][1][1];
        cqsum[idx]=sh[grp][2][0]+sh[grp][2][1];
        cksum[idx]=sh[grp][3][0]+sh[grp][3][1];
    }
}

/* -------- Wasserstein scores + sigmoid + bias + softmax -------- */
#define SNT 16
#define SMT 64
#define KP  68
#define OFF_QSH  0
#define OFF_CQSH (SNT*KP)
#define OFF_KT   (2*SNT*KP)
#define OFF_CKT  (OFF_KT + SMT*KP)
#define OFF_SSC  (OFF_CKT + SMT*KP)
#define OFF_RQ2  (OFF_SSC + SNT*208)
#define OFF_RCQ  (OFF_RQ2 + SNT)
#define SCORE_SMEM ((OFF_RCQ + SNT)*4)

__global__ void __launch_bounds__(256) attn_score(
    const float* __restrict__ qbuf, const float* __restrict__ cqs,
    const float* __restrict__ kbuf, const float* __restrict__ cks,
    const float* __restrict__ qs2,  const float* __restrict__ cqsum,
    const float* __restrict__ ks2,  const float* __restrict__ cksum,
    const float* __restrict__ relb, float* __restrict__ attn)
{
    extern __shared__ float sm[];
    float* qsh  = sm + OFF_QSH;
    float* cqsh = sm + OFF_CQSH;
    float* kt   = sm + OFF_KT;
    float* ckt  = sm + OFF_CKT;
    float* ssc  = sm + OFF_SSC;
    float* rowq2= sm + OFF_RQ2;
    float* rowcq= sm + OFF_RCQ;

    int bh = blockIdx.y;
    int h  = bh % NHEAD;
    int n0 = blockIdx.x * SNT;
    int tid = threadIdx.x;

    for (int i = tid; i < SNT*64; i += 256) {
        int nl = i>>6, d = i&63;
        int n = n0+nl;
        float qv=0.f, cv=0.f;
        if (n < NTOK) { size_t o=((size_t)bh*NTOK+n)*64+d; qv=qbuf[o]; cv=cqs[o]; }
        qsh[nl*KP+d]=qv; cqsh[nl*KP+d]=cv;
    }
    if (tid < SNT) {
        int n = n0+tid;
        rowq2[tid] = (n<NTOK)? qs2[bh*NTOK+n]:0.f;
        rowcq[tid] = (n<NTOK)? cqsum[bh*NTOK+n]:0.f;
    }
    __syncthreads();

    const int nl  = tid >> 4;
    const int mlb = tid & 15;
    const int n   = n0 + nl;

    for (int m0=0; m0<NTOK; m0+=SMT) {
        for (int i = tid; i < SMT*64; i += 256) {
            int ml=i>>6, d=i&63; int m=m0+ml;
            float kv=0.f,cv=0.f;
            if (m<NTOK){ size_t o=((size_t)bh*NTOK+m)*64+d; kv=kbuf[o]; cv=cks[o]; }
            kt[ml*KP+d]=kv; ckt[ml*KP+d]=cv;
        }
        __syncthreads();

        float dm[4]={0,0,0,0}, dc[4]={0,0,0,0};
#pragma unroll
        for (int d=0; d<64; d+=4){
            float4 q4 = *(const float4*)&qsh[nl*KP+d];
            float4 c4 = *(const float4*)&cqsh[nl*KP+d];
#pragma unroll
            for (int j=0;j<4;j++){
                float4 k4 = *(const float4*)&kt[(mlb+16*j)*KP+d];
                dm[j] = fmaf(q4.x,k4.x,fmaf(q4.y,k4.y,fmaf(q4.z,k4.z,fmaf(q4.w,k4.w,dm[j]))));
                float4 e4 = *(const float4*)&ckt[(mlb+16*j)*KP+d];
                dc[j] = fmaf(c4.x,e4.x,fmaf(c4.y,e4.y,fmaf(c4.z,e4.z,fmaf(c4.w,e4.w,dc[j]))));
            }
        }
        if (n < NTOK){
#pragma unroll
            for (int j=0;j<4;j++){
                int m = m0 + mlb + 16*j;
                if (m < NTOK){
                    float w = -2.f*dm[j] + rowq2[nl] + ks2[bh*NTOK+m]
                              -2.f*dc[j] + rowcq[nl] + cksum[bh*NTOK+m];
                    float s = 1.f/(1.f+expf(w - 1e-24f));
                    ssc[nl*208+m] = s + relb[((size_t)h*NTOK + n)*NTOK + m];
                }
            }
        }
        __syncthreads();
    }
    int wid = tid>>5, lane = tid&31;
    for (int r = wid; r < SNT; r += 8) {
        int nn = n0+r;
        if (nn >= NTOK) continue;
        float mx = -1e30f;
        for (int m=lane; m<NTOK; m+=32) mx = fmaxf(mx, ssc[r*208+m]);
#pragma unroll
        for (int o=16;o;o>>=1) mx = fmaxf(mx, __shfl_xor_sync(0xffffffffu,mx,o));
        float sum=0.f;
        for (int m=lane;m<NTOK;m+=32){ float e=expf(ssc[r*208+m]-mx); ssc[r*208+m]=e; sum+=e; }
#pragma unroll
        for (int o=16;o;o>>=1) sum += __shfl_xor_sync(0xffffffffu,sum,o);
        float inv = 1.f/sum;
        for (int m=lane;m<NTOK;m+=32)
            attn[(((size_t)bh)*NTOK+nn)*NTOK+m] = ssc[r*208+m]*inv;
    }
}

/* -------- AV: mean_ctx / cov_ctx, writes fp16 plane -------- */
__global__ void __launch_bounds__(256) attn_av2(const float* __restrict__ attn,
    const float* __restrict__ qkv, __half* __restrict__ ch_)
{
    int h  = blockIdx.x;
    int n0 = blockIdx.y * 32;
    int b  = blockIdx.z;
    int e0 = h * 64;
    __shared__ float sat[32][200];
    __shared__ float sv[32][64], scv[32][64];
    int tid = threadIdx.x;
    int wid = tid>>5, lane = tid&31;

    for (int r = wid; r < 32; r += 8){
        int n = n0 + r;
        if (n < NTOK){
            const float* src = attn + (((size_t)(b*NHEAD+h))*NTOK + n)*NTOK;
            for (int m=lane; m<NTOK; m+=32) sat[r][m] = src[m];
        } else {
            for (int m=lane; m<NTOK; m+=32) sat[r][m] = 0.f;
        }
    }

    float acc[2][4]={{0}}, cac[2][4]={{0}};
    int ew = (tid & 15) * 4;
    int nb = (tid >> 4) * 2;

    for (int m0=0; m0<NTOK; m0+=32){
        __syncthreads();
        for (int i = tid; i < 32*16; i += 256){
            int mr = i >> 4, c4 = (i & 15)*4;
            int m = m0 + mr;
            float4 v = make_float4(0,0,0,0), cv = make_float4(0,0,0,0);
            if (m < NTOK){
                size_t vb = ((size_t)(b*NTOK+m))*E3 + 2*EMB + e0 + c4;
                size_t cb = ((size_t)(MROWS + b*NTOK+m))*E3 + 2*EMB + e0 + c4;
                v  = *(const float4*)(qkv + vb);
                cv = *(const float4*)(qkv + cb);
            }
            *(float4*)&sv[mr][c4]  = v;
            *(float4*)&scv[mr][c4] = cv;
        }
        __syncthreads();
        int mlim = min(32, NTOK-m0);
        for (int mm=0; mm<mlim; mm++){
            float4 v  = *(const float4*)&sv[mm][ew];
            float4 cv = *(const float4*)&scv[mm][ew];
#pragma unroll
            for (int i=0;i<2;i++){
                float a = sat[nb+i][m0+mm];
                float a2 = a*a;
                acc[i][0]=fmaf(a,v.x,acc[i][0]); acc[i][1]=fmaf(a,v.y,acc[i][1]);
                acc[i][2]=fmaf(a,v.z,acc[i][2]); acc[i][3]=fmaf(a,v.w,acc[i][3]);
                cac[i][0]=fmaf(a2,cv.x,cac[i][0]); cac[i][1]=fmaf(a2,cv.y,cac[i][1]);
                cac[i][2]=fmaf(a2,cv.z,cac[i][2]); cac[i][3]=fmaf(a2,cv.w,cac[i][3]);
            }
        }
    }
#pragma unroll
    for (int i=0;i<2;i++){
        int n = n0 + nb + i;
        if (n >= NTOK) continue;
        size_t mbase = ((size_t)(b*NTOK+n))*EMB + e0 + ew;
        size_t cbase = ((size_t)(MPAD + b*NTOK+n))*EMB + e0 + ew;
#pragma unroll
        for (int j=0;j<4;j++){
            ch_[mbase+j] = __float2half_rn(acc[i][j]);
            ch_[cbase+j] = __float2half_rn(cac[i][j]);
        }
    }
}

/* ------------------------------ tail ---------------------------------- */
__global__ void __launch_bounds__(256) pool_kernel(const float* __restrict__ xx, float* __restrict__ pool)
{
    int b = blockIdx.x;
    int tid=threadIdx.x;
#pragma unroll
    for (int r=0;r<3;r++){
        int e = tid + r*256;
        float s=0.f;
        for (int n=1;n<NTOK;n++) s += xx[((size_t)(b*NTOK+n))*EMB+e];
        pool[b*EMB+e]=s*(1.f/196.f);
    }
}

__global__ void head_kernel(const float* __restrict__ t, const float* __restrict__ w,
                            const float* __restrict__ hb, float* __restrict__ out)
{
    int idx = blockIdx.x*blockDim.x + threadIdx.x;
    if (idx >= BATCH*NCLS) return;
    int b = idx/NCLS, c = idx%NCLS;
    const float* tr = t + b*EMB;
    const float* wr = w + (size_t)c*EMB;
    float s = hb[c];
    for (int e=0;e<EMB;e+=4){
        float4 tv=*(const float4*)(tr+e);
        float4 wv=*(const float4*)(wr+e);
        s += tv.x*wv.x+tv.y*wv.y+tv.z*wv.z+tv.w*wv.w;
    }
    out[idx]=s;
}

/* ------------------------------ host ---------------------------------- */
extern "C" void kernel_launch(void* const* d_in, const int* in_sizes, int n_in,
                              void* d_out, int out_size)
{
    const float* x        = (const float*)d_in[0];
    const float* relb     = (const float*)d_in[1];
    const float* patch_w  = (const float*)d_in[2];
    const float* patch_b  = (const float*)d_in[3];
    const float* cpatch_w = (const float*)d_in[4];
    const float* cpatch_b = (const float*)d_in[5];
    const float* cls      = (const float*)d_in[6];
    const float* ccls     = (const float*)d_in[7];
    const float* n1g      = (const float*)d_in[8];
    const float* n1b      = (const float*)d_in[9];
    const float* qkvw     = (const float*)d_in[10];
    const float* qb       = (const float*)d_in[11];
    const float* vb       = (const float*)d_in[12];
    const float* cqb      = (const float*)d_in[13];
    const float* cvb      = (const float*)d_in[14];
    const float* projw    = (const float*)d_in[15];
    const float* projb    = (const float*)d_in[16];
    const float* cprojw   = (const float*)d_in[17];
    const float* cprojb   = (const float*)d_in[18];
    const float* gamma1   = (const float*)d_in[19];
    const float* gamma2   = (const float*)d_in[20];
    const float* n2g      = (const float*)d_in[21];
    const float* n2b      = (const float*)d_in[22];
    const float* fc1w     = (const float*)d_in[23];
    const float* fc1b     = (const float*)d_in[24];
    const float* fc2w     = (const float*)d_in[25];
    const float* fc2b     = (const float*)d_in[26];
    const float* fng      = (const float*)d_in[27];
    const float* fnb      = (const float*)d_in[28];
    const float* headw    = (const float*)d_in[29];
    const float* headb    = (const float*)d_in[30];
    float* out = (float*)d_out;

    static int attr_set = 0;
    if (!attr_set){
        cudaFuncSetAttribute(gemm_h, cudaFuncAttributeMaxDynamicSharedMemorySize, GEMM_SMEM);
        cudaFuncSetAttribute(attn_score, cudaFuncAttributeMaxDynamicSharedMemorySize, SCORE_SMEM);
        attr_set = 1;
    }

    __half *w,*pat,*tn,*ctx,*hbuf;
    float *p_x,*p_qkv,*p_qbuf,*p_kbuf,*p_cqs,*p_cks,
          *p_qs2,*p_ks2,*p_cqsum,*p_cksum,*p_attn,*p_qkvb,*p_cqkvb,*p_pool,*p_pooln;
    cudaGetSymbolAddress((void**)&w, g_w);
    cudaGetSymbolAddress((void**)&pat, g_pat);
    cudaGetSymbolAddress((void**)&tn, g_tn);
    cudaGetSymbolAddress((void**)&ctx, g_ctx);
    cudaGetSymbolAddress((void**)&hbuf, g_h);
    cudaGetSymbolAddress((void**)&p_x,    g_x);
    cudaGetSymbolAddress((void**)&p_qkv,  g_qkv);
    cudaGetSymbolAddress((void**)&p_qbuf, g_qbuf);
    cudaGetSymbolAddress((void**)&p_kbuf, g_kbuf);
    cudaGetSymbolAddress((void**)&p_cqs,  g_cqs);
    cudaGetSymbolAddress((void**)&p_cks,  g_cks);
    cudaGetSymbolAddress((void**)&p_qs2,  g_qs2);
    cudaGetSymbolAddress((void**)&p_ks2,  g_ks2);
    cudaGetSymbolAddress((void**)&p_cqsum,g_cqsum);
    cudaGetSymbolAddress((void**)&p_cksum,g_cksum);
    cudaGetSymbolAddress((void**)&p_attn, g_attn);
    cudaGetSymbolAddress((void**)&p_qkvb, g_qkvb);
    cudaGetSymbolAddress((void**)&p_cqkvb,g_cqkvb);
    cudaGetSymbolAddress((void**)&p_pool, g_pool);
    cudaGetSymbolAddress((void**)&p_pooln,g_pooln);

    auto wsp = [&](const float* src, size_t off, size_t cnt){
        size_t n4 = cnt/4;
        wsplit_h<<<(unsigned)((n4+255)/256),256>>>((const float4*)src, w+off, n4);
    };
    wsp(patch_w,  OFF_PW,    589824);
    wsp(cpatch_w, OFF_CPW,   589824);
    wsp(qkvw,     OFF_QKV,   21233664);
    wsp(projw,    OFF_PROJ,  7077888);
    wsp(cprojw,   OFF_CPROJ, 7077888);
    wsp(fc1w,     OFF_FC1,   28311552);
    wsp(fc2w,     OFF_FC2,   28311552);

    build_qkvb<<<(NLAYER*E3+255)/256,256>>>(qb,vb,cqb,cvb,p_qkvb,p_cqkvb);
    im2col_split<<<(MROWS*EMB+255)/256,256>>>(x, pat);

    gemm_h<<<dim3(EMB/128,13,2),256,GEMM_SMEM>>>(
        pat, w+OFF_PW, w+OFF_CPW,
        patch_b, cpatch_b, nullptr, p_x, nullptr, EMB, EMB, EPI_BIAS, EPI_BIAS, 1);
    fill_cls<<<BATCH,256>>>(cls, ccls, p_x);

    for (int i=0;i<NLAYER;i++){
        size_t qkv_o  = OFF_QKV   + (size_t)i*E3*EMB;
        size_t proj_o = OFF_PROJ  + (size_t)i*EMB*EMB;
        size_t cprj_o = OFF_CPROJ + (size_t)i*EMB*EMB;
        size_t fc1_o  = OFF_FC1   + (size_t)i*(size_t)MLPD*EMB;
        size_t fc2_o  = OFF_FC2   + (size_t)i*(size_t)EMB*MLPD;

        ln_split<<<2*MROWS,256>>>(p_x, n1g+i*EMB, n1b+i*EMB, tn);
        gemm_h<<<dim3(E3/128,13,2),256,GEMM_SMEM>>>(
            tn, w+qkv_o, w+qkv_o,
            p_qkvb+i*E3, p_cqkvb+i*E3, nullptr, p_qkv, nullptr,
            E3, EMB, EPI_BIAS, EPI_ELU1, 0);

        attn_pre<<<BATCH*NHEAD*NTOK/4,256>>>(p_qkv,p_qbuf,p_kbuf,p_cqs,p_cks,
                                             p_qs2,p_ks2,p_cqsum,p_cksum);
        attn_score<<<dim3((NTOK+SNT-1)/SNT, BATCH*NHEAD),256,SCORE_SMEM>>>(
            p_qbuf,p_cqs,p_kbuf,p_cks,p_qs2,p_cqsum,p_ks2,p_cksum,relb,p_attn);
        attn_av2<<<dim3(NHEAD,(NTOK+31)/32,BATCH),256>>>(p_attn,p_qkv,ctx);

        gemm_h<<<dim3(EMB/128,13,2),256,GEMM_SMEM>>>(
            ctx, w+proj_o, w+cprj_o,
            projb+i*EMB, cprojb+i*EMB, gamma1+i*EMB, p_x, nullptr,
            EMB, EMB, EPI_RES, EPI_RES, 0);

        ln_split<<<2*MROWS,256>>>(p_x, n2g+i*EMB, n2b+i*EMB, tn);
        gemm_h<<<dim3(MLPD/128,13,2),256,GEMM_SMEM>>>(
            tn, w+fc1_o, w+fc1_o,
            fc1b+i*MLPD, fc1b+i*MLPD, nullptr, nullptr, hbuf,
            MLPD, EMB, EPI_GELU, EPI_GELU, 0);
        gemm_h<<<dim3(EMB/128,13,2),256,GEMM_SMEM>>>(
            hbuf, w+fc2_o, w+fc2_o,
            fc2b+i*EMB, fc2b+i*EMB, gamma2+i*EMB, p_x, nullptr,
            EMB, MLPD, EPI_RES, EPI_RES, 0);
    }

    pool_kernel<<<BATCH,256>>>(p_x, p_pool);
    ln_f32<<<BATCH,256>>>(p_pool, fng, fnb, p_pooln);
    head_kernel<<<(BATCH*NCLS+255)/256,256>>>(p_pooln, headw, headb, out);
}

// round 8
// speedup vs baseline: 5.5349x; 1.2220x over previous
#include <cuda_runtime.h>
#include <cuda_fp16.h>
#include <stdint.h>
#include <math.h>

#define BATCH 8
#define EMB 768
#define NHEAD 12
#define NLAYER 12
#define HD 64
#define NTOK 197
#define MROWS (BATCH*NTOK)   /* 1576 */
#define MPAD 1664            /* 13*128 */
#define E3 2304
#define MLPD 3072
#define QSCALE 0.125f
#define NCLS 1000
#define BH 96                /* BATCH*NHEAD */
#define TP 256               /* padded tokens for mma M/N */
#define MP 208               /* padded m (K dim of AV) */

enum { EPI_BIAS=0, EPI_ELU1=1, EPI_GELU=2, EPI_RES=3 };

/* ---------------- weight plane offsets (elements) ---------------- */
#define OFF_PW    0ULL
#define OFF_CPW   589824ULL
#define OFF_QKV   1179648ULL
#define OFF_PROJ  22413312ULL
#define OFF_CPROJ 29491200ULL
#define OFF_FC1   36569088ULL
#define OFF_FC2   64880640ULL
#define WTOT      93192192ULL

/* ------------------------------ scratch ------------------------------ */
__device__ __half g_w[WTOT];

__device__ __half g_pat[MPAD*EMB];
__device__ __half g_tn [2*MPAD*EMB];
__device__ __half g_ctx[2*MPAD*EMB];
__device__ __half g_h  [2*(size_t)MPAD*MLPD];

__device__ float g_x[2*MROWS*EMB];
__device__ float g_qkv[2*(size_t)MROWS*E3];

/* attention buffers (zero-initialized; pad regions never written) */
__device__ __half g_qph[(size_t)BH*TP*128];
__device__ __half g_qpl[(size_t)BH*TP*128];
__device__ __half g_kp [(size_t)BH*TP*128];
__device__ __half g_vt [(size_t)BH*64*MP];
__device__ __half g_cvt[(size_t)BH*64*MP];
__device__ float  g_sdot[(size_t)BH*TP*TP];
__device__ __half g_ah [(size_t)BH*TP*MP];
__device__ __half g_al [(size_t)BH*TP*MP];
__device__ __half g_a2h[(size_t)BH*TP*MP];
__device__ __half g_a2l[(size_t)BH*TP*MP];

__device__ float g_qs2[BH*NTOK];
__device__ float g_ks2[BH*NTOK];
__device__ float g_cqsum[BH*NTOK];
__device__ float g_cksum[BH*NTOK];
__device__ float g_qkvb[NLAYER*E3];
__device__ float g_cqkvb[NLAYER*E3];
__device__ float g_pool[BATCH*EMB];
__device__ float g_pooln[BATCH*EMB];

/* ------------------------------ helpers ------------------------------ */
__device__ __forceinline__ uint32_t s2u(const void* p){
    return (uint32_t)__cvta_generic_to_shared(p);
}
__device__ __forceinline__ void cpa16(uint32_t dst, const void* src){
    asm volatile("cp.async.cg.shared.global [%0], [%1], 16;\n" :: "r"(dst), "l"(src));
}
__device__ __forceinline__ void mma16816(float* c, uint32_t a0,uint32_t a1,uint32_t a2,uint32_t a3,
                                         uint32_t b0,uint32_t b1){
    asm volatile("mma.sync.aligned.m16n8k16.row.col.f32.f16.f16.f32 "
        "{%0,%1,%2,%3},{%4,%5,%6,%7},{%8,%9},{%0,%1,%2,%3};\n"
        : "+f"(c[0]),"+f"(c[1]),"+f"(c[2]),"+f"(c[3])
        : "r"(a0),"r"(a1),"r"(a2),"r"(a3),"r"(b0),"r"(b1));
}
__device__ __forceinline__ void split_h(float f, __half& h, __half& l){
    h = __float2half_rn(f);
    l = __float2half_rn(f - __half2float(h));
}

/* ---------------- fp16 GEMM: C[M,N] = A[M,K]*B[N,K]^T ---------------- */
#define APITCH 20
#define PLANE_U32 (128*APITCH)
#define STAGE_U32 (2*PLANE_U32)
#define GEMM_SMEM (2*STAGE_U32*4)

__global__ void __launch_bounds__(256)
gemm_h(const __half* __restrict__ A,
       const __half* __restrict__ B0, const __half* __restrict__ B1,
       const float* __restrict__ bias0, const float* __restrict__ bias1,
       const float* __restrict__ gamma,
       float* __restrict__ C, __half* __restrict__ Ch,
       int N, int K, int epi0, int epi1, int aShared)
{
    extern __shared__ uint32_t smem[];
    const int tid = threadIdx.x;
    const int lane = tid & 31, wid = tid >> 5;
    const int wm = wid >> 2, wn = wid & 3;
    const int g = lane >> 2, tig = lane & 3;
    const int half_ = blockIdx.z;
    const int lmBase = blockIdx.y * 128;
    const int aBase = (aShared ? 0 : half_*MPAD) + lmBase;
    const int bn = blockIdx.x * 128;
    const int K2 = K >> 1;
    const __half* B = half_ ? B1 : B0;
    const float* bias = half_ ? bias1 : bias0;
    const int epi = half_ ? epi1 : epi0;

    const uint32_t* gA = (const uint32_t*)A;
    const uint32_t* gB = (const uint32_t*)B;
    const uint32_t sbase_u = s2u(smem);

    float acc[4][4][4];
#pragma unroll
    for (int a=0;a<4;a++)
#pragma unroll
        for (int b=0;b<4;b++)
#pragma unroll
            for (int c=0;c<4;c++) acc[a][b][c]=0.f;

    const int KT = K >> 5;

    auto fill = [&](int buf, int kt){
        uint32_t sd = sbase_u + (uint32_t)buf*STAGE_U32*4;
        int kc0 = kt*16;
#pragma unroll
        for (int i=0;i<2;i++){
            int t = tid + i*256;
            int row = t >> 2, ch = (t & 3) * 4;
            size_t ga = (size_t)(aBase+row)*K2 + kc0 + ch;
            size_t gb = (size_t)(bn + row)*K2 + kc0 + ch;
            uint32_t so = (uint32_t)(row*APITCH + ch)*4;
            cpa16(sd + so,                 gA + ga);
            cpa16(sd + PLANE_U32*4 + so,   gB + gb);
        }
        asm volatile("cp.async.commit_group;\n");
    };

    fill(0, 0);
    for (int kt=0; kt<KT; kt++){
        int buf = kt & 1;
        if (kt+1 < KT) fill(buf^1, kt+1);
        else asm volatile("cp.async.commit_group;\n");
        asm volatile("cp.async.wait_group 1;\n" ::: "memory");
        __syncthreads();

        const uint32_t* sA = smem + buf*STAGE_U32;
        const uint32_t* sB = sA + PLANE_U32;

#pragma unroll
        for (int ks=0; ks<2; ks++){
            const int kc = ks*8 + tig;
            uint32_t bh[4][2];
#pragma unroll
            for (int nt=0;nt<4;nt++){
                int n = wn*32 + nt*8 + g;
                bh[nt][0]=sB[n*APITCH+kc]; bh[nt][1]=sB[n*APITCH+kc+4];
            }
#pragma unroll
            for (int mt=0;mt<4;mt++){
                int m = wm*64 + mt*16 + g;
                uint32_t a0=sA[m*APITCH+kc],     a1=sA[(m+8)*APITCH+kc];
                uint32_t a2=sA[m*APITCH+kc+4],   a3=sA[(m+8)*APITCH+kc+4];
#pragma unroll
                for (int nt=0;nt<4;nt++){
                    mma16816(acc[mt][nt], a0,a1,a2,a3, bh[nt][0],bh[nt][1]);
                }
            }
        }
        __syncthreads();
    }

#pragma unroll
    for (int mt=0;mt<4;mt++){
        int lm0 = lmBase + wm*64 + mt*16 + g;
#pragma unroll
        for (int hf=0; hf<2; hf++){
            int lm = lm0 + hf*8;
            if (lm >= MROWS) continue;
            size_t crow = (size_t)(half_*MROWS + lm)*N;
            size_t prow = (size_t)(half_*MPAD  + lm)*N;
#pragma unroll
            for (int nt=0;nt<4;nt++){
                int gn = bn + wn*32 + nt*8 + tig*2;
                float z0 = acc[mt][nt][hf*2+0];
                float z1 = acc[mt][nt][hf*2+1];
                if (bias){ z0 += bias[gn]; z1 += bias[gn+1]; }
                if (epi == EPI_BIAS){
                    *(float2*)(C + crow + gn) = make_float2(z0, z1);
                } else if (epi == EPI_ELU1){
                    float o0 = (z0>0.f)? z0+1.f : expf(z0);
                    float o1 = (z1>0.f)? z1+1.f : expf(z1);
                    *(float2*)(C + crow + gn) = make_float2(o0,o1);
                } else if (epi == EPI_GELU){
                    float o0 = 0.5f*z0*(1.f+erff(z0*0.70710678118f));
                    float o1 = 0.5f*z1*(1.f+erff(z1*0.70710678118f));
                    __half2 hv;
                    hv.x = __float2half_rn(o0); hv.y = __float2half_rn(o1);
                    *(__half2*)(Ch + prow + gn) = hv;
                } else {
                    float2 old = *(const float2*)(C + crow + gn);
                    float o0 = old.x + gamma[gn]*z0;
                    float o1 = old.y + gamma[gn+1]*z1;
                    *(float2*)(C + crow + gn) = make_float2(o0,o1);
                }
            }
        }
    }
}

/* ---------------- weight -> fp16 ---------------- */
__global__ void wsplit_h(const float4* __restrict__ src, __half* __restrict__ hi, size_t n4)
{
    size_t i = (size_t)blockIdx.x*256 + threadIdx.x;
    if (i >= n4) return;
    float4 f = src[i];
    __half2 a, b;
    a.x = __float2half_rn(f.x); a.y = __float2half_rn(f.y);
    b.x = __float2half_rn(f.z); b.y = __float2half_rn(f.w);
    *(__half2*)(hi + 4*i)   = a;
    *(__half2*)(hi + 4*i+2) = b;
}

/* ---------------- merged LayerNorm -> fp16 plane ---------------- */
__global__ void __launch_bounds__(256) ln_split(const float* __restrict__ x,
        const float* __restrict__ g, const float* __restrict__ b,
        __half* __restrict__ yh)
{
    int row = blockIdx.x;
    int drow = (row < MROWS) ? row : row + (MPAD - MROWS);
    const float* xr = x + (size_t)row*EMB;
    int tid = threadIdx.x;
    float v0=xr[tid], v1=xr[tid+256], v2=xr[tid+512];
    float s  = v0+v1+v2;
    float s2 = v0*v0+v1*v1+v2*v2;
    __shared__ float red[2][8];
    int lane=tid&31, wid=tid>>5;
#pragma unroll
    for(int o=16;o;o>>=1){ s+=__shfl_xor_sync(0xffffffffu,s,o); s2+=__shfl_xor_sync(0xffffffffu,s2,o); }
    if(!lane){ red[0][wid]=s; red[1][wid]=s2; }
    __syncthreads();
    s=0.f; s2=0.f;
#pragma unroll
    for (int i=0;i<8;i++){ s+=red[0][i]; s2+=red[1][i]; }
    float mu = s * (1.f/768.f);
    float var = s2*(1.f/768.f) - mu*mu;
    float inv = rsqrtf(var + 1e-5f);
    size_t o0 = (size_t)drow*EMB;
#pragma unroll
    for (int r=0;r<3;r++){
        int e = tid + r*256;
        float v = (r==0)?v0:((r==1)?v1:v2);
        float y = (v-mu)*inv*g[e] + b[e];
        yh[o0+e] = __float2half_rn(y);
    }
}

__global__ void __launch_bounds__(256) ln_f32(const float* __restrict__ x,
        const float* __restrict__ g, const float* __restrict__ b,
        float* __restrict__ y)
{
    int row = blockIdx.x;
    const float* xr = x + (size_t)row*EMB;
    float* yr = y + (size_t)row*EMB;
    int tid = threadIdx.x;
    float v0=xr[tid], v1=xr[tid+256], v2=xr[tid+512];
    float s  = v0+v1+v2;
    float s2 = v0*v0+v1*v1+v2*v2;
    __shared__ float red[2][8];
    int lane=tid&31, wid=tid>>5;
#pragma unroll
    for(int o=16;o;o>>=1){ s+=__shfl_xor_sync(0xffffffffu,s,o); s2+=__shfl_xor_sync(0xffffffffu,s2,o); }
    if(!lane){ red[0][wid]=s; red[1][wid]=s2; }
    __syncthreads();
    s=0.f; s2=0.f;
#pragma unroll
    for (int i=0;i<8;i++){ s+=red[0][i]; s2+=red[1][i]; }
    float mu = s * (1.f/768.f);
    float var = s2*(1.f/768.f) - mu*mu;
    float inv = rsqrtf(var + 1e-5f);
    yr[tid]     = (v0-mu)*inv*g[tid]     + b[tid];
    yr[tid+256] = (v1-mu)*inv*g[tid+256] + b[tid+256];
    yr[tid+512] = (v2-mu)*inv*g[tid+512] + b[tid+512];
}

/* ---------------- im2col -> fp16 plane ---------------- */
__global__ void im2col_split(const float* __restrict__ x, __half* __restrict__ ph)
{
    int idx = blockIdx.x*blockDim.x + threadIdx.x;
    if (idx >= MROWS*EMB) return;
    int r = idx / EMB, col = idx % EMB;
    int b = r / NTOK, t = r % NTOK;
    float v = 0.f;
    if (t > 0){
        int pp = t-1;
        int py = pp/14, px = pp%14;
        int c = col >> 8, phh = (col>>4)&15, pw = col&15;
        v = x[(((size_t)b*3 + c)*224 + py*16+phh)*224 + px*16+pw];
    }
    ph[idx] = __float2half_rn(v);
}

__global__ void fill_cls(const float* __restrict__ cls, const float* __restrict__ ccls,
                         float* __restrict__ xx)
{
    int b = blockIdx.x, tid=threadIdx.x;
#pragma unroll
    for (int r=0;r<3;r++){
        int e = tid+r*256;
        xx[(size_t)b*NTOK*EMB+e]              = cls[e];
        xx[((size_t)MROWS + b*NTOK)*EMB+e]    = ccls[e];
    }
}

__global__ void build_qkvb(const float* __restrict__ qb, const float* __restrict__ vb,
                           const float* __restrict__ cqb, const float* __restrict__ cvb,
                           float* __restrict__ outv, float* __restrict__ coutv)
{
    int idx = blockIdx.x*blockDim.x+threadIdx.x;
    if (idx >= NLAYER*E3) return;
    int l = idx / E3, j = idx % E3;
    float v=0.f, cv=0.f;
    if (j < EMB)        { v=qb[l*EMB+j];        cv=cqb[l*EMB+j]; }
    else if (j >= 2*EMB){ v=vb[l*EMB+j-2*EMB];  cv=cvb[l*EMB+j-2*EMB]; }
    outv[idx]=v; coutv[idx]=cv;
}

/* -------- attention preprocess: pack Qp(hi/lo), Kp, Vt, cVt + stats --- */
__global__ void __launch_bounds__(256) attn_pre(const float* __restrict__ qkv,
   __half* __restrict__ qph, __half* __restrict__ qpl, __half* __restrict__ kp,
   __half* __restrict__ vt, __half* __restrict__ cvt,
   float* __restrict__ qs2, float* __restrict__ ks2,
   float* __restrict__ cqsum, float* __restrict__ cksum)
{
    int grp = threadIdx.x >> 6;
    int d   = threadIdx.x & 63;
    int idx = blockIdx.x*4 + grp;
    int t  = idx % NTOK;
    int bh = idx / NTOK;
    int h  = bh % NHEAD;
    int b  = bh / NHEAD;
    size_t mb = ((size_t)(b*NTOK+t))*E3 + h*HD + d;
    size_t cb = ((size_t)(MROWS + b*NTOK+t))*E3 + h*HD + d;
    float q  = qkv[mb]*QSCALE;
    float k  = qkv[mb+EMB];
    float v  = qkv[mb+2*EMB];
    float cq = qkv[cb];
    float ck = qkv[cb+EMB];
    float cv = qkv[cb+2*EMB];
    float sq = sqrtf(fmaxf(cq,1e-24f));
    float sk = sqrtf(fmaxf(ck,1e-24f));

    size_t qrow = ((size_t)bh*TP + t)*128;
    __half hh,ll;
    split_h(q, hh, ll);  qph[qrow+d]    = hh; qpl[qrow+d]    = ll;
    split_h(sq, hh, ll); qph[qrow+64+d] = hh; qpl[qrow+64+d] = ll;
    kp[qrow+d]    = __float2half_rn(k);
    kp[qrow+64+d] = __float2half_rn(sk);
    vt [((size_t)bh*64 + d)*MP + t] = __float2half_rn(v);
    cvt[((size_t)bh*64 + d)*MP + t] = __float2half_rn(cv);

    float r0=q*q, r1=k*k, r2=cq, r3=ck;
#pragma unroll
    for(int off=16;off;off>>=1){
        r0+=__shfl_xor_sync(0xffffffffu,r0,off);
        r1+=__shfl_xor_sync(0xffffffffu,r1,off);
        r2+=__shfl_xor_sync(0xffffffffu,r2,off);
        r3+=__shfl_xor_sync(0xffffffffu,r3,off);
    }
    __shared__ float sh[4][4][2];
    int lane = threadIdx.x & 31;
    int wno = (threadIdx.x >> 5) & 1;
    if(!lane){ sh[grp][0][wno]=r0; sh[grp][1][wno]=r1; sh[grp][2][wno]=r2; sh[grp][3][wno]=r3; }
    __syncthreads();
    if (d==0){
        qs2[idx]  =sh[grp][0][0]+sh[grp][0][1];
        ks2[idx]  =sh[grp][1][0]+sh[grp][1][1];
        cqsum[idx]=sh[grp][2][0]+sh[grp][2][1];
        cksum[idx]=sh[grp][3][0]+sh[grp][3][1];
    }
}

/* -------- score MMA: sdot[bh][n][m] = Qp[n]·Kp[m], K=128, 2 products --- */
#define SPITCH 68
#define SC_SMEM (3*64*SPITCH*4)
__global__ void __launch_bounds__(256) score_mma(
    const __half* __restrict__ qph, const __half* __restrict__ qpl,
    const __half* __restrict__ kp, float* __restrict__ sdot)
{
    extern __shared__ uint32_t sm[];
    uint32_t* sQh = sm;
    uint32_t* sQl = sm + 64*SPITCH;
    uint32_t* sK  = sm + 2*64*SPITCH;
    const int tid = threadIdx.x;
    const int lane = tid & 31, wid = tid >> 5;
    const int wm = wid >> 2, wn = wid & 3;
    const int g = lane >> 2, tig = lane & 3;
    const int bh = blockIdx.z;
    const int n0 = blockIdx.y * 64;
    const int m0 = blockIdx.x * 64;
    const uint32_t sb = s2u(sm);
    const uint32_t* gQh = (const uint32_t*)qph;
    const uint32_t* gQl = (const uint32_t*)qpl;
    const uint32_t* gK  = (const uint32_t*)kp;

#pragma unroll
    for (int i=0;i<4;i++){
        int j = tid + i*256;
        int row = j >> 4, c = (j & 15)*4;
        uint32_t so = (uint32_t)(row*SPITCH + c)*4;
        size_t qa = ((size_t)bh*TP + n0 + row)*64 + c;
        size_t ka = ((size_t)bh*TP + m0 + row)*64 + c;
        cpa16(sb + so,                  gQh + qa);
        cpa16(sb + 64*SPITCH*4 + so,    gQl + qa);
        cpa16(sb + 2*64*SPITCH*4 + so,  gK  + ka);
    }
    asm volatile("cp.async.commit_group;\n");
    asm volatile("cp.async.wait_group 0;\n" ::: "memory");
    __syncthreads();

    float acc[2][2][4];
#pragma unroll
    for (int a=0;a<2;a++)
#pragma unroll
        for (int b=0;b<2;b++)
#pragma unroll
            for (int c=0;c<4;c++) acc[a][b][c]=0.f;

#pragma unroll
    for (int s=0;s<8;s++){
        int kc = s*8 + tig;
        uint32_t b0[2], b1[2];
#pragma unroll
        for (int nt=0;nt<2;nt++){
            int rb = wn*16 + nt*8 + g;
            b0[nt]=sK[rb*SPITCH+kc]; b1[nt]=sK[rb*SPITCH+kc+4];
        }
#pragma unroll
        for (int mt=0;mt<2;mt++){
            int r = wm*32 + mt*16 + g;
            uint32_t ah0=sQh[r*SPITCH+kc],     ah1=sQh[(r+8)*SPITCH+kc];
            uint32_t ah2=sQh[r*SPITCH+kc+4],   ah3=sQh[(r+8)*SPITCH+kc+4];
            uint32_t al0=sQl[r*SPITCH+kc],     al1=sQl[(r+8)*SPITCH+kc];
            uint32_t al2=sQl[r*SPITCH+kc+4],   al3=sQl[(r+8)*SPITCH+kc+4];
#pragma unroll
            for (int nt=0;nt<2;nt++){
                mma16816(acc[mt][nt], ah0,ah1,ah2,ah3, b0[nt],b1[nt]);
                mma16816(acc[mt][nt], al0,al1,al2,al3, b0[nt],b1[nt]);
            }
        }
    }

#pragma unroll
    for (int mt=0;mt<2;mt++){
#pragma unroll
        for (int hf=0;hf<2;hf++){
            int n = n0 + wm*32 + mt*16 + g + hf*8;
#pragma unroll
            for (int nt=0;nt<2;nt++){
                int m = m0 + wn*16 + nt*8 + tig*2;
                *(float2*)&sdot[((size_t)bh*TP + n)*TP + m] =
                    make_float2(acc[mt][nt][hf*2], acc[mt][nt][hf*2+1]);
            }
        }
    }
}

/* -------- softmax: w -> sigmoid -> +relb -> softmax -> attn planes ----- */
__global__ void __launch_bounds__(256) attn_softmax(
    const float* __restrict__ sdot,
    const float* __restrict__ qs2, const float* __restrict__ cqsum,
    const float* __restrict__ ks2, const float* __restrict__ cksum,
    const float* __restrict__ relb,
    __half* __restrict__ ah, __half* __restrict__ al,
    __half* __restrict__ a2h, __half* __restrict__ a2l)
{
    __shared__ float ssc[16][MP];
    int bh = blockIdx.y;
    int hh = bh % NHEAD;
    int n0 = blockIdx.x * 16;
    int tid = threadIdx.x;
    int wid = tid>>5, lane = tid&31;

    for (int r = wid; r < 16; r += 8){
        int n = n0 + r;
        if (n >= NTOK) continue;
        float rq = qs2[bh*NTOK+n] + cqsum[bh*NTOK+n];
        const float* srow = sdot + ((size_t)bh*TP + n)*TP;
        float mx = -1e30f;
        for (int m=lane; m<NTOK; m+=32){
            float w = -2.f*srow[m] + rq + ks2[bh*NTOK+m] + cksum[bh*NTOK+m];
            float s = 1.f/(1.f+expf(w - 1e-24f));
            float val = s + relb[((size_t)hh*NTOK + n)*NTOK + m];
            ssc[r][m] = val;
            mx = fmaxf(mx, val);
        }
#pragma unroll
        for (int o=16;o;o>>=1) mx = fmaxf(mx, __shfl_xor_sync(0xffffffffu,mx,o));
        float sum = 0.f;
        for (int m=lane; m<NTOK; m+=32){
            float e = expf(ssc[r][m]-mx); ssc[r][m]=e; sum+=e;
        }
#pragma unroll
        for (int o=16;o;o>>=1) sum += __shfl_xor_sync(0xffffffffu,sum,o);
        float inv = 1.f/sum;
        size_t ob = ((size_t)bh*TP + n)*MP;
        for (int m=lane; m<NTOK; m+=32){
            float a = ssc[r][m]*inv;
            __half h1,l1; split_h(a,h1,l1);
            ah[ob+m]=h1; al[ob+m]=l1;
            float a2 = a*a;
            split_h(a2,h1,l1);
            a2h[ob+m]=h1; a2l[ob+m]=l1;
        }
    }
}

/* -------- AV MMA: ctx[n][d] = attn(hi/lo)·Vt, K=208 -------------------- */
#define AVPITCH 108
#define AV_SMEM (3*64*AVPITCH*4)
__global__ void __launch_bounds__(256) av_mma(
    const __half* __restrict__ ah, const __half* __restrict__ al,
    const __half* __restrict__ a2h, const __half* __restrict__ a2l,
    const __half* __restrict__ vt, const __half* __restrict__ cvt,
    __half* __restrict__ ctx)
{
    extern __shared__ uint32_t sm[];
    uint32_t* sAh = sm;
    uint32_t* sAl = sm + 64*AVPITCH;
    uint32_t* sB  = sm + 2*64*AVPITCH;
    const int tid = threadIdx.x;
    const int lane = tid & 31, wid = tid >> 5;
    const int wm = wid >> 2, wn = wid & 3;
    const int g = lane >> 2, tig = lane & 3;
    const int n0 = blockIdx.x * 64;
    const int bh = blockIdx.y;
    const int path = blockIdx.z;
    const uint32_t sb = s2u(sm);
    const uint32_t* gAh = (const uint32_t*)(path ? a2h : ah);
    const uint32_t* gAl = (const uint32_t*)(path ? a2l : al);
    const uint32_t* gB  = (const uint32_t*)(path ? cvt : vt);

#pragma unroll
    for (int i=0;i<7;i++){
        int j = tid + i*256;
        if (j < 1664){
            int row = j / 26, c = (j % 26)*4;
            uint32_t so = (uint32_t)(row*AVPITCH + c)*4;
            size_t aa = ((size_t)bh*TP + n0 + row)*104 + c;
            size_t ba = ((size_t)bh*64 + row)*104 + c;
            cpa16(sb + so,                   gAh + aa);
            cpa16(sb + 64*AVPITCH*4 + so,    gAl + aa);
            cpa16(sb + 2*64*AVPITCH*4 + so,  gB  + ba);
        }
    }
    asm volatile("cp.async.commit_group;\n");
    asm volatile("cp.async.wait_group 0;\n" ::: "memory");
    __syncthreads();

    float acc[2][2][4];
#pragma unroll
    for (int a=0;a<2;a++)
#pragma unroll
        for (int b=0;b<2;b++)
#pragma unroll
            for (int c=0;c<4;c++) acc[a][b][c]=0.f;

    for (int s=0;s<13;s++){
        int kc = s*8 + tig;
        uint32_t b0[2], b1[2];
#pragma unroll
        for (int nt=0;nt<2;nt++){
            int rb = wn*16 + nt*8 + g;
            b0[nt]=sB[rb*AVPITCH+kc]; b1[nt]=sB[rb*AVPITCH+kc+4];
        }
#pragma unroll
        for (int mt=0;mt<2;mt++){
            int r = wm*32 + mt*16 + g;
            uint32_t ah0=sAh[r*AVPITCH+kc],     ah1=sAh[(r+8)*AVPITCH+kc];
            uint32_t ah2=sAh[r*AVPITCH+kc+4],   ah3=sAh[(r+8)*AVPITCH+kc+4];
            uint32_t al0=sAl[r*AVPITCH+kc],     al1=sAl[(r+8)*AVPITCH+kc];
            uint32_t al2=sAl[r*AVPITCH+kc+4],   al3=sAl[(r+8)*AVPITCH+kc+4];
#pragma unroll
            for (int nt=0;nt<2;nt++){
                mma16816(acc[mt][nt], ah0,ah1,ah2,ah3, b0[nt],b1[nt]);
                mma16816(acc[mt][nt], al0,al1,al2,al3, b0[nt],b1[nt]);
            }
        }
    }

    const int b = bh / NHEAD;
    const int hh = bh % NHEAD;
#pragma unroll
    for (int mt=0;mt<2;mt++){
#pragma unroll
        for (int hf=0;hf<2;hf++){
            int n = n0 + wm*32 + mt*16 + g + hf*8;
            if (n >= NTOK) continue;
            size_t row = (size_t)(path*MPAD + b*NTOK + n)*EMB + hh*64;
#pragma unroll
            for (int nt=0;nt<2;nt++){
                int d0 = wn*16 + nt*8 + tig*2;
                __half2 hv;
                hv.x = __float2half_rn(acc[mt][nt][hf*2]);
                hv.y = __float2half_rn(acc[mt][nt][hf*2+1]);
                *(__half2*)(ctx + row + d0) = hv;
            }
        }
    }
}

/* ------------------------------ tail ---------------------------------- */
__global__ void __launch_bounds__(256) pool_kernel(const float* __restrict__ xx, float* __restrict__ pool)
{
    int b = blockIdx.x;
    int tid=threadIdx.x;
#pragma unroll
    for (int r=0;r<3;r++){
        int e = tid + r*256;
        float s=0.f;
        for (int n=1;n<NTOK;n++) s += xx[((size_t)(b*NTOK+n))*EMB+e];
        pool[b*EMB+e]=s*(1.f/196.f);
    }
}

__global__ void head_kernel(const float* __restrict__ t, const float* __restrict__ w,
                            const float* __restrict__ hb, float* __restrict__ out)
{
    int idx = blockIdx.x*blockDim.x + threadIdx.x;
    if (idx >= BATCH*NCLS) return;
    int b = idx/NCLS, c = idx%NCLS;
    const float* tr = t + b*EMB;
    const float* wr = w + (size_t)c*EMB;
    float s = hb[c];
    for (int e=0;e<EMB;e+=4){
        float4 tv=*(const float4*)(tr+e);
        float4 wv=*(const float4*)(wr+e);
        s += tv.x*wv.x+tv.y*wv.y+tv.z*wv.z+tv.w*wv.w;
    }
    out[idx]=s;
}

/* ------------------------------ host ---------------------------------- */
extern "C" void kernel_launch(void* const* d_in, const int* in_sizes, int n_in,
                              void* d_out, int out_size)
{
    const float* x        = (const float*)d_in[0];
    const float* relb     = (const float*)d_in[1];
    const float* patch_w  = (const float*)d_in[2];
    const float* patch_b  = (const float*)d_in[3];
    const float* cpatch_w = (const float*)d_in[4];
    const float* cpatch_b = (const float*)d_in[5];
    const float* cls      = (const float*)d_in[6];
    const float* ccls     = (const float*)d_in[7];
    const float* n1g      = (const float*)d_in[8];
    const float* n1b      = (const float*)d_in[9];
    const float* qkvw     = (const float*)d_in[10];
    const float* qb       = (const float*)d_in[11];
    const float* vb       = (const float*)d_in[12];
    const float* cqb      = (const float*)d_in[13];
    const float* cvb      = (const float*)d_in[14];
    const float* projw    = (const float*)d_in[15];
    const float* projb    = (const float*)d_in[16];
    const float* cprojw   = (const float*)d_in[17];
    const float* cprojb   = (const float*)d_in[18];
    const float* gamma1   = (const float*)d_in[19];
    const float* gamma2   = (const float*)d_in[20];
    const float* n2g      = (const float*)d_in[21];
    const float* n2b      = (const float*)d_in[22];
    const float* fc1w     = (const float*)d_in[23];
    const float* fc1b     = (const float*)d_in[24];
    const float* fc2w     = (const float*)d_in[25];
    const float* fc2b     = (const float*)d_in[26];
    const float* fng      = (const float*)d_in[27];
    const float* fnb      = (const float*)d_in[28];
    const float* headw    = (const float*)d_in[29];
    const float* headb    = (const float*)d_in[30];
    float* out = (float*)d_out;

    static int attr_set = 0;
    if (!attr_set){
        cudaFuncSetAttribute(gemm_h, cudaFuncAttributeMaxDynamicSharedMemorySize, GEMM_SMEM);
        cudaFuncSetAttribute(score_mma, cudaFuncAttributeMaxDynamicSharedMemorySize, SC_SMEM);
        cudaFuncSetAttribute(av_mma, cudaFuncAttributeMaxDynamicSharedMemorySize, AV_SMEM);
        attr_set = 1;
    }

    __half *w,*pat,*tn,*ctx,*hbuf,*qph,*qpl,*kp,*vt,*cvt,*ahp,*alp,*a2hp,*a2lp;
    float *p_x,*p_qkv,*p_sdot,*p_qs2,*p_ks2,*p_cqsum,*p_cksum,*p_qkvb,*p_cqkvb,*p_pool,*p_pooln;
    cudaGetSymbolAddress((void**)&w, g_w);
    cudaGetSymbolAddress((void**)&pat, g_pat);
    cudaGetSymbolAddress((void**)&tn, g_tn);
    cudaGetSymbolAddress((void**)&ctx, g_ctx);
    cudaGetSymbolAddress((void**)&hbuf, g_h);
    cudaGetSymbolAddress((void**)&qph, g_qph);
    cudaGetSymbolAddress((void**)&qpl, g_qpl);
    cudaGetSymbolAddress((void**)&kp,  g_kp);
    cudaGetSymbolAddress((void**)&vt,  g_vt);
    cudaGetSymbolAddress((void**)&cvt, g_cvt);
    cudaGetSymbolAddress((void**)&ahp, g_ah);
    cudaGetSymbolAddress((void**)&alp, g_al);
    cudaGetSymbolAddress((void**)&a2hp,g_a2h);
    cudaGetSymbolAddress((void**)&a2lp,g_a2l);
    cudaGetSymbolAddress((void**)&p_x,    g_x);
    cudaGetSymbolAddress((void**)&p_qkv,  g_qkv);
    cudaGetSymbolAddress((void**)&p_sdot, g_sdot);
    cudaGetSymbolAddress((void**)&p_qs2,  g_qs2);
    cudaGetSymbolAddress((void**)&p_ks2,  g_ks2);
    cudaGetSymbolAddress((void**)&p_cqsum,g_cqsum);
    cudaGetSymbolAddress((void**)&p_cksum,g_cksum);
    cudaGetSymbolAddress((void**)&p_qkvb, g_qkvb);
    cudaGetSymbolAddress((void**)&p_cqkvb,g_cqkvb);
    cudaGetSymbolAddress((void**)&p_pool, g_pool);
    cudaGetSymbolAddress((void**)&p_pooln,g_pooln);

    auto wsp = [&](const float* src, size_t off, size_t cnt){
        size_t n4 = cnt/4;
        wsplit_h<<<(unsigned)((n4+255)/256),256>>>((const float4*)src, w+off, n4);
    };
    wsp(patch_w,  OFF_PW,    589824);
    wsp(cpatch_w, OFF_CPW,   589824);
    wsp(qkvw,     OFF_QKV,   21233664);
    wsp(projw,    OFF_PROJ,  7077888);
    wsp(cprojw,   OFF_CPROJ, 7077888);
    wsp(fc1w,     OFF_FC1,   28311552);
    wsp(fc2w,     OFF_FC2,   28311552);

    build_qkvb<<<(NLAYER*E3+255)/256,256>>>(qb,vb,cqb,cvb,p_qkvb,p_cqkvb);
    im2col_split<<<(MROWS*EMB+255)/256,256>>>(x, pat);

    gemm_h<<<dim3(EMB/128,13,2),256,GEMM_SMEM>>>(
        pat, w+OFF_PW, w+OFF_CPW,
        patch_b, cpatch_b, nullptr, p_x, nullptr, EMB, EMB, EPI_BIAS, EPI_BIAS, 1);
    fill_cls<<<BATCH,256>>>(cls, ccls, p_x);

    for (int i=0;i<NLAYER;i++){
        size_t qkv_o  = OFF_QKV   + (size_t)i*E3*EMB;
        size_t proj_o = OFF_PROJ  + (size_t)i*EMB*EMB;
        size_t cprj_o = OFF_CPROJ + (size_t)i*EMB*EMB;
        size_t fc1_o  = OFF_FC1   + (size_t)i*(size_t)MLPD*EMB;
        size_t fc2_o  = OFF_FC2   + (size_t)i*(size_t)EMB*MLPD;

        ln_split<<<2*MROWS,256>>>(p_x, n1g+i*EMB, n1b+i*EMB, tn);
        gemm_h<<<dim3(E3/128,13,2),256,GEMM_SMEM>>>(
            tn, w+qkv_o, w+qkv_o,
            p_qkvb+i*E3, p_cqkvb+i*E3, nullptr, p_qkv, nullptr,
            E3, EMB, EPI_BIAS, EPI_ELU1, 0);

        attn_pre<<<BATCH*NHEAD*NTOK/4,256>>>(p_qkv, qph,qpl,kp,vt,cvt,
                                             p_qs2,p_ks2,p_cqsum,p_cksum);
        score_mma<<<dim3(4,4,BH),256,SC_SMEM>>>(qph,qpl,kp,p_sdot);
        attn_softmax<<<dim3(13,BH),256>>>(p_sdot,p_qs2,p_cqsum,p_ks2,p_cksum,relb,
                                          ahp,alp,a2hp,a2lp);
        av_mma<<<dim3(4,BH,2),256,AV_SMEM>>>(ahp,alp,a2hp,a2lp,vt,cvt,ctx);

        gemm_h<<<dim3(EMB/128,13,2),256,GEMM_SMEM>>>(
            ctx, w+proj_o, w+cprj_o,
            projb+i*EMB, cprojb+i*EMB, gamma1+i*EMB, p_x, nullptr,
            EMB, EMB, EPI_RES, EPI_RES, 0);

        ln_split<<<2*MROWS,256>>>(p_x, n2g+i*EMB, n2b+i*EMB, tn);
        gemm_h<<<dim3(MLPD/128,13,2),256,GEMM_SMEM>>>(
            tn, w+fc1_o, w+fc1_o,
            fc1b+i*MLPD, fc1b+i*MLPD, nullptr, nullptr, hbuf,
            MLPD, EMB, EPI_GELU, EPI_GELU, 0);
        gemm_h<<<dim3(EMB/128,13,2),256,GEMM_SMEM>>>(
            hbuf, w+fc2_o, w+fc2_o,
            fc2b+i*EMB, fc2b+i*EMB, gamma2+i*EMB, p_x, nullptr,
            EMB, MLPD, EPI_RES, EPI_RES, 0);
    }

    pool_kernel<<<BATCH,256>>>(p_x, p_pool);
    ln_f32<<<BATCH,256>>>(p_pool, fng, fnb, p_pooln);
    head_kernel<<<(BATCH*NCLS+255)/256,256>>>(p_pooln, headw, headb, out);
}